// round 1
// baseline (speedup 1.0000x reference)
#include <cuda_runtime.h>
#include <cuda_bf16.h>
#include <math.h>

#define BSZ   2
#define SEQ   2048
#define DM    2048
#define NH    16
#define HDIM  128
#define HID   5632
#define NTOK  (BSZ*SEQ)   // 4096

// ---------------- scratch (no allocation allowed -> __device__ globals) ----
__device__ float g_xn  [NTOK*(size_t)DM];
__device__ float g_q   [NTOK*(size_t)DM];
__device__ float g_k   [NTOK*(size_t)DM];
__device__ float g_v   [NTOK*(size_t)DM];
__device__ float g_attn[NTOK*(size_t)DM];
__device__ float g_h   [NTOK*(size_t)DM];
__device__ float g_hn  [NTOK*(size_t)DM];
__device__ float g_ffa [NTOK*(size_t)HID];
__device__ float g_ffb [NTOK*(size_t)HID];

// ---------------- helpers --------------------------------------------------
__device__ __forceinline__ unsigned f2tf(float x){
    unsigned r; asm("cvt.rna.tf32.f32 %0, %1;" : "=r"(r) : "f"(x)); return r;
}
__device__ __forceinline__ void mma_tf32(float c[4], const unsigned a[4], const unsigned b[2]){
    asm volatile("mma.sync.aligned.m16n8k8.row.col.f32.tf32.tf32.f32 "
        "{%0,%1,%2,%3},{%4,%5,%6,%7},{%8,%9},{%0,%1,%2,%3};"
        : "+f"(c[0]), "+f"(c[1]), "+f"(c[2]), "+f"(c[3])
        : "r"(a[0]), "r"(a[1]), "r"(a[2]), "r"(a[3]), "r"(b[0]), "r"(b[1]));
}
__device__ __forceinline__ void cp16(float* dst, const float* src){
    unsigned d = (unsigned)__cvta_generic_to_shared(dst);
    asm volatile("cp.async.cg.shared.global [%0], [%1], 16;" :: "r"(d), "l"(src));
}
__device__ __forceinline__ void cp_commit(){ asm volatile("cp.async.commit_group;"); }
__device__ __forceinline__ void cp_wait0(){ asm volatile("cp.async.wait_group 0;"); }

// ---------------- rmsnorm --------------------------------------------------
__global__ void rmsnorm_kernel(const float* __restrict__ x, const float* __restrict__ w,
                               float* __restrict__ out){
    int row = blockIdx.x;
    const float* xr = x + (size_t)row*DM;
    float* orow = out + (size_t)row*DM;
    float ss = 0.f;
    for (int i = threadIdx.x; i < DM; i += blockDim.x){ float v = xr[i]; ss += v*v; }
    __shared__ float red[8];
    #pragma unroll
    for (int o = 16; o; o >>= 1) ss += __shfl_xor_sync(~0u, ss, o);
    if ((threadIdx.x & 31) == 0) red[threadIdx.x >> 5] = ss;
    __syncthreads();
    if (threadIdx.x == 0){
        float t = 0.f;
        #pragma unroll
        for (int i = 0; i < 8; i++) t += red[i];
        red[0] = t;
    }
    __syncthreads();
    float inv = rsqrtf(red[0] / (float)DM + 1e-5f);
    for (int i = threadIdx.x; i < DM; i += blockDim.x) orow[i] = xr[i] * inv * w[i];
}

// ---------------- rope (in place) -----------------------------------------
__global__ void rope_kernel(float* __restrict__ q, const float* __restrict__ cs,
                            const float* __restrict__ sn){
    int idx = blockIdx.x*blockDim.x + threadIdx.x;
    if (idx >= NTOK*NH*64) return;
    int i = idx & 63;
    int h = (idx >> 6) & (NH-1);
    int t = idx >> 10;            // token 0..4095  (NH*64 = 1024)
    int s = t & (SEQ-1);
    float c = cs[s*64 + i], sv = sn[s*64 + i];
    float* p = q + ((size_t)t*NH + h)*HDIM + 2*i;
    float a = p[0], b = p[1];
    p[0] = a*c - b*sv;
    p[1] = a*sv + b*c;
}

// ---------------- silu(a)*b ------------------------------------------------
__global__ void silu_mul_kernel(float* __restrict__ a, const float* __restrict__ b, int n){
    int i = blockIdx.x*blockDim.x + threadIdx.x;
    if (i < n){
        float x = a[i];
        float s = x / (1.f + __expf(-x));
        a[i] = s * b[i];
    }
}

// ---------------- GEMM: C[M,N] = A[M,K] @ B[K,N]  (+Add), tf32 mma ---------
#define GBM 128
#define GBN 128
#define GBK 32
#define AST 36      // A smem stride [m][k]:  bank (4m+k)%32 distinct  -> conflict free
#define BST 136     // B smem stride [k][n]:  bank (8k+n)%32 distinct  -> conflict free
#define GEMM_SMEM ((2*GBM*AST + 2*GBK*BST)*4)   // 71680 B

template<bool ADD>
__global__ void __launch_bounds__(256)
gemm_kernel(const float* __restrict__ A, const float* __restrict__ B,
            const float* __restrict__ Add, float* __restrict__ C,
            int M, int N, int K)
{
    extern __shared__ float sm[];
    float* As = sm;                     // 2 * 128*36
    float* Bs = sm + 2*GBM*AST;         // 2 * 32*136
    const int tid = threadIdx.x;
    const int lane = tid & 31, wid = tid >> 5;
    const int wm = (wid >> 2) * 64;     // 2 warp-rows
    const int wn = (wid & 3) * 32;      // 4 warp-cols
    const int bm = blockIdx.y * GBM, bn = blockIdx.x * GBN;

    float acc[4][4][4];
    #pragma unroll
    for (int i=0;i<4;i++)
        #pragma unroll
        for (int j=0;j<4;j++)
            #pragma unroll
            for (int r=0;r<4;r++) acc[i][j][r] = 0.f;

    const int nk = K / GBK;

    auto issue = [&](int kt, int st){
        const float* Ag = A + (size_t)bm*K + (size_t)kt*GBK;
        float* Ad = As + st*GBM*AST;
        #pragma unroll
        for (int i=0;i<4;i++){
            int idx = tid + i*256;
            int r = idx >> 3, c = (idx & 7) * 4;
            cp16(Ad + r*AST + c, Ag + (size_t)r*K + c);
        }
        const float* Bg = B + (size_t)kt*GBK*N + bn;
        float* Bd = Bs + st*GBK*BST;
        #pragma unroll
        for (int i=0;i<4;i++){
            int idx = tid + i*256;
            int r = idx >> 5, c = (idx & 31) * 4;
            cp16(Bd + r*BST + c, Bg + (size_t)r*N + c);
        }
        cp_commit();
    };

    issue(0, 0);
    for (int kt = 0; kt < nk; kt++){
        cp_wait0();
        __syncthreads();
        if (kt+1 < nk) issue(kt+1, (kt+1)&1);
        const float* Ab = As + (kt&1)*GBM*AST;
        const float* Bb = Bs + (kt&1)*GBK*BST;
        #pragma unroll
        for (int ks = 0; ks < 4; ks++){
            int k0 = ks*8;
            unsigned af[4][4], bf[4][2];
            #pragma unroll
            for (int mt=0; mt<4; mt++){
                int r = wm + mt*16 + (lane>>2);
                int c = k0 + (lane&3);
                af[mt][0] = f2tf(Ab[r*AST + c]);
                af[mt][1] = f2tf(Ab[(r+8)*AST + c]);
                af[mt][2] = f2tf(Ab[r*AST + c + 4]);
                af[mt][3] = f2tf(Ab[(r+8)*AST + c + 4]);
            }
            #pragma unroll
            for (int nt=0; nt<4; nt++){
                int n = wn + nt*8 + (lane>>2);
                int kk = k0 + (lane&3);
                bf[nt][0] = f2tf(Bb[kk*BST + n]);
                bf[nt][1] = f2tf(Bb[(kk+4)*BST + n]);
            }
            #pragma unroll
            for (int mt=0; mt<4; mt++)
                #pragma unroll
                for (int nt=0; nt<4; nt++)
                    mma_tf32(acc[mt][nt], af[mt], bf[nt]);
        }
    }

    #pragma unroll
    for (int mt=0; mt<4; mt++){
        #pragma unroll
        for (int nt=0; nt<4; nt++){
            int r = bm + wm + mt*16 + (lane>>2);
            int c = bn + wn + nt*8 + (lane&3)*2;
            float2 v0 = make_float2(acc[mt][nt][0], acc[mt][nt][1]);
            float2 v1 = make_float2(acc[mt][nt][2], acc[mt][nt][3]);
            if (ADD){
                const float* A0 = Add + (size_t)r*N + c;
                const float* A1 = Add + (size_t)(r+8)*N + c;
                v0.x += A0[0]; v0.y += A0[1];
                v1.x += A1[0]; v1.y += A1[1];
            }
            *(float2*)(C + (size_t)r*N + c)     = v0;
            *(float2*)(C + (size_t)(r+8)*N + c) = v1;
        }
    }
}

// ---------------- flash attention (non-causal) -----------------------------
// grid (S/64, NH, B), 128 threads (4 warps); each warp owns 16 q-rows.
#define FBQ 64
#define FBK 64
#define QST 132     // [q][d] : bank (4q+d)%32 distinct
#define KST 132     // read n-major: bank (4n+k)%32 distinct
#define VST 136     // read k-major: bank (8k+n)%32 distinct
#define PST 68      // [q][kpos]: bank (4q+k)%32 distinct
#define FLASH_SMEM ((FBQ*QST + 2*FBK*KST + 2*FBK*VST + FBQ*PST)*4)   // 188416 B

__global__ void __launch_bounds__(128)
flash_kernel(const float* __restrict__ Q, const float* __restrict__ Kb,
             const float* __restrict__ Vb, float* __restrict__ O)
{
    extern __shared__ float sm[];
    float* Qs = sm;
    float* Ks = Qs + FBQ*QST;
    float* Vs = Ks + 2*FBK*KST;
    float* Ps = Vs + 2*FBK*VST;

    const int tid = threadIdx.x, lane = tid & 31, wid = tid >> 5;
    const int qt = blockIdx.x, h = blockIdx.y, b = blockIdx.z;
    const int q0 = qt*FBQ;
    const float scale = 0.08838834764831845f;     // 1/sqrt(128)

    // token layout: [B,S,H,HD]; next token = +DM floats
    const float* Qg = Q + (((size_t)b*SEQ + q0)*NH + h)*HDIM;
    #pragma unroll
    for (int i=0;i<16;i++){
        int idx = tid + i*128;
        int r = idx >> 5, c = (idx & 31) * 4;
        cp16(Qs + r*QST + c, Qg + (size_t)r*DM + c);
    }

    auto issueKV = [&](int kt, int st){
        const float* Kg = Kb + (((size_t)b*SEQ + kt*FBK)*NH + h)*HDIM;
        const float* Vg = Vb + (((size_t)b*SEQ + kt*FBK)*NH + h)*HDIM;
        float* Kd = Ks + st*FBK*KST;
        float* Vd = Vs + st*FBK*VST;
        #pragma unroll
        for (int i=0;i<16;i++){
            int idx = tid + i*128;
            int r = idx >> 5, c = (idx & 31) * 4;
            cp16(Kd + r*KST + c, Kg + (size_t)r*DM + c);
            cp16(Vd + r*VST + c, Vg + (size_t)r*DM + c);
        }
        cp_commit();
    };

    issueKV(0, 0);   // group includes Q loads above

    float m0 = -1e30f, m1 = -1e30f, l0 = 0.f, l1 = 0.f;
    float oacc[16][4];
    #pragma unroll
    for (int i=0;i<16;i++)
        #pragma unroll
        for (int j=0;j<4;j++) oacc[i][j] = 0.f;

    const int nkt = SEQ / FBK;    // 32
    for (int kt = 0; kt < nkt; kt++){
        cp_wait0();
        __syncthreads();
        if (kt+1 < nkt) issueKV(kt+1, (kt+1)&1);
        const float* Kc = Ks + (kt&1)*FBK*KST;
        const float* Vc = Vs + (kt&1)*FBK*VST;

        // S[16x64] = Q_slab @ K^T
        float sacc[8][4];
        #pragma unroll
        for (int i=0;i<8;i++)
            #pragma unroll
            for (int j=0;j<4;j++) sacc[i][j] = 0.f;
        #pragma unroll
        for (int ks = 0; ks < 16; ks++){
            int k0 = ks*8;
            unsigned af[4];
            int r = wid*16 + (lane>>2);
            int c = k0 + (lane&3);
            af[0] = f2tf(Qs[r*QST + c]);
            af[1] = f2tf(Qs[(r+8)*QST + c]);
            af[2] = f2tf(Qs[r*QST + c + 4]);
            af[3] = f2tf(Qs[(r+8)*QST + c + 4]);
            #pragma unroll
            for (int nt = 0; nt < 8; nt++){
                unsigned bf[2];
                int n = nt*8 + (lane>>2);
                bf[0] = f2tf(Kc[n*KST + k0 + (lane&3)]);
                bf[1] = f2tf(Kc[n*KST + k0 + 4 + (lane&3)]);
                mma_tf32(sacc[nt], af, bf);
            }
        }

        // online softmax
        float mx0 = -1e30f, mx1 = -1e30f;
        #pragma unroll
        for (int nt=0; nt<8; nt++){
            #pragma unroll
            for (int j=0;j<4;j++) sacc[nt][j] *= scale;
            mx0 = fmaxf(mx0, fmaxf(sacc[nt][0], sacc[nt][1]));
            mx1 = fmaxf(mx1, fmaxf(sacc[nt][2], sacc[nt][3]));
        }
        mx0 = fmaxf(mx0, __shfl_xor_sync(~0u, mx0, 1));
        mx0 = fmaxf(mx0, __shfl_xor_sync(~0u, mx0, 2));
        mx1 = fmaxf(mx1, __shfl_xor_sync(~0u, mx1, 1));
        mx1 = fmaxf(mx1, __shfl_xor_sync(~0u, mx1, 2));
        float mn0 = fmaxf(m0, mx0), mn1 = fmaxf(m1, mx1);
        float cr0 = __expf(m0 - mn0), cr1 = __expf(m1 - mn1);
        m0 = mn0; m1 = mn1;
        float rs0 = 0.f, rs1 = 0.f;
        int pr = wid*16 + (lane>>2);
        #pragma unroll
        for (int nt=0; nt<8; nt++){
            float p0 = __expf(sacc[nt][0] - mn0);
            float p1 = __expf(sacc[nt][1] - mn0);
            float p2 = __expf(sacc[nt][2] - mn1);
            float p3 = __expf(sacc[nt][3] - mn1);
            rs0 += p0 + p1; rs1 += p2 + p3;
            int pc = nt*8 + (lane&3)*2;
            *(float2*)&Ps[pr*PST + pc]     = make_float2(p0, p1);
            *(float2*)&Ps[(pr+8)*PST + pc] = make_float2(p2, p3);
        }
        rs0 += __shfl_xor_sync(~0u, rs0, 1); rs0 += __shfl_xor_sync(~0u, rs0, 2);
        rs1 += __shfl_xor_sync(~0u, rs1, 1); rs1 += __shfl_xor_sync(~0u, rs1, 2);
        l0 = l0*cr0 + rs0; l1 = l1*cr1 + rs1;
        #pragma unroll
        for (int i=0;i<16;i++){
            oacc[i][0] *= cr0; oacc[i][1] *= cr0;
            oacc[i][2] *= cr1; oacc[i][3] *= cr1;
        }
        __syncwarp();   // each warp reads only its own P rows

        // O[16x128] += P[16x64] @ V[64x128]
        #pragma unroll
        for (int ks = 0; ks < 8; ks++){
            int k0 = ks*8;
            unsigned af[4];
            int r = wid*16 + (lane>>2);
            af[0] = f2tf(Ps[r*PST + k0 + (lane&3)]);
            af[1] = f2tf(Ps[(r+8)*PST + k0 + (lane&3)]);
            af[2] = f2tf(Ps[r*PST + k0 + 4 + (lane&3)]);
            af[3] = f2tf(Ps[(r+8)*PST + k0 + 4 + (lane&3)]);
            #pragma unroll
            for (int nt = 0; nt < 16; nt++){
                unsigned bf[2];
                int n = nt*8 + (lane>>2);
                bf[0] = f2tf(Vc[(k0 + (lane&3))*VST + n]);
                bf[1] = f2tf(Vc[(k0 + 4 + (lane&3))*VST + n]);
                mma_tf32(oacc[nt], af, bf);
            }
        }
    }

    float inv0 = 1.f/l0, inv1 = 1.f/l1;
    int r = wid*16 + (lane>>2);
    float* Og0 = O + (((size_t)b*SEQ + q0 + r)*NH + h)*HDIM;
    float* Og1 = O + (((size_t)b*SEQ + q0 + r + 8)*NH + h)*HDIM;
    #pragma unroll
    for (int nt=0; nt<16; nt++){
        int c = nt*8 + (lane&3)*2;
        *(float2*)&Og0[c] = make_float2(oacc[nt][0]*inv0, oacc[nt][1]*inv0);
        *(float2*)&Og1[c] = make_float2(oacc[nt][2]*inv1, oacc[nt][3]*inv1);
    }
}

// ---------------- launch ---------------------------------------------------
extern "C" void kernel_launch(void* const* d_in, const int* in_sizes, int n_in,
                              void* d_out, int out_size){
    const float* x   = (const float*)d_in[0];
    const float* fc  = (const float*)d_in[1];
    const float* fs  = (const float*)d_in[2];
    const float* wq  = (const float*)d_in[3];
    const float* wk  = (const float*)d_in[4];
    const float* wv  = (const float*)d_in[5];
    const float* wo  = (const float*)d_in[6];
    const float* w1  = (const float*)d_in[7];
    const float* w2  = (const float*)d_in[8];
    const float* w3  = (const float*)d_in[9];
    const float* anw = (const float*)d_in[10];
    const float* fnw = (const float*)d_in[11];
    float* out = (float*)d_out;

    float *xn,*q,*k,*v,*attn,*h,*hn,*fa,*fb;
    cudaGetSymbolAddress((void**)&xn,   g_xn);
    cudaGetSymbolAddress((void**)&q,    g_q);
    cudaGetSymbolAddress((void**)&k,    g_k);
    cudaGetSymbolAddress((void**)&v,    g_v);
    cudaGetSymbolAddress((void**)&attn, g_attn);
    cudaGetSymbolAddress((void**)&h,    g_h);
    cudaGetSymbolAddress((void**)&hn,   g_hn);
    cudaGetSymbolAddress((void**)&fa,   g_ffa);
    cudaGetSymbolAddress((void**)&fb,   g_ffb);

    cudaFuncSetAttribute(gemm_kernel<false>, cudaFuncAttributeMaxDynamicSharedMemorySize, GEMM_SMEM);
    cudaFuncSetAttribute(gemm_kernel<true>,  cudaFuncAttributeMaxDynamicSharedMemorySize, GEMM_SMEM);
    cudaFuncSetAttribute(flash_kernel,       cudaFuncAttributeMaxDynamicSharedMemorySize, FLASH_SMEM);

    // 1. attn rmsnorm
    rmsnorm_kernel<<<NTOK, 256>>>(x, anw, xn);
    // 2. q,k,v projections
    dim3 g2048(DM/GBN, NTOK/GBM);     // (16,32)
    gemm_kernel<false><<<g2048, 256, GEMM_SMEM>>>(xn, wq, nullptr, q, NTOK, DM, DM);
    gemm_kernel<false><<<g2048, 256, GEMM_SMEM>>>(xn, wk, nullptr, k, NTOK, DM, DM);
    gemm_kernel<false><<<g2048, 256, GEMM_SMEM>>>(xn, wv, nullptr, v, NTOK, DM, DM);
    // 3. rope on q, k
    int nrope = NTOK*NH*64;
    rope_kernel<<<(nrope+255)/256, 256>>>(q, fc, fs);
    rope_kernel<<<(nrope+255)/256, 256>>>(k, fc, fs);
    // 4. attention
    dim3 gf(SEQ/FBQ, NH, BSZ);        // (32,16,2)
    flash_kernel<<<gf, 128, FLASH_SMEM>>>(q, k, v, attn);
    // 5. output proj + residual
    gemm_kernel<true><<<g2048, 256, GEMM_SMEM>>>(attn, wo, x, h, NTOK, DM, DM);
    // 6. ffn rmsnorm
    rmsnorm_kernel<<<NTOK, 256>>>(h, fnw, hn);
    // 7. w1 / w3
    dim3 ghid(HID/GBN, NTOK/GBM);     // (44,32)
    gemm_kernel<false><<<ghid, 256, GEMM_SMEM>>>(hn, w1, nullptr, fa, NTOK, HID, DM);
    gemm_kernel<false><<<ghid, 256, GEMM_SMEM>>>(hn, w3, nullptr, fb, NTOK, HID, DM);
    // 8. silu * gate
    int nff = NTOK*HID;
    silu_mul_kernel<<<(nff+255)/256, 256>>>(fa, fb, nff);
    // 9. w2 + residual -> out
    gemm_kernel<true><<<g2048, 256, GEMM_SMEM>>>(fa, w2, h, out, NTOK, DM, HID);
}

// round 3
// speedup vs baseline: 1.2163x; 1.2163x over previous
#include <cuda_runtime.h>
#include <cuda_bf16.h>
#include <math.h>
#include <stdint.h>

#define BSZ   2
#define SEQ   2048
#define DM    2048
#define NH    16
#define HDIM  128
#define HID   5632
#define NTOK  (BSZ*SEQ)     // 4096
#define QKVN  (3*DM)        // 6144
#define FFN2  (2*HID)       // 11264

// ---------------- scratch (no allocation allowed -> __device__ globals) ----
__device__ float g_xn  [NTOK*(size_t)DM];
__device__ float g_qkv [NTOK*(size_t)QKVN];
__device__ float g_attn[NTOK*(size_t)DM];
__device__ float g_h   [NTOK*(size_t)DM];
__device__ float g_hn  [NTOK*(size_t)DM];
__device__ float g_ff  [NTOK*(size_t)FFN2];
__device__ float g_ffa [NTOK*(size_t)HID];
// tf32-pre-rounded weights, original [K,N] layout (wq|wk|wv and w1|w3 fused)
__device__ float g_wqkv[DM*(size_t)QKVN];
__device__ float g_woR [DM*(size_t)DM];
__device__ float g_w13 [DM*(size_t)FFN2];
__device__ float g_w2R [HID*(size_t)DM];

// ---------------- helpers --------------------------------------------------
__device__ __forceinline__ unsigned f2tf(float x){
    unsigned r; asm("cvt.rna.tf32.f32 %0, %1;" : "=r"(r) : "f"(x)); return r;
}
__device__ __forceinline__ float f2tf_f(float x){ return __uint_as_float(f2tf(x)); }

__device__ __forceinline__ void mma_tf32(float c[4], const unsigned a[4], const unsigned b[2]){
    asm volatile("mma.sync.aligned.m16n8k8.row.col.f32.tf32.tf32.f32 "
        "{%0,%1,%2,%3},{%4,%5,%6,%7},{%8,%9},{%0,%1,%2,%3};"
        : "+f"(c[0]), "+f"(c[1]), "+f"(c[2]), "+f"(c[3])
        : "r"(a[0]), "r"(a[1]), "r"(a[2]), "r"(a[3]), "r"(b[0]), "r"(b[1]));
}
__device__ __forceinline__ void cp16(void* dst, const float* src){
    unsigned d = (unsigned)__cvta_generic_to_shared(dst);
    asm volatile("cp.async.cg.shared.global [%0], [%1], 16;" :: "r"(d), "l"(src));
}
__device__ __forceinline__ void cp_commit(){ asm volatile("cp.async.commit_group;"); }
__device__ __forceinline__ void cp_wait0(){ asm volatile("cp.async.wait_group 0;"); }

// ---------------- weight rounding / fusing prepass -------------------------
// dst[k, col0 + j] = round_tf32(src[k, j]),  j in [0, Ns)
__global__ void round_cols(const float* __restrict__ src, float* __restrict__ dst,
                           int Ns, int Nd, int col0, int total4){
    int idx = blockIdx.x*blockDim.x + threadIdx.x;
    if (idx >= total4) return;
    int ns4 = Ns >> 2;
    int k = idx / ns4, j = (idx - k*ns4) << 2;
    float4 v = *(const float4*)(src + (size_t)k*Ns + j);
    v.x = f2tf_f(v.x); v.y = f2tf_f(v.y); v.z = f2tf_f(v.z); v.w = f2tf_f(v.w);
    *(float4*)(dst + (size_t)k*Nd + col0 + j) = v;
}

// ---------------- rmsnorm (output tf32-rounded) ----------------------------
__global__ void rmsnorm_kernel(const float* __restrict__ x, const float* __restrict__ w,
                               float* __restrict__ out){
    int row = blockIdx.x;
    const float* xr = x + (size_t)row*DM;
    float* orow = out + (size_t)row*DM;
    float ss = 0.f;
    for (int i = threadIdx.x; i < DM; i += blockDim.x){ float v = xr[i]; ss += v*v; }
    __shared__ float red[8];
    #pragma unroll
    for (int o = 16; o; o >>= 1) ss += __shfl_xor_sync(~0u, ss, o);
    if ((threadIdx.x & 31) == 0) red[threadIdx.x >> 5] = ss;
    __syncthreads();
    if (threadIdx.x == 0){
        float t = 0.f;
        #pragma unroll
        for (int i = 0; i < 8; i++) t += red[i];
        red[0] = t;
    }
    __syncthreads();
    float inv = rsqrtf(red[0] / (float)DM + 1e-5f);
    for (int i = threadIdx.x; i < DM; i += blockDim.x)
        orow[i] = f2tf_f(xr[i] * inv * w[i]);
}

// ---------------- rope on fused qkv buffer (rounded output) ----------------
__global__ void rope_kernel(float* __restrict__ qkv, int off,
                            const float* __restrict__ cs, const float* __restrict__ sn){
    int idx = blockIdx.x*blockDim.x + threadIdx.x;
    if (idx >= NTOK*NH*64) return;
    int i = idx & 63;
    int h = (idx >> 6) & (NH-1);
    int t = idx >> 10;
    int s = t & (SEQ-1);
    float c = cs[s*64 + i], sv = sn[s*64 + i];
    float* p = qkv + (size_t)t*QKVN + off + h*HDIM + 2*i;
    float a = p[0], b = p[1];
    p[0] = f2tf_f(a*c - b*sv);
    p[1] = f2tf_f(a*sv + b*c);
}

// ---------------- silu(w1col)*w3col on fused ff buffer (rounded) -----------
__global__ void silu_mul_kernel(const float* __restrict__ ff, float* __restrict__ out){
    int row = blockIdx.y;
    int j = blockIdx.x*blockDim.x + threadIdx.x;    // < HID
    const float* fr = ff + (size_t)row*FFN2;
    float a = fr[j], b = fr[HID + j];
    float s = a / (1.f + __expf(-a));
    out[(size_t)row*HID + j] = f2tf_f(s * b);
}

// ---------------- GEMM: C[M,N] = A[M,K] @ B[K,N] (+Add / round) ------------
// A, B hold tf32-pre-rounded fp32 bit patterns -> no cvt in the hot loop.
#define GBM 128
#define GBN 128
#define GBK 32
#define AST 36
#define BST 136
#define GEMM_SMEM ((2*GBM*AST + 2*GBK*BST)*4)   // 71680

template<bool ADD, bool ROUND>
__global__ void __launch_bounds__(256, 2)
gemm_kernel(const float* __restrict__ A, const float* __restrict__ B,
            const float* __restrict__ Add, float* __restrict__ C,
            int M, int N, int K)
{
    extern __shared__ float sm[];
    float* As = sm;
    float* Bs = sm + 2*GBM*AST;
    const int tid = threadIdx.x;
    const int lane = tid & 31, wid = tid >> 5;
    const int wm = (wid >> 2) * 64;
    const int wn = (wid & 3) * 32;
    const int bm = blockIdx.y * GBM, bn = blockIdx.x * GBN;

    float acc[4][4][4];
    #pragma unroll
    for (int i=0;i<4;i++)
        #pragma unroll
        for (int j=0;j<4;j++)
            #pragma unroll
            for (int r=0;r<4;r++) acc[i][j][r] = 0.f;

    const int nk = K / GBK;

    auto issue = [&](int kt, int st){
        const float* Ag = A + (size_t)bm*K + (size_t)kt*GBK;
        float* Ad = As + st*GBM*AST;
        #pragma unroll
        for (int i=0;i<4;i++){
            int idx = tid + i*256;
            int r = idx >> 3, c = (idx & 7) * 4;
            cp16(Ad + r*AST + c, Ag + (size_t)r*K + c);
        }
        const float* Bg = B + (size_t)kt*GBK*N + bn;
        float* Bd = Bs + st*GBK*BST;
        #pragma unroll
        for (int i=0;i<4;i++){
            int idx = tid + i*256;
            int r = idx >> 5, c = (idx & 31) * 4;
            cp16(Bd + r*BST + c, Bg + (size_t)r*N + c);
        }
        cp_commit();
    };

    issue(0, 0);
    for (int kt = 0; kt < nk; kt++){
        cp_wait0();
        __syncthreads();
        if (kt+1 < nk) issue(kt+1, (kt+1)&1);
        const unsigned* Ab = (const unsigned*)(As + (kt&1)*GBM*AST);
        const unsigned* Bb = (const unsigned*)(Bs + (kt&1)*GBK*BST);
        #pragma unroll
        for (int ks = 0; ks < 4; ks++){
            int k0 = ks*8;
            unsigned af[4][4], bf[4][2];
            #pragma unroll
            for (int mt=0; mt<4; mt++){
                int r = wm + mt*16 + (lane>>2);
                int c = k0 + (lane&3);
                af[mt][0] = Ab[r*AST + c];
                af[mt][1] = Ab[(r+8)*AST + c];
                af[mt][2] = Ab[r*AST + c + 4];
                af[mt][3] = Ab[(r+8)*AST + c + 4];
            }
            #pragma unroll
            for (int nt=0; nt<4; nt++){
                int n = wn + nt*8 + (lane>>2);
                int kk = k0 + (lane&3);
                bf[nt][0] = Bb[kk*BST + n];
                bf[nt][1] = Bb[(kk+4)*BST + n];
            }
            #pragma unroll
            for (int mt=0; mt<4; mt++)
                #pragma unroll
                for (int nt=0; nt<4; nt++)
                    mma_tf32(acc[mt][nt], af[mt], bf[nt]);
        }
    }

    #pragma unroll
    for (int mt=0; mt<4; mt++){
        #pragma unroll
        for (int nt=0; nt<4; nt++){
            int r = bm + wm + mt*16 + (lane>>2);
            int c = bn + wn + nt*8 + (lane&3)*2;
            float2 v0 = make_float2(acc[mt][nt][0], acc[mt][nt][1]);
            float2 v1 = make_float2(acc[mt][nt][2], acc[mt][nt][3]);
            if (ADD){
                const float* A0 = Add + (size_t)r*N + c;
                const float* A1 = Add + (size_t)(r+8)*N + c;
                v0.x += A0[0]; v0.y += A0[1];
                v1.x += A1[0]; v1.y += A1[1];
            }
            if (ROUND){
                v0.x = f2tf_f(v0.x); v0.y = f2tf_f(v0.y);
                v1.x = f2tf_f(v1.x); v1.y = f2tf_f(v1.y);
            }
            *(float2*)(C + (size_t)r*N + c)     = v0;
            *(float2*)(C + (size_t)(r+8)*N + c) = v1;
        }
    }
}

// ---------------- flash attention (non-causal, fused-qkv input) ------------
#define FBQ 64
#define FBK 64
#define QST 132
#define KST 132
#define VST 136
#define PST 68
#define FLASH_SMEM ((FBQ*QST + 2*FBK*KST + 2*FBK*VST + FBQ*PST)*4)   // 188416 B

__global__ void __launch_bounds__(128)
flash_kernel(const float* __restrict__ QKV, float* __restrict__ O)
{
    extern __shared__ float sm[];
    float* Qs = sm;
    float* Ks = Qs + FBQ*QST;
    float* Vs = Ks + 2*FBK*KST;
    float* Ps = Vs + 2*FBK*VST;

    const int tid = threadIdx.x, lane = tid & 31, wid = tid >> 5;
    const int qt = blockIdx.x, h = blockIdx.y, b = blockIdx.z;
    const int q0 = qt*FBQ;
    const float scale = 0.08838834764831845f;

    const float* Qg = QKV + ((size_t)b*SEQ + q0)*QKVN + h*HDIM;            // q block
    #pragma unroll
    for (int i=0;i<16;i++){
        int idx = tid + i*128;
        int r = idx >> 5, c = (idx & 31) * 4;
        cp16(Qs + r*QST + c, Qg + (size_t)r*QKVN + c);
    }

    auto issueKV = [&](int kt, int st){
        const float* Kg = QKV + ((size_t)b*SEQ + kt*FBK)*QKVN + DM   + h*HDIM;
        const float* Vg = QKV + ((size_t)b*SEQ + kt*FBK)*QKVN + 2*DM + h*HDIM;
        float* Kd = Ks + st*FBK*KST;
        float* Vd = Vs + st*FBK*VST;
        #pragma unroll
        for (int i=0;i<16;i++){
            int idx = tid + i*128;
            int r = idx >> 5, c = (idx & 31) * 4;
            cp16(Kd + r*KST + c, Kg + (size_t)r*QKVN + c);
            cp16(Vd + r*VST + c, Vg + (size_t)r*QKVN + c);
        }
        cp_commit();
    };

    issueKV(0, 0);

    float m0 = -1e30f, m1 = -1e30f, l0 = 0.f, l1 = 0.f;
    float oacc[16][4];
    #pragma unroll
    for (int i=0;i<16;i++)
        #pragma unroll
        for (int j=0;j<4;j++) oacc[i][j] = 0.f;

    const int nkt = SEQ / FBK;
    for (int kt = 0; kt < nkt; kt++){
        cp_wait0();
        __syncthreads();
        if (kt+1 < nkt) issueKV(kt+1, (kt+1)&1);
        const unsigned* Kc = (const unsigned*)(Ks + (kt&1)*FBK*KST);
        const unsigned* Vc = (const unsigned*)(Vs + (kt&1)*FBK*VST);
        const unsigned* Qu = (const unsigned*)Qs;

        float sacc[8][4];
        #pragma unroll
        for (int i=0;i<8;i++)
            #pragma unroll
            for (int j=0;j<4;j++) sacc[i][j] = 0.f;
        #pragma unroll
        for (int ks = 0; ks < 16; ks++){
            int k0 = ks*8;
            unsigned af[4];
            int r = wid*16 + (lane>>2);
            int c = k0 + (lane&3);
            af[0] = Qu[r*QST + c];
            af[1] = Qu[(r+8)*QST + c];
            af[2] = Qu[r*QST + c + 4];
            af[3] = Qu[(r+8)*QST + c + 4];
            #pragma unroll
            for (int nt = 0; nt < 8; nt++){
                unsigned bf[2];
                int n = nt*8 + (lane>>2);
                bf[0] = Kc[n*KST + k0 + (lane&3)];
                bf[1] = Kc[n*KST + k0 + 4 + (lane&3)];
                mma_tf32(sacc[nt], af, bf);
            }
        }

        float mx0 = -1e30f, mx1 = -1e30f;
        #pragma unroll
        for (int nt=0; nt<8; nt++){
            #pragma unroll
            for (int j=0;j<4;j++) sacc[nt][j] *= scale;
            mx0 = fmaxf(mx0, fmaxf(sacc[nt][0], sacc[nt][1]));
            mx1 = fmaxf(mx1, fmaxf(sacc[nt][2], sacc[nt][3]));
        }
        mx0 = fmaxf(mx0, __shfl_xor_sync(~0u, mx0, 1));
        mx0 = fmaxf(mx0, __shfl_xor_sync(~0u, mx0, 2));
        mx1 = fmaxf(mx1, __shfl_xor_sync(~0u, mx1, 1));
        mx1 = fmaxf(mx1, __shfl_xor_sync(~0u, mx1, 2));
        float mn0 = fmaxf(m0, mx0), mn1 = fmaxf(m1, mx1);
        float cr0 = __expf(m0 - mn0), cr1 = __expf(m1 - mn1);
        m0 = mn0; m1 = mn1;
        float rs0 = 0.f, rs1 = 0.f;
        int pr = wid*16 + (lane>>2);
        #pragma unroll
        for (int nt=0; nt<8; nt++){
            float p0 = f2tf_f(__expf(sacc[nt][0] - mn0));
            float p1 = f2tf_f(__expf(sacc[nt][1] - mn0));
            float p2 = f2tf_f(__expf(sacc[nt][2] - mn1));
            float p3 = f2tf_f(__expf(sacc[nt][3] - mn1));
            rs0 += p0 + p1; rs1 += p2 + p3;
            int pc = nt*8 + (lane&3)*2;
            *(float2*)&Ps[pr*PST + pc]     = make_float2(p0, p1);
            *(float2*)&Ps[(pr+8)*PST + pc] = make_float2(p2, p3);
        }
        rs0 += __shfl_xor_sync(~0u, rs0, 1); rs0 += __shfl_xor_sync(~0u, rs0, 2);
        rs1 += __shfl_xor_sync(~0u, rs1, 1); rs1 += __shfl_xor_sync(~0u, rs1, 2);
        l0 = l0*cr0 + rs0; l1 = l1*cr1 + rs1;
        #pragma unroll
        for (int i=0;i<16;i++){
            oacc[i][0] *= cr0; oacc[i][1] *= cr0;
            oacc[i][2] *= cr1; oacc[i][3] *= cr1;
        }
        __syncwarp();

        const unsigned* Pu = (const unsigned*)Ps;
        #pragma unroll
        for (int ks = 0; ks < 8; ks++){
            int k0 = ks*8;
            unsigned af[4];
            int r = wid*16 + (lane>>2);
            af[0] = Pu[r*PST + k0 + (lane&3)];
            af[1] = Pu[(r+8)*PST + k0 + (lane&3)];
            af[2] = Pu[r*PST + k0 + 4 + (lane&3)];
            af[3] = Pu[(r+8)*PST + k0 + 4 + (lane&3)];
            #pragma unroll
            for (int nt = 0; nt < 16; nt++){
                unsigned bf[2];
                int n = nt*8 + (lane>>2);
                bf[0] = Vc[(k0 + (lane&3))*VST + n];
                bf[1] = Vc[(k0 + 4 + (lane&3))*VST + n];
                mma_tf32(oacc[nt], af, bf);
            }
        }
    }

    float inv0 = 1.f/l0, inv1 = 1.f/l1;
    int r = wid*16 + (lane>>2);
    float* Og0 = O + ((size_t)b*SEQ + q0 + r)*DM + h*HDIM;
    float* Og1 = O + ((size_t)b*SEQ + q0 + r + 8)*DM + h*HDIM;
    #pragma unroll
    for (int nt=0; nt<16; nt++){
        int c = nt*8 + (lane&3)*2;
        *(float2*)&Og0[c] = make_float2(f2tf_f(oacc[nt][0]*inv0), f2tf_f(oacc[nt][1]*inv0));
        *(float2*)&Og1[c] = make_float2(f2tf_f(oacc[nt][2]*inv1), f2tf_f(oacc[nt][3]*inv1));
    }
}

// ---------------- launch ---------------------------------------------------
extern "C" void kernel_launch(void* const* d_in, const int* in_sizes, int n_in,
                              void* d_out, int out_size){
    const float* x   = (const float*)d_in[0];
    const float* fc  = (const float*)d_in[1];
    const float* fs  = (const float*)d_in[2];
    const float* wq  = (const float*)d_in[3];
    const float* wk  = (const float*)d_in[4];
    const float* wv  = (const float*)d_in[5];
    const float* wo  = (const float*)d_in[6];
    const float* w1  = (const float*)d_in[7];
    const float* w2  = (const float*)d_in[8];
    const float* w3  = (const float*)d_in[9];
    const float* anw = (const float*)d_in[10];
    const float* fnw = (const float*)d_in[11];
    float* out = (float*)d_out;

    float *xn,*qkv,*attn,*h,*hn,*ff,*ffa,*wqkv,*woR,*w13,*w2R;
    cudaGetSymbolAddress((void**)&xn,   g_xn);
    cudaGetSymbolAddress((void**)&qkv,  g_qkv);
    cudaGetSymbolAddress((void**)&attn, g_attn);
    cudaGetSymbolAddress((void**)&h,    g_h);
    cudaGetSymbolAddress((void**)&hn,   g_hn);
    cudaGetSymbolAddress((void**)&ff,   g_ff);
    cudaGetSymbolAddress((void**)&ffa,  g_ffa);
    cudaGetSymbolAddress((void**)&wqkv, g_wqkv);
    cudaGetSymbolAddress((void**)&woR,  g_woR);
    cudaGetSymbolAddress((void**)&w13,  g_w13);
    cudaGetSymbolAddress((void**)&w2R,  g_w2R);

    cudaFuncSetAttribute((const void*)gemm_kernel<false,true>,  cudaFuncAttributeMaxDynamicSharedMemorySize, GEMM_SMEM);
    cudaFuncSetAttribute((const void*)gemm_kernel<true,false>,  cudaFuncAttributeMaxDynamicSharedMemorySize, GEMM_SMEM);
    cudaFuncSetAttribute((const void*)flash_kernel, cudaFuncAttributeMaxDynamicSharedMemorySize, FLASH_SMEM);

    // weight rounding + fusing prepass
    {
        int t4 = DM*DM/4, thr = 256;
        round_cols<<<(t4+thr-1)/thr, thr>>>(wq, wqkv, DM, QKVN, 0,    t4);
        round_cols<<<(t4+thr-1)/thr, thr>>>(wk, wqkv, DM, QKVN, DM,   t4);
        round_cols<<<(t4+thr-1)/thr, thr>>>(wv, wqkv, DM, QKVN, 2*DM, t4);
        round_cols<<<(t4+thr-1)/thr, thr>>>(wo, woR,  DM, DM,   0,    t4);
        int t4h = DM*HID/4;
        round_cols<<<(t4h+thr-1)/thr, thr>>>(w1, w13, HID, FFN2, 0,   t4h);
        round_cols<<<(t4h+thr-1)/thr, thr>>>(w3, w13, HID, FFN2, HID, t4h);
        round_cols<<<(t4h+thr-1)/thr, thr>>>(w2, w2R, DM,  DM,   0,   t4h);
    }

    // 1. attn rmsnorm
    rmsnorm_kernel<<<NTOK, 256>>>(x, anw, xn);
    // 2. fused q,k,v projection (rounded output)
    dim3 gqkv(QKVN/GBN, NTOK/GBM);    // (48,32)
    gemm_kernel<false,true><<<gqkv, 256, GEMM_SMEM>>>(xn, wqkv, nullptr, qkv, NTOK, QKVN, DM);
    // 3. rope on q and k slices
    int nrope = NTOK*NH*64;
    rope_kernel<<<(nrope+255)/256, 256>>>(qkv, 0,  fc, fs);
    rope_kernel<<<(nrope+255)/256, 256>>>(qkv, DM, fc, fs);
    // 4. attention
    dim3 gf(SEQ/FBQ, NH, BSZ);        // (32,16,2)
    flash_kernel<<<gf, 128, FLASH_SMEM>>>(qkv, attn);
    // 5. output proj + residual
    dim3 g2048(DM/GBN, NTOK/GBM);     // (16,32)
    gemm_kernel<true,false><<<g2048, 256, GEMM_SMEM>>>(attn, woR, x, h, NTOK, DM, DM);
    // 6. ffn rmsnorm
    rmsnorm_kernel<<<NTOK, 256>>>(h, fnw, hn);
    // 7. fused w1/w3 (rounded output)
    dim3 gff(FFN2/GBN, NTOK/GBM);     // (88,32)
    gemm_kernel<false,true><<<gff, 256, GEMM_SMEM>>>(hn, w13, nullptr, ff, NTOK, FFN2, DM);
    // 8. silu * gate (rounded output)
    silu_mul_kernel<<<dim3(HID/256, NTOK), 256>>>(ff, ffa);
    // 9. w2 + residual -> out
    gemm_kernel<true,false><<<g2048, 256, GEMM_SMEM>>>(ffa, w2R, h, out, NTOK, DM, HID);
}

// round 4
// speedup vs baseline: 2.4478x; 2.0125x over previous
#include <cuda_runtime.h>
#include <cuda_fp16.h>
#include <math.h>
#include <stdint.h>

#define BSZ   2
#define SEQ   2048
#define DM    2048
#define NH    16
#define HDIM  128
#define HID   5632
#define NTOK  (BSZ*SEQ)     // 4096
#define QKVN  (3*DM)        // 6144
#define FFN2  (2*HID)       // 11264

// ---------------- scratch (no allocation allowed -> __device__ globals) ----
__device__ __half g_xn  [NTOK*(size_t)DM];
__device__ __half g_qkv [NTOK*(size_t)QKVN];
__device__ __half g_attn[NTOK*(size_t)DM];
__device__ float  g_h   [NTOK*(size_t)DM];
__device__ __half g_hn  [NTOK*(size_t)DM];
__device__ __half g_ff  [NTOK*(size_t)FFN2];
__device__ __half g_ffa [NTOK*(size_t)HID];
// fp16 weights, original [K,N] layout (wq|wk|wv and w1|w3 fused)
__device__ __half g_wqkv[DM*(size_t)QKVN];
__device__ __half g_wo  [DM*(size_t)DM];
__device__ __half g_w13 [DM*(size_t)FFN2];
__device__ __half g_w2  [HID*(size_t)DM];

// ---------------- helpers --------------------------------------------------
__device__ __forceinline__ uint32_t smem_u32(const void* p){
    uint32_t a;
    asm("{ .reg .u64 t; cvta.to.shared.u64 t, %1; cvt.u32.u64 %0, t; }" : "=r"(a) : "l"(p));
    return a;
}
__device__ __forceinline__ void cp16(void* dst, const void* src){
    unsigned d = (unsigned)__cvta_generic_to_shared(dst);
    asm volatile("cp.async.cg.shared.global [%0], [%1], 16;" :: "r"(d), "l"(src));
}
__device__ __forceinline__ void cp_commit(){ asm volatile("cp.async.commit_group;"); }
__device__ __forceinline__ void cp_wait0(){ asm volatile("cp.async.wait_group 0;"); }

__device__ __forceinline__ void ldm4(uint32_t r[4], uint32_t addr){
    asm volatile("ldmatrix.sync.aligned.m8n8.x4.shared.b16 {%0,%1,%2,%3}, [%4];"
        : "=r"(r[0]), "=r"(r[1]), "=r"(r[2]), "=r"(r[3]) : "r"(addr));
}
__device__ __forceinline__ void ldm4t(uint32_t r[4], uint32_t addr){
    asm volatile("ldmatrix.sync.aligned.m8n8.x4.trans.shared.b16 {%0,%1,%2,%3}, [%4];"
        : "=r"(r[0]), "=r"(r[1]), "=r"(r[2]), "=r"(r[3]) : "r"(addr));
}
__device__ __forceinline__ void mma_f16(float c[4], const uint32_t a[4], uint32_t b0, uint32_t b1){
    asm volatile("mma.sync.aligned.m16n8k16.row.col.f32.f16.f16.f32 "
        "{%0,%1,%2,%3},{%4,%5,%6,%7},{%8,%9},{%0,%1,%2,%3};"
        : "+f"(c[0]), "+f"(c[1]), "+f"(c[2]), "+f"(c[3])
        : "r"(a[0]), "r"(a[1]), "r"(a[2]), "r"(a[3]), "r"(b0), "r"(b1));
}
__device__ __forceinline__ uint32_t pkh2(float a, float b){
    __half2 h = __floats2half2_rn(a, b);
    return reinterpret_cast<uint32_t&>(h);
}
// swizzles (relative byte offsets; conflict-free ldmatrix phases)
__device__ __forceinline__ uint32_t swA(uint32_t o){ return o ^ (((o >> 7) & 7) << 4); }   // 128B rows
__device__ __forceinline__ uint32_t sw256(uint32_t o){ return o ^ (((o >> 8) & 7) << 4); } // 256B rows
__device__ __forceinline__ uint32_t sw512(uint32_t o){ return o ^ (((o >> 9) & 7) << 4); } // 512B rows

// ---------------- weight convert prepass: fp32 [K,Ns] -> fp16 [K,Nd]@col0 --
__global__ void cvt_cols(const float* __restrict__ src, __half* __restrict__ dst,
                         int Ns, int Nd, int col0, int total4){
    int idx = blockIdx.x*blockDim.x + threadIdx.x;
    if (idx >= total4) return;
    int ns4 = Ns >> 2;
    int k = idx / ns4, j = (idx - k*ns4) << 2;
    float4 v = *(const float4*)(src + (size_t)k*Ns + j);
    uint32_t lo = pkh2(v.x, v.y), hi = pkh2(v.z, v.w);
    *(uint2*)(dst + (size_t)k*Nd + col0 + j) = make_uint2(lo, hi);
}

// ---------------- rmsnorm (fp32 in -> fp16 out) ----------------------------
__global__ void rmsnorm_kernel(const float* __restrict__ x, const float* __restrict__ w,
                               __half* __restrict__ out){
    int row = blockIdx.x;
    const float* xr = x + (size_t)row*DM;
    __half* orow = out + (size_t)row*DM;
    float ss = 0.f;
    for (int i = threadIdx.x; i < DM; i += blockDim.x){ float v = xr[i]; ss += v*v; }
    __shared__ float red[8];
    #pragma unroll
    for (int o = 16; o; o >>= 1) ss += __shfl_xor_sync(~0u, ss, o);
    if ((threadIdx.x & 31) == 0) red[threadIdx.x >> 5] = ss;
    __syncthreads();
    if (threadIdx.x == 0){
        float t = 0.f;
        #pragma unroll
        for (int i = 0; i < 8; i++) t += red[i];
        red[0] = t;
    }
    __syncthreads();
    float inv = rsqrtf(red[0] / (float)DM + 1e-5f);
    for (int i = threadIdx.x; i < DM; i += blockDim.x)
        orow[i] = __float2half(xr[i] * inv * w[i]);
}

// ---------------- rope on fused qkv (fp16 in/out, fp32 math) ---------------
__global__ void rope_kernel(__half* __restrict__ qkv, int off,
                            const float* __restrict__ cs, const float* __restrict__ sn){
    int idx = blockIdx.x*blockDim.x + threadIdx.x;
    if (idx >= NTOK*NH*64) return;
    int i = idx & 63;
    int h = (idx >> 6) & (NH-1);
    int t = idx >> 10;
    int s = t & (SEQ-1);
    float c = cs[s*64 + i], sv = sn[s*64 + i];
    __half2* p = (__half2*)(qkv + (size_t)t*QKVN + off + h*HDIM + 2*i);
    float2 v = __half22float2(*p);
    *p = __floats2half2_rn(v.x*c - v.y*sv, v.x*sv + v.y*c);
}

// ---------------- silu(w1col)*w3col (fp16) ---------------------------------
__global__ void silu_mul_kernel(const __half* __restrict__ ff, __half* __restrict__ out){
    int row = blockIdx.y;
    int j = blockIdx.x*blockDim.x + threadIdx.x;    // < HID
    const __half* fr = ff + (size_t)row*FFN2;
    float a = __half2float(fr[j]), b = __half2float(fr[HID + j]);
    float s = a / (1.f + __expf(-a));
    out[(size_t)row*HID + j] = __float2half(s * b);
}

// ================= fp16 GEMM: C[M,N] = A[M,K] @ B[K,N] (+Add) ==============
// 128x256 block, 8 warps of 64x64, BK=64, double-buffered cp.async.
#define GSTG_BYTES (48*1024)
#define GEMM_SMEM  (2*GSTG_BYTES)     // 98304

template<bool ADD, bool HOUT>
__global__ void __launch_bounds__(256)
gemm_kernel(const __half* __restrict__ A, const __half* __restrict__ B,
            const float* __restrict__ Add, void* __restrict__ Cv,
            int M, int N, int K)
{
    extern __shared__ char smem[];
    const uint32_t sb = smem_u32(smem);
    const int tid = threadIdx.x, lane = tid & 31, wid = tid >> 5;
    const int wm = (wid >> 2) * 64;       // 2 warp-rows
    const int wn = (wid & 3) * 64;        // 4 warp-cols
    const int bm = blockIdx.y * 128, bn = blockIdx.x * 256;

    float acc[4][8][4];
    #pragma unroll
    for (int i=0;i<4;i++)
        #pragma unroll
        for (int j=0;j<8;j++)
            #pragma unroll
            for (int r=0;r<4;r++) acc[i][j][r] = 0.f;

    const int nk = K / 64;

    auto issue = [&](int kt, int st){
        char* Ad = smem + st*GSTG_BYTES;
        const __half* Ag = A + (size_t)bm*K + kt*64;
        #pragma unroll
        for (int i = 0; i < 4; i++){
            int idx = tid + i*256;            // 0..1023
            int m = idx >> 3, c = idx & 7;
            cp16(Ad + swA(m*128 + c*16), Ag + (size_t)m*K + c*8);
        }
        char* Bd = Ad + 16*1024;
        const __half* Bg = B + (size_t)(kt*64)*N + bn;
        #pragma unroll
        for (int i = 0; i < 8; i++){
            int idx = tid + i*256;            // 0..2047
            int k = idx >> 5, c = idx & 31;
            cp16(Bd + sw512(k*512 + c*16), Bg + (size_t)k*N + c*8);
        }
        cp_commit();
    };

    issue(0, 0);
    for (int kt = 0; kt < nk; kt++){
        cp_wait0();
        __syncthreads();
        if (kt+1 < nk) issue(kt+1, (kt+1)&1);
        const uint32_t sA = sb + (kt&1)*GSTG_BYTES;
        const uint32_t sB = sA + 16*1024;
        #pragma unroll
        for (int ks = 0; ks < 4; ks++){
            uint32_t af[4][4];
            #pragma unroll
            for (int mt = 0; mt < 4; mt++){
                int row = wm + mt*16 + (lane&7) + ((lane>>3)&1)*8;
                int ch  = 2*ks + (lane>>4);
                ldm4(af[mt], sA + swA(row*128 + ch*16));
            }
            uint32_t bf[4][4];
            #pragma unroll
            for (int ntp = 0; ntp < 4; ntp++){
                int n0 = wn + ntp*16;
                int krow = ks*16 + (lane&7) + ((lane>>3)&1)*8;
                int ch   = (n0 >> 3) + (lane>>4);
                ldm4t(bf[ntp], sB + sw512(krow*512 + ch*16));
            }
            #pragma unroll
            for (int mt = 0; mt < 4; mt++)
                #pragma unroll
                for (int ntp = 0; ntp < 4; ntp++){
                    mma_f16(acc[mt][2*ntp],   af[mt], bf[ntp][0], bf[ntp][1]);
                    mma_f16(acc[mt][2*ntp+1], af[mt], bf[ntp][2], bf[ntp][3]);
                }
        }
    }

    // epilogue
    #pragma unroll
    for (int mt = 0; mt < 4; mt++){
        #pragma unroll
        for (int nt = 0; nt < 8; nt++){
            int r = bm + wm + mt*16 + (lane>>2);
            int c = bn + wn + nt*8 + (lane&3)*2;
            float2 v0 = make_float2(acc[mt][nt][0], acc[mt][nt][1]);
            float2 v1 = make_float2(acc[mt][nt][2], acc[mt][nt][3]);
            if (ADD){
                const float* A0 = Add + (size_t)r*N + c;
                const float* A1 = Add + (size_t)(r+8)*N + c;
                v0.x += A0[0]; v0.y += A0[1];
                v1.x += A1[0]; v1.y += A1[1];
            }
            if (HOUT){
                __half* C = (__half*)Cv;
                *(uint32_t*)(C + (size_t)r*N + c)     = pkh2(v0.x, v0.y);
                *(uint32_t*)(C + (size_t)(r+8)*N + c) = pkh2(v1.x, v1.y);
            } else {
                float* C = (float*)Cv;
                *(float2*)(C + (size_t)r*N + c)     = v0;
                *(float2*)(C + (size_t)(r+8)*N + c) = v1;
            }
        }
    }
}

// ---------------- flash attention, fp16 fragments, P in registers ----------
// grid (S/64, NH, B), 128 threads; warp owns 16 q-rows.
// smem: Q 16KB | K 2x16KB | V 2x16KB = 80KB
#define FQ_OFF  0
#define FK_OFF  (16*1024)
#define FV_OFF  (48*1024)
#define FLASH_SMEM (80*1024)

__global__ void __launch_bounds__(128)
flash_kernel(const __half* __restrict__ QKV, __half* __restrict__ O)
{
    extern __shared__ char smem[];
    const uint32_t sb = smem_u32(smem);
    const int tid = threadIdx.x, lane = tid & 31, wid = tid >> 5;
    const int qt = blockIdx.x, h = blockIdx.y, b = blockIdx.z;
    const int q0 = qt*64;
    const float scale = 0.08838834764831845f;     // 1/sqrt(128)

    // Q load (group shared with KV0 commit)
    {
        const __half* Qg = QKV + ((size_t)b*SEQ + q0)*QKVN + h*HDIM;
        #pragma unroll
        for (int i = 0; i < 8; i++){
            int idx = tid + i*128;
            int r = idx >> 4, c = idx & 15;
            cp16(smem + FQ_OFF + sw256(r*256 + c*16), Qg + (size_t)r*QKVN + c*8);
        }
    }
    auto issueKV = [&](int kt, int st){
        const __half* Kg = QKV + ((size_t)b*SEQ + kt*64)*QKVN + DM   + h*HDIM;
        const __half* Vg = QKV + ((size_t)b*SEQ + kt*64)*QKVN + 2*DM + h*HDIM;
        char* Kd = smem + FK_OFF + st*16*1024;
        char* Vd = smem + FV_OFF + st*16*1024;
        #pragma unroll
        for (int i = 0; i < 8; i++){
            int idx = tid + i*128;
            int r = idx >> 4, c = idx & 15;
            uint32_t so = sw256(r*256 + c*16);
            cp16(Kd + so, Kg + (size_t)r*QKVN + c*8);
            cp16(Vd + so, Vg + (size_t)r*QKVN + c*8);
        }
        cp_commit();
    };
    issueKV(0, 0);
    cp_wait0();
    __syncthreads();

    // Q fragments -> registers for whole loop
    uint32_t qf[8][4];
    #pragma unroll
    for (int ks = 0; ks < 8; ks++){
        int row = wid*16 + (lane&7) + ((lane>>3)&1)*8;
        int ch  = 2*ks + (lane>>4);
        ldm4(qf[ks], sb + FQ_OFF + sw256(row*256 + ch*16));
    }

    float m0 = -1e30f, m1 = -1e30f, l0 = 0.f, l1 = 0.f;
    float oacc[16][4];
    #pragma unroll
    for (int i=0;i<16;i++)
        #pragma unroll
        for (int j=0;j<4;j++) oacc[i][j] = 0.f;

    const int nkt = SEQ / 64;     // 32
    for (int kt = 0; kt < nkt; kt++){
        if (kt > 0){ cp_wait0(); __syncthreads(); }
        if (kt+1 < nkt) issueKV(kt+1, (kt+1)&1);
        const uint32_t sK = sb + FK_OFF + (kt&1)*16*1024;
        const uint32_t sV = sb + FV_OFF + (kt&1)*16*1024;

        // S[16x64] = Q @ K^T
        float sacc[8][4];
        #pragma unroll
        for (int i=0;i<8;i++)
            #pragma unroll
            for (int j=0;j<4;j++) sacc[i][j] = 0.f;
        #pragma unroll
        for (int ks = 0; ks < 8; ks++){
            #pragma unroll
            for (int ntp = 0; ntp < 4; ntp++){
                uint32_t kf[4];
                int row = ntp*16 + ((lane>>4)&1)*8 + (lane&7);
                int ch  = 2*ks + ((lane>>3)&1);
                ldm4(kf, sK + sw256(row*256 + ch*16));
                mma_f16(sacc[2*ntp],   qf[ks], kf[0], kf[1]);
                mma_f16(sacc[2*ntp+1], qf[ks], kf[2], kf[3]);
            }
        }

        // online softmax (rows r=lane>>2 and r+8)
        float mx0 = -1e30f, mx1 = -1e30f;
        #pragma unroll
        for (int nt=0; nt<8; nt++){
            #pragma unroll
            for (int j=0;j<4;j++) sacc[nt][j] *= scale;
            mx0 = fmaxf(mx0, fmaxf(sacc[nt][0], sacc[nt][1]));
            mx1 = fmaxf(mx1, fmaxf(sacc[nt][2], sacc[nt][3]));
        }
        mx0 = fmaxf(mx0, __shfl_xor_sync(~0u, mx0, 1));
        mx0 = fmaxf(mx0, __shfl_xor_sync(~0u, mx0, 2));
        mx1 = fmaxf(mx1, __shfl_xor_sync(~0u, mx1, 1));
        mx1 = fmaxf(mx1, __shfl_xor_sync(~0u, mx1, 2));
        float mn0 = fmaxf(m0, mx0), mn1 = fmaxf(m1, mx1);
        float cr0 = __expf(m0 - mn0), cr1 = __expf(m1 - mn1);
        m0 = mn0; m1 = mn1;
        float rs0 = 0.f, rs1 = 0.f;
        #pragma unroll
        for (int nt=0; nt<8; nt++){
            sacc[nt][0] = __expf(sacc[nt][0] - mn0);
            sacc[nt][1] = __expf(sacc[nt][1] - mn0);
            sacc[nt][2] = __expf(sacc[nt][2] - mn1);
            sacc[nt][3] = __expf(sacc[nt][3] - mn1);
            rs0 += sacc[nt][0] + sacc[nt][1];
            rs1 += sacc[nt][2] + sacc[nt][3];
        }
        rs0 += __shfl_xor_sync(~0u, rs0, 1); rs0 += __shfl_xor_sync(~0u, rs0, 2);
        rs1 += __shfl_xor_sync(~0u, rs1, 1); rs1 += __shfl_xor_sync(~0u, rs1, 2);
        l0 = l0*cr0 + rs0; l1 = l1*cr1 + rs1;
        #pragma unroll
        for (int i=0;i<16;i++){
            oacc[i][0] *= cr0; oacc[i][1] *= cr0;
            oacc[i][2] *= cr1; oacc[i][3] *= cr1;
        }

        // O += P @ V  (P taken straight from sacc registers)
        #pragma unroll
        for (int kv = 0; kv < 4; kv++){
            uint32_t pf[4];
            pf[0] = pkh2(sacc[2*kv][0],   sacc[2*kv][1]);
            pf[1] = pkh2(sacc[2*kv][2],   sacc[2*kv][3]);
            pf[2] = pkh2(sacc[2*kv+1][0], sacc[2*kv+1][1]);
            pf[3] = pkh2(sacc[2*kv+1][2], sacc[2*kv+1][3]);
            #pragma unroll
            for (int ntp = 0; ntp < 8; ntp++){
                uint32_t vf[4];
                int row = kv*16 + (lane&7) + ((lane>>3)&1)*8;
                int ch  = 2*ntp + (lane>>4);
                ldm4t(vf, sV + sw256(row*256 + ch*16));
                mma_f16(oacc[2*ntp],   pf, vf[0], vf[1]);
                mma_f16(oacc[2*ntp+1], pf, vf[2], vf[3]);
            }
        }
    }

    float inv0 = 1.f/l0, inv1 = 1.f/l1;
    int r = wid*16 + (lane>>2);
    __half* Og0 = O + ((size_t)b*SEQ + q0 + r)*DM + h*HDIM;
    __half* Og1 = O + ((size_t)b*SEQ + q0 + r + 8)*DM + h*HDIM;
    #pragma unroll
    for (int nt=0; nt<16; nt++){
        int c = nt*8 + (lane&3)*2;
        *(uint32_t*)(Og0 + c) = pkh2(oacc[nt][0]*inv0, oacc[nt][1]*inv0);
        *(uint32_t*)(Og1 + c) = pkh2(oacc[nt][2]*inv1, oacc[nt][3]*inv1);
    }
}

// ---------------- launch ---------------------------------------------------
extern "C" void kernel_launch(void* const* d_in, const int* in_sizes, int n_in,
                              void* d_out, int out_size){
    const float* x   = (const float*)d_in[0];
    const float* fc  = (const float*)d_in[1];
    const float* fs  = (const float*)d_in[2];
    const float* wq  = (const float*)d_in[3];
    const float* wk  = (const float*)d_in[4];
    const float* wv  = (const float*)d_in[5];
    const float* wo  = (const float*)d_in[6];
    const float* w1  = (const float*)d_in[7];
    const float* w2  = (const float*)d_in[8];
    const float* w3  = (const float*)d_in[9];
    const float* anw = (const float*)d_in[10];
    const float* fnw = (const float*)d_in[11];
    float* out = (float*)d_out;

    __half *xn,*qkv,*attn,*hn,*ff,*ffa,*wqkvH,*woH,*w13H,*w2H;
    float  *h;
    cudaGetSymbolAddress((void**)&xn,    g_xn);
    cudaGetSymbolAddress((void**)&qkv,   g_qkv);
    cudaGetSymbolAddress((void**)&attn,  g_attn);
    cudaGetSymbolAddress((void**)&h,     g_h);
    cudaGetSymbolAddress((void**)&hn,    g_hn);
    cudaGetSymbolAddress((void**)&ff,    g_ff);
    cudaGetSymbolAddress((void**)&ffa,   g_ffa);
    cudaGetSymbolAddress((void**)&wqkvH, g_wqkv);
    cudaGetSymbolAddress((void**)&woH,   g_wo);
    cudaGetSymbolAddress((void**)&w13H,  g_w13);
    cudaGetSymbolAddress((void**)&w2H,   g_w2);

    cudaFuncSetAttribute((const void*)gemm_kernel<false,true>, cudaFuncAttributeMaxDynamicSharedMemorySize, GEMM_SMEM);
    cudaFuncSetAttribute((const void*)gemm_kernel<true,false>, cudaFuncAttributeMaxDynamicSharedMemorySize, GEMM_SMEM);
    cudaFuncSetAttribute((const void*)flash_kernel, cudaFuncAttributeMaxDynamicSharedMemorySize, FLASH_SMEM);

    // weight fp16 conversion + fusing prepass
    {
        int t4 = DM*DM/4, thr = 256;
        cvt_cols<<<(t4+thr-1)/thr, thr>>>(wq, wqkvH, DM, QKVN, 0,    t4);
        cvt_cols<<<(t4+thr-1)/thr, thr>>>(wk, wqkvH, DM, QKVN, DM,   t4);
        cvt_cols<<<(t4+thr-1)/thr, thr>>>(wv, wqkvH, DM, QKVN, 2*DM, t4);
        cvt_cols<<<(t4+thr-1)/thr, thr>>>(wo, woH,   DM, DM,   0,    t4);
        int t4h = DM*HID/4;
        cvt_cols<<<(t4h+thr-1)/thr, thr>>>(w1, w13H, HID, FFN2, 0,   t4h);
        cvt_cols<<<(t4h+thr-1)/thr, thr>>>(w3, w13H, HID, FFN2, HID, t4h);
        cvt_cols<<<(t4h+thr-1)/thr, thr>>>(w2, w2H,  DM,  DM,   0,   t4h);
    }

    // 1. attn rmsnorm -> fp16
    rmsnorm_kernel<<<NTOK, 256>>>(x, anw, xn);
    // 2. fused q,k,v projection -> fp16
    dim3 gqkv(QKVN/256, NTOK/128);    // (24,32)
    gemm_kernel<false,true><<<gqkv, 256, GEMM_SMEM>>>(xn, wqkvH, nullptr, qkv, NTOK, QKVN, DM);
    // 3. rope on q and k slices
    int nrope = NTOK*NH*64;
    rope_kernel<<<(nrope+255)/256, 256>>>(qkv, 0,  fc, fs);
    rope_kernel<<<(nrope+255)/256, 256>>>(qkv, DM, fc, fs);
    // 4. attention -> fp16
    dim3 gf(SEQ/64, NH, BSZ);         // (32,16,2)
    flash_kernel<<<gf, 128, FLASH_SMEM>>>(qkv, attn);
    // 5. output proj + residual -> fp32 h
    dim3 g2048(DM/256, NTOK/128);     // (8,32)
    gemm_kernel<true,false><<<g2048, 256, GEMM_SMEM>>>(attn, woH, x, h, NTOK, DM, DM);
    // 6. ffn rmsnorm -> fp16
    rmsnorm_kernel<<<NTOK, 256>>>(h, fnw, hn);
    // 7. fused w1/w3 -> fp16
    dim3 gff(FFN2/256, NTOK/128);     // (44,32)
    gemm_kernel<false,true><<<gff, 256, GEMM_SMEM>>>(hn, w13H, nullptr, ff, NTOK, FFN2, DM);
    // 8. silu * gate -> fp16
    silu_mul_kernel<<<dim3(HID/256, NTOK), 256>>>(ff, ffa);
    // 9. w2 + residual -> fp32 out
    gemm_kernel<true,false><<<g2048, 256, GEMM_SMEM>>>(ffa, w2H, h, out, NTOK, DM, HID);
}

// round 5
// speedup vs baseline: 2.5458x; 1.0401x over previous
#include <cuda_runtime.h>
#include <cuda_fp16.h>
#include <math.h>
#include <stdint.h>

#define BSZ   2
#define SEQ   2048
#define DM    2048
#define NH    16
#define HDIM  128
#define HID   5632
#define NTOK  (BSZ*SEQ)     // 4096
#define QKVN  (3*DM)        // 6144
#define FFN2  (2*HID)       // 11264

// ---------------- scratch (no allocation allowed -> __device__ globals) ----
__device__ __half g_xn  [NTOK*(size_t)DM];
__device__ __half g_qkv [NTOK*(size_t)QKVN];
__device__ __half g_attn[NTOK*(size_t)DM];
__device__ float  g_h   [NTOK*(size_t)DM];
__device__ __half g_hn  [NTOK*(size_t)DM];
__device__ __half g_ffa [NTOK*(size_t)HID];
// fp16 weights, [K,N] layout (wq|wk|wv fused; w1/w3 interleaved by 8 cols)
__device__ __half g_wqkv[DM*(size_t)QKVN];
__device__ __half g_wo  [DM*(size_t)DM];
__device__ __half g_w13 [DM*(size_t)FFN2];
__device__ __half g_w2  [HID*(size_t)DM];

// ---------------- helpers --------------------------------------------------
__device__ __forceinline__ uint32_t smem_u32(const void* p){
    uint32_t a;
    asm("{ .reg .u64 t; cvta.to.shared.u64 t, %1; cvt.u32.u64 %0, t; }" : "=r"(a) : "l"(p));
    return a;
}
__device__ __forceinline__ void cp16(void* dst, const void* src){
    unsigned d = (unsigned)__cvta_generic_to_shared(dst);
    asm volatile("cp.async.cg.shared.global [%0], [%1], 16;" :: "r"(d), "l"(src));
}
__device__ __forceinline__ void cp_commit(){ asm volatile("cp.async.commit_group;"); }
__device__ __forceinline__ void cp_wait0(){ asm volatile("cp.async.wait_group 0;"); }
__device__ __forceinline__ void cp_wait1(){ asm volatile("cp.async.wait_group 1;"); }

__device__ __forceinline__ void ldm4(uint32_t r[4], uint32_t addr){
    asm volatile("ldmatrix.sync.aligned.m8n8.x4.shared.b16 {%0,%1,%2,%3}, [%4];"
        : "=r"(r[0]), "=r"(r[1]), "=r"(r[2]), "=r"(r[3]) : "r"(addr));
}
__device__ __forceinline__ void ldm4t(uint32_t r[4], uint32_t addr){
    asm volatile("ldmatrix.sync.aligned.m8n8.x4.trans.shared.b16 {%0,%1,%2,%3}, [%4];"
        : "=r"(r[0]), "=r"(r[1]), "=r"(r[2]), "=r"(r[3]) : "r"(addr));
}
__device__ __forceinline__ void mma_f16(float c[4], const uint32_t a[4], uint32_t b0, uint32_t b1){
    asm volatile("mma.sync.aligned.m16n8k16.row.col.f32.f16.f16.f32 "
        "{%0,%1,%2,%3},{%4,%5,%6,%7},{%8,%9},{%0,%1,%2,%3};"
        : "+f"(c[0]), "+f"(c[1]), "+f"(c[2]), "+f"(c[3])
        : "r"(a[0]), "r"(a[1]), "r"(a[2]), "r"(a[3]), "r"(b0), "r"(b1));
}
__device__ __forceinline__ uint32_t pkh2(float a, float b){
    __half2 h = __floats2half2_rn(a, b);
    return reinterpret_cast<uint32_t&>(h);
}
__device__ __forceinline__ float siluf(float x){ return x / (1.f + __expf(-x)); }
// swizzles (relative byte offsets; conflict-free ldmatrix phases)
__device__ __forceinline__ uint32_t swA(uint32_t o){ return o ^ (((o >> 7) & 7) << 4); }   // 128B rows
__device__ __forceinline__ uint32_t sw256(uint32_t o){ return o ^ (((o >> 8) & 7) << 4); } // 256B rows
__device__ __forceinline__ uint32_t sw512(uint32_t o){ return o ^ (((o >> 9) & 7) << 4); } // 512B rows

// ------- weight convert prepass: fp32[K,Ns] -> fp16 dstcol = j*mul + col0 --
__global__ void cvt8(const float* __restrict__ src, __half* __restrict__ dst,
                     int Ns, int Nd, int mul, int col0, int total8){
    int idx = blockIdx.x*blockDim.x + threadIdx.x;
    if (idx >= total8) return;
    int ns8 = Ns >> 3;
    int k = idx / ns8, j = (idx - k*ns8) << 3;
    const float4* s = (const float4*)(src + (size_t)k*Ns + j);
    float4 v0 = s[0], v1 = s[1];
    uint4 o;
    o.x = pkh2(v0.x, v0.y); o.y = pkh2(v0.z, v0.w);
    o.z = pkh2(v1.x, v1.y); o.w = pkh2(v1.z, v1.w);
    *(uint4*)(dst + (size_t)k*Nd + j*mul + col0) = o;
}

// ---------------- rmsnorm (fp32 in -> fp16 out) ----------------------------
__global__ void rmsnorm_kernel(const float* __restrict__ x, const float* __restrict__ w,
                               __half* __restrict__ out){
    int row = blockIdx.x;
    const float* xr = x + (size_t)row*DM;
    __half* orow = out + (size_t)row*DM;
    float ss = 0.f;
    for (int i = threadIdx.x; i < DM; i += blockDim.x){ float v = xr[i]; ss += v*v; }
    __shared__ float red[8];
    #pragma unroll
    for (int o = 16; o; o >>= 1) ss += __shfl_xor_sync(~0u, ss, o);
    if ((threadIdx.x & 31) == 0) red[threadIdx.x >> 5] = ss;
    __syncthreads();
    if (threadIdx.x == 0){
        float t = 0.f;
        #pragma unroll
        for (int i = 0; i < 8; i++) t += red[i];
        red[0] = t;
    }
    __syncthreads();
    float inv = rsqrtf(red[0] / (float)DM + 1e-5f);
    for (int i = threadIdx.x; i < DM; i += blockDim.x)
        orow[i] = __float2half(xr[i] * inv * w[i]);
}

// ================= fp16 GEMM: C[M,N] = A[M,K] @ B[K,N] =====================
// 128x256 block, 8 warps of 64x64, BK=64, 3-stage cp.async pipeline.
// ROPE: rotate output pairs for cols < 2*DM (qkv projection).
// SILU: w1/w3 interleaved by 8 cols -> out[j]=silu(w1)*w3, fp16, width N/2.
#define GSTG_BYTES (48*1024)
#define GEMM_SMEM  (3*GSTG_BYTES)     // 147456

template<bool ADD, bool HOUT, bool ROPE, bool SILU>
__global__ void __launch_bounds__(256)
gemm_kernel(const __half* __restrict__ A, const __half* __restrict__ B,
            const float* __restrict__ Add, void* __restrict__ Cv,
            int M, int N, int K,
            const float* __restrict__ fc, const float* __restrict__ fs)
{
    extern __shared__ char smem[];
    const uint32_t sb = smem_u32(smem);
    const int tid = threadIdx.x, lane = tid & 31, wid = tid >> 5;
    const int wm = (wid >> 2) * 64;
    const int wn = (wid & 3) * 64;
    const int bm = blockIdx.y * 128, bn = blockIdx.x * 256;

    float acc[4][8][4];
    #pragma unroll
    for (int i=0;i<4;i++)
        #pragma unroll
        for (int j=0;j<8;j++)
            #pragma unroll
            for (int r=0;r<4;r++) acc[i][j][r] = 0.f;

    const int nk = K / 64;

    auto issue = [&](int kt, int st){
        char* Ad = smem + st*GSTG_BYTES;
        const __half* Ag = A + (size_t)bm*K + kt*64;
        #pragma unroll
        for (int i = 0; i < 4; i++){
            int idx = tid + i*256;
            int m = idx >> 3, c = idx & 7;
            cp16(Ad + swA(m*128 + c*16), Ag + (size_t)m*K + c*8);
        }
        char* Bd = Ad + 16*1024;
        const __half* Bg = B + (size_t)(kt*64)*N + bn;
        #pragma unroll
        for (int i = 0; i < 8; i++){
            int idx = tid + i*256;
            int k = idx >> 5, c = idx & 31;
            cp16(Bd + sw512(k*512 + c*16), Bg + (size_t)k*N + c*8);
        }
        cp_commit();
    };

    issue(0, 0);
    issue(1, 1);
    int cur = 0, nxt = 2;
    for (int kt = 0; kt < nk; kt++){
        cp_wait1();
        __syncthreads();
        if (kt+2 < nk) issue(kt+2, nxt);
        const uint32_t sA = sb + cur*GSTG_BYTES;
        const uint32_t sB = sA + 16*1024;
        if (++cur == 3) cur = 0;
        if (++nxt == 3) nxt = 0;
        #pragma unroll
        for (int ks = 0; ks < 4; ks++){
            uint32_t af[4][4];
            #pragma unroll
            for (int mt = 0; mt < 4; mt++){
                int row = wm + mt*16 + (lane&7) + ((lane>>3)&1)*8;
                int ch  = 2*ks + (lane>>4);
                ldm4(af[mt], sA + swA(row*128 + ch*16));
            }
            uint32_t bf[4][4];
            #pragma unroll
            for (int ntp = 0; ntp < 4; ntp++){
                int n0 = wn + ntp*16;
                int krow = ks*16 + (lane&7) + ((lane>>3)&1)*8;
                int ch   = (n0 >> 3) + (lane>>4);
                ldm4t(bf[ntp], sB + sw512(krow*512 + ch*16));
            }
            #pragma unroll
            for (int mt = 0; mt < 4; mt++)
                #pragma unroll
                for (int ntp = 0; ntp < 4; ntp++){
                    mma_f16(acc[mt][2*ntp],   af[mt], bf[ntp][0], bf[ntp][1]);
                    mma_f16(acc[mt][2*ntp+1], af[mt], bf[ntp][2], bf[ntp][3]);
                }
        }
    }

    // ---------------- epilogue ----------------
    if (SILU){
        __half* C = (__half*)Cv;
        const int NO = N >> 1;    // HID
        #pragma unroll
        for (int mt = 0; mt < 4; mt++){
            int r0 = bm + wm + mt*16 + (lane>>2);
            #pragma unroll
            for (int ntp = 0; ntp < 4; ntp++){
                int j = ((bn + wn) >> 1) + ntp*8 + (lane&3)*2;
                const float* a1 = acc[mt][2*ntp];     // w1 part
                const float* a3 = acc[mt][2*ntp+1];   // w3 part
                *(uint32_t*)(C + (size_t)r0*NO + j) =
                    pkh2(siluf(a1[0])*a3[0], siluf(a1[1])*a3[1]);
                *(uint32_t*)(C + (size_t)(r0+8)*NO + j) =
                    pkh2(siluf(a1[2])*a3[2], siluf(a1[3])*a3[3]);
            }
        }
        return;
    }
    #pragma unroll
    for (int mt = 0; mt < 4; mt++){
        #pragma unroll
        for (int nt = 0; nt < 8; nt++){
            int r = bm + wm + mt*16 + (lane>>2);
            int c = bn + wn + nt*8 + (lane&3)*2;
            float2 v0 = make_float2(acc[mt][nt][0], acc[mt][nt][1]);
            float2 v1 = make_float2(acc[mt][nt][2], acc[mt][nt][3]);
            if (ADD){
                const float* A0 = Add + (size_t)r*N + c;
                const float* A1 = Add + (size_t)(r+8)*N + c;
                v0.x += A0[0]; v0.y += A0[1];
                v1.x += A1[0]; v1.y += A1[1];
            }
            if (ROPE && c < 2*DM){
                int i = (c & (HDIM-1)) >> 1;
                int s0 = r & (SEQ-1), s1 = (r+8) & (SEQ-1);
                float c0 = fc[s0*64 + i], sn0 = fs[s0*64 + i];
                float c1 = fc[s1*64 + i], sn1 = fs[s1*64 + i];
                float a = v0.x, b = v0.y;
                v0.x = a*c0 - b*sn0; v0.y = a*sn0 + b*c0;
                a = v1.x; b = v1.y;
                v1.x = a*c1 - b*sn1; v1.y = a*sn1 + b*c1;
            }
            if (HOUT){
                __half* C = (__half*)Cv;
                *(uint32_t*)(C + (size_t)r*N + c)     = pkh2(v0.x, v0.y);
                *(uint32_t*)(C + (size_t)(r+8)*N + c) = pkh2(v1.x, v1.y);
            } else {
                float* C = (float*)Cv;
                *(float2*)(C + (size_t)r*N + c)     = v0;
                *(float2*)(C + (size_t)(r+8)*N + c) = v1;
            }
        }
    }
}

// ---------------- flash attention, fp16 fragments, P in registers ----------
#define FQ_OFF  0
#define FK_OFF  (16*1024)
#define FV_OFF  (48*1024)
#define FLASH_SMEM (80*1024)

__global__ void __launch_bounds__(128)
flash_kernel(const __half* __restrict__ QKV, __half* __restrict__ O)
{
    extern __shared__ char smem[];
    const uint32_t sb = smem_u32(smem);
    const int tid = threadIdx.x, lane = tid & 31, wid = tid >> 5;
    const int qt = blockIdx.x, h = blockIdx.y, b = blockIdx.z;
    const int q0 = qt*64;
    const float scale = 0.08838834764831845f;

    {
        const __half* Qg = QKV + ((size_t)b*SEQ + q0)*QKVN + h*HDIM;
        #pragma unroll
        for (int i = 0; i < 8; i++){
            int idx = tid + i*128;
            int r = idx >> 4, c = idx & 15;
            cp16(smem + FQ_OFF + sw256(r*256 + c*16), Qg + (size_t)r*QKVN + c*8);
        }
    }
    auto issueKV = [&](int kt, int st){
        const __half* Kg = QKV + ((size_t)b*SEQ + kt*64)*QKVN + DM   + h*HDIM;
        const __half* Vg = QKV + ((size_t)b*SEQ + kt*64)*QKVN + 2*DM + h*HDIM;
        char* Kd = smem + FK_OFF + st*16*1024;
        char* Vd = smem + FV_OFF + st*16*1024;
        #pragma unroll
        for (int i = 0; i < 8; i++){
            int idx = tid + i*128;
            int r = idx >> 4, c = idx & 15;
            uint32_t so = sw256(r*256 + c*16);
            cp16(Kd + so, Kg + (size_t)r*QKVN + c*8);
            cp16(Vd + so, Vg + (size_t)r*QKVN + c*8);
        }
        cp_commit();
    };
    issueKV(0, 0);
    cp_wait0();
    __syncthreads();

    uint32_t qf[8][4];
    #pragma unroll
    for (int ks = 0; ks < 8; ks++){
        int row = wid*16 + (lane&7) + ((lane>>3)&1)*8;
        int ch  = 2*ks + (lane>>4);
        ldm4(qf[ks], sb + FQ_OFF + sw256(row*256 + ch*16));
    }

    float m0 = -1e30f, m1 = -1e30f, l0 = 0.f, l1 = 0.f;
    float oacc[16][4];
    #pragma unroll
    for (int i=0;i<16;i++)
        #pragma unroll
        for (int j=0;j<4;j++) oacc[i][j] = 0.f;

    const int nkt = SEQ / 64;
    for (int kt = 0; kt < nkt; kt++){
        if (kt > 0){ cp_wait0(); __syncthreads(); }
        if (kt+1 < nkt) issueKV(kt+1, (kt+1)&1);
        const uint32_t sK = sb + FK_OFF + (kt&1)*16*1024;
        const uint32_t sV = sb + FV_OFF + (kt&1)*16*1024;

        float sacc[8][4];
        #pragma unroll
        for (int i=0;i<8;i++)
            #pragma unroll
            for (int j=0;j<4;j++) sacc[i][j] = 0.f;
        #pragma unroll
        for (int ks = 0; ks < 8; ks++){
            #pragma unroll
            for (int ntp = 0; ntp < 4; ntp++){
                uint32_t kf[4];
                int row = ntp*16 + ((lane>>4)&1)*8 + (lane&7);
                int ch  = 2*ks + ((lane>>3)&1);
                ldm4(kf, sK + sw256(row*256 + ch*16));
                mma_f16(sacc[2*ntp],   qf[ks], kf[0], kf[1]);
                mma_f16(sacc[2*ntp+1], qf[ks], kf[2], kf[3]);
            }
        }

        float mx0 = -1e30f, mx1 = -1e30f;
        #pragma unroll
        for (int nt=0; nt<8; nt++){
            #pragma unroll
            for (int j=0;j<4;j++) sacc[nt][j] *= scale;
            mx0 = fmaxf(mx0, fmaxf(sacc[nt][0], sacc[nt][1]));
            mx1 = fmaxf(mx1, fmaxf(sacc[nt][2], sacc[nt][3]));
        }
        mx0 = fmaxf(mx0, __shfl_xor_sync(~0u, mx0, 1));
        mx0 = fmaxf(mx0, __shfl_xor_sync(~0u, mx0, 2));
        mx1 = fmaxf(mx1, __shfl_xor_sync(~0u, mx1, 1));
        mx1 = fmaxf(mx1, __shfl_xor_sync(~0u, mx1, 2));
        float mn0 = fmaxf(m0, mx0), mn1 = fmaxf(m1, mx1);
        float cr0 = __expf(m0 - mn0), cr1 = __expf(m1 - mn1);
        m0 = mn0; m1 = mn1;
        float rs0 = 0.f, rs1 = 0.f;
        #pragma unroll
        for (int nt=0; nt<8; nt++){
            sacc[nt][0] = __expf(sacc[nt][0] - mn0);
            sacc[nt][1] = __expf(sacc[nt][1] - mn0);
            sacc[nt][2] = __expf(sacc[nt][2] - mn1);
            sacc[nt][3] = __expf(sacc[nt][3] - mn1);
            rs0 += sacc[nt][0] + sacc[nt][1];
            rs1 += sacc[nt][2] + sacc[nt][3];
        }
        rs0 += __shfl_xor_sync(~0u, rs0, 1); rs0 += __shfl_xor_sync(~0u, rs0, 2);
        rs1 += __shfl_xor_sync(~0u, rs1, 1); rs1 += __shfl_xor_sync(~0u, rs1, 2);
        l0 = l0*cr0 + rs0; l1 = l1*cr1 + rs1;
        #pragma unroll
        for (int i=0;i<16;i++){
            oacc[i][0] *= cr0; oacc[i][1] *= cr0;
            oacc[i][2] *= cr1; oacc[i][3] *= cr1;
        }

        #pragma unroll
        for (int kv = 0; kv < 4; kv++){
            uint32_t pf[4];
            pf[0] = pkh2(sacc[2*kv][0],   sacc[2*kv][1]);
            pf[1] = pkh2(sacc[2*kv][2],   sacc[2*kv][3]);
            pf[2] = pkh2(sacc[2*kv+1][0], sacc[2*kv+1][1]);
            pf[3] = pkh2(sacc[2*kv+1][2], sacc[2*kv+1][3]);
            #pragma unroll
            for (int ntp = 0; ntp < 8; ntp++){
                uint32_t vf[4];
                int row = kv*16 + (lane&7) + ((lane>>3)&1)*8;
                int ch  = 2*ntp + (lane>>4);
                ldm4t(vf, sV + sw256(row*256 + ch*16));
                mma_f16(oacc[2*ntp],   pf, vf[0], vf[1]);
                mma_f16(oacc[2*ntp+1], pf, vf[2], vf[3]);
            }
        }
    }

    float inv0 = 1.f/l0, inv1 = 1.f/l1;
    int r = wid*16 + (lane>>2);
    __half* Og0 = O + ((size_t)b*SEQ + q0 + r)*DM + h*HDIM;
    __half* Og1 = O + ((size_t)b*SEQ + q0 + r + 8)*DM + h*HDIM;
    #pragma unroll
    for (int nt=0; nt<16; nt++){
        int c = nt*8 + (lane&3)*2;
        *(uint32_t*)(Og0 + c) = pkh2(oacc[nt][0]*inv0, oacc[nt][1]*inv0);
        *(uint32_t*)(Og1 + c) = pkh2(oacc[nt][2]*inv1, oacc[nt][3]*inv1);
    }
}

// ---------------- launch ---------------------------------------------------
extern "C" void kernel_launch(void* const* d_in, const int* in_sizes, int n_in,
                              void* d_out, int out_size){
    const float* x   = (const float*)d_in[0];
    const float* fc  = (const float*)d_in[1];
    const float* fs  = (const float*)d_in[2];
    const float* wq  = (const float*)d_in[3];
    const float* wk  = (const float*)d_in[4];
    const float* wv  = (const float*)d_in[5];
    const float* wo  = (const float*)d_in[6];
    const float* w1  = (const float*)d_in[7];
    const float* w2  = (const float*)d_in[8];
    const float* w3  = (const float*)d_in[9];
    const float* anw = (const float*)d_in[10];
    const float* fnw = (const float*)d_in[11];
    float* out = (float*)d_out;

    __half *xn,*qkv,*attn,*hn,*ffa,*wqkvH,*woH,*w13H,*w2H;
    float  *h;
    cudaGetSymbolAddress((void**)&xn,    g_xn);
    cudaGetSymbolAddress((void**)&qkv,   g_qkv);
    cudaGetSymbolAddress((void**)&attn,  g_attn);
    cudaGetSymbolAddress((void**)&h,     g_h);
    cudaGetSymbolAddress((void**)&hn,    g_hn);
    cudaGetSymbolAddress((void**)&ffa,   g_ffa);
    cudaGetSymbolAddress((void**)&wqkvH, g_wqkv);
    cudaGetSymbolAddress((void**)&woH,   g_wo);
    cudaGetSymbolAddress((void**)&w13H,  g_w13);
    cudaGetSymbolAddress((void**)&w2H,   g_w2);

    cudaFuncSetAttribute((const void*)gemm_kernel<false,true,true,false>,  cudaFuncAttributeMaxDynamicSharedMemorySize, GEMM_SMEM);
    cudaFuncSetAttribute((const void*)gemm_kernel<true,false,false,false>, cudaFuncAttributeMaxDynamicSharedMemorySize, GEMM_SMEM);
    cudaFuncSetAttribute((const void*)gemm_kernel<false,true,false,true>,  cudaFuncAttributeMaxDynamicSharedMemorySize, GEMM_SMEM);
    cudaFuncSetAttribute((const void*)flash_kernel, cudaFuncAttributeMaxDynamicSharedMemorySize, FLASH_SMEM);

    // weight fp16 conversion + fusing prepass
    {
        int thr = 256;
        int t8 = DM*DM/8;
        cvt8<<<(t8+thr-1)/thr, thr>>>(wq, wqkvH, DM, QKVN, 1, 0,    t8);
        cvt8<<<(t8+thr-1)/thr, thr>>>(wk, wqkvH, DM, QKVN, 1, DM,   t8);
        cvt8<<<(t8+thr-1)/thr, thr>>>(wv, wqkvH, DM, QKVN, 1, 2*DM, t8);
        cvt8<<<(t8+thr-1)/thr, thr>>>(wo, woH,   DM, DM,   1, 0,    t8);
        int t8h = DM*HID/8;
        cvt8<<<(t8h+thr-1)/thr, thr>>>(w1, w13H, HID, FFN2, 2, 0,   t8h);  // interleave
        cvt8<<<(t8h+thr-1)/thr, thr>>>(w3, w13H, HID, FFN2, 2, 8,   t8h);
        cvt8<<<(t8h+thr-1)/thr, thr>>>(w2, w2H,  DM,  DM,   1, 0,   t8h);
    }

    // 1. attn rmsnorm -> fp16
    rmsnorm_kernel<<<NTOK, 256>>>(x, anw, xn);
    // 2. fused q,k,v projection with fused RoPE -> fp16
    dim3 gqkv(QKVN/256, NTOK/128);    // (24,32)
    gemm_kernel<false,true,true,false><<<gqkv, 256, GEMM_SMEM>>>(xn, wqkvH, nullptr, qkv, NTOK, QKVN, DM, fc, fs);
    // 3. attention -> fp16
    dim3 gf(SEQ/64, NH, BSZ);         // (32,16,2)
    flash_kernel<<<gf, 128, FLASH_SMEM>>>(qkv, attn);
    // 4. output proj + residual -> fp32 h
    dim3 g2048(DM/256, NTOK/128);     // (8,32)
    gemm_kernel<true,false,false,false><<<g2048, 256, GEMM_SMEM>>>(attn, woH, x, h, NTOK, DM, DM, nullptr, nullptr);
    // 5. ffn rmsnorm -> fp16
    rmsnorm_kernel<<<NTOK, 256>>>(h, fnw, hn);
    // 6. fused w1/w3 with fused silu*gate -> fp16 ffa
    dim3 gff(FFN2/256, NTOK/128);     // (44,32)
    gemm_kernel<false,true,false,true><<<gff, 256, GEMM_SMEM>>>(hn, w13H, nullptr, ffa, NTOK, FFN2, DM, nullptr, nullptr);
    // 7. w2 + residual -> fp32 out
    gemm_kernel<true,false,false,false><<<g2048, 256, GEMM_SMEM>>>(ffa, w2H, h, out, NTOK, DM, HID, nullptr, nullptr);
}

// round 6
// speedup vs baseline: 2.5806x; 1.0136x over previous
#include <cuda_runtime.h>
#include <cuda_fp16.h>
#include <math.h>
#include <stdint.h>

#define BSZ   2
#define SEQ   2048
#define DM    2048
#define NH    16
#define HDIM  128
#define HID   5632
#define NTOK  (BSZ*SEQ)     // 4096
#define QKVN  (3*DM)        // 6144
#define FFN2  (2*HID)       // 11264

// ---------------- scratch (no allocation allowed -> __device__ globals) ----
__device__ __half g_xn  [NTOK*(size_t)DM];
__device__ __half g_qkv [NTOK*(size_t)QKVN];
__device__ __half g_attn[NTOK*(size_t)DM];
__device__ float  g_h   [NTOK*(size_t)DM];
__device__ __half g_hn  [NTOK*(size_t)DM];
__device__ __half g_ffa [NTOK*(size_t)HID];
// fp16 weights, [K,N] layout (wq|wk|wv fused; w1/w3 interleaved by 8 cols)
__device__ __half g_wqkv[DM*(size_t)QKVN];
__device__ __half g_wo  [DM*(size_t)DM];
__device__ __half g_w13 [DM*(size_t)FFN2];
__device__ __half g_w2  [HID*(size_t)DM];

// ---------------- helpers --------------------------------------------------
__device__ __forceinline__ uint32_t smem_u32(const void* p){
    uint32_t a;
    asm("{ .reg .u64 t; cvta.to.shared.u64 t, %1; cvt.u32.u64 %0, t; }" : "=r"(a) : "l"(p));
    return a;
}
__device__ __forceinline__ void cp16(void* dst, const void* src){
    unsigned d = (unsigned)__cvta_generic_to_shared(dst);
    asm volatile("cp.async.cg.shared.global [%0], [%1], 16;" :: "r"(d), "l"(src));
}
__device__ __forceinline__ void cp_commit(){ asm volatile("cp.async.commit_group;"); }
__device__ __forceinline__ void cp_wait0(){ asm volatile("cp.async.wait_group 0;"); }
__device__ __forceinline__ void cp_wait2(){ asm volatile("cp.async.wait_group 2;"); }

__device__ __forceinline__ void ldm4(uint32_t r[4], uint32_t addr){
    asm volatile("ldmatrix.sync.aligned.m8n8.x4.shared.b16 {%0,%1,%2,%3}, [%4];"
        : "=r"(r[0]), "=r"(r[1]), "=r"(r[2]), "=r"(r[3]) : "r"(addr));
}
__device__ __forceinline__ void ldm4t(uint32_t r[4], uint32_t addr){
    asm volatile("ldmatrix.sync.aligned.m8n8.x4.trans.shared.b16 {%0,%1,%2,%3}, [%4];"
        : "=r"(r[0]), "=r"(r[1]), "=r"(r[2]), "=r"(r[3]) : "r"(addr));
}
__device__ __forceinline__ void mma_f16(float c[4], const uint32_t a[4], uint32_t b0, uint32_t b1){
    asm volatile("mma.sync.aligned.m16n8k16.row.col.f32.f16.f16.f32 "
        "{%0,%1,%2,%3},{%4,%5,%6,%7},{%8,%9},{%0,%1,%2,%3};"
        : "+f"(c[0]), "+f"(c[1]), "+f"(c[2]), "+f"(c[3])
        : "r"(a[0]), "r"(a[1]), "r"(a[2]), "r"(a[3]), "r"(b0), "r"(b1));
}
__device__ __forceinline__ uint32_t pkh2(float a, float b){
    __half2 h = __floats2half2_rn(a, b);
    return reinterpret_cast<uint32_t&>(h);
}
__device__ __forceinline__ float siluf(float x){ return x / (1.f + __expf(-x)); }
// swizzles (relative byte offsets; conflict-free ldmatrix phases)
__device__ __forceinline__ uint32_t swA(uint32_t o){ return o ^ (((o >> 7) & 7) << 4); }   // 128B rows
__device__ __forceinline__ uint32_t sw256(uint32_t o){ return o ^ (((o >> 8) & 7) << 4); } // 256B rows
__device__ __forceinline__ uint32_t sw512(uint32_t o){ return o ^ (((o >> 9) & 7) << 4); } // 512B rows

// ------- weight convert prepass (grouped): fp32[K,Ns] -> fp16 --------------
__device__ __forceinline__ void cvt8_body(const float* __restrict__ src, __half* __restrict__ dst,
                                          int Ns, int Nd, int mul, int col0, int total8){
    int idx = blockIdx.x*blockDim.x + threadIdx.x;
    if (idx >= total8) return;
    int ns8 = Ns >> 3;
    int k = idx / ns8, j = (idx - k*ns8) << 3;
    const float4* s = (const float4*)(src + (size_t)k*Ns + j);
    float4 v0 = s[0], v1 = s[1];
    uint4 o;
    o.x = pkh2(v0.x, v0.y); o.y = pkh2(v0.z, v0.w);
    o.z = pkh2(v1.x, v1.y); o.w = pkh2(v1.z, v1.w);
    *(uint4*)(dst + (size_t)k*Nd + j*mul + col0) = o;
}

__global__ void cvt_qkv(const float* wq, const float* wk, const float* wv, __half* dst){
    const float* srcs[3] = {wq, wk, wv};
    int y = blockIdx.y;
    cvt8_body(srcs[y], dst, DM, QKVN, 1, y*DM, DM*DM/8);
}
__global__ void cvt_w13(const float* w1, const float* w3, __half* dst){
    const float* srcs[2] = {w1, w3};
    int y = blockIdx.y;
    cvt8_body(srcs[y], dst, HID, FFN2, 2, y*8, DM*HID/8);
}
__global__ void cvt_ow2(const float* wo, const float* w2, __half* dwo, __half* dw2){
    if (blockIdx.y == 0) cvt8_body(wo, dwo, DM, DM, 1, 0, DM*DM/8);
    else                 cvt8_body(w2, dw2, DM, DM, 1, 0, HID*DM/8);
}

// ---------------- rmsnorm (fp32 in -> fp16 out, vectorized) ----------------
__global__ void rmsnorm_kernel(const float* __restrict__ x, const float* __restrict__ w,
                               __half* __restrict__ out){
    int row = blockIdx.x;
    const float4* xr = (const float4*)(x + (size_t)row*DM);
    float4 v0 = xr[threadIdx.x], v1 = xr[threadIdx.x + 256];
    float ss = v0.x*v0.x + v0.y*v0.y + v0.z*v0.z + v0.w*v0.w
             + v1.x*v1.x + v1.y*v1.y + v1.z*v1.z + v1.w*v1.w;
    __shared__ float red[8];
    #pragma unroll
    for (int o = 16; o; o >>= 1) ss += __shfl_xor_sync(~0u, ss, o);
    if ((threadIdx.x & 31) == 0) red[threadIdx.x >> 5] = ss;
    __syncthreads();
    if (threadIdx.x == 0){
        float t = 0.f;
        #pragma unroll
        for (int i = 0; i < 8; i++) t += red[i];
        red[0] = t;
    }
    __syncthreads();
    float inv = rsqrtf(red[0] / (float)DM + 1e-5f);
    const float4* w4 = (const float4*)w;
    uint2* o2 = (uint2*)(out + (size_t)row*DM);
    float4 a = w4[threadIdx.x], b = w4[threadIdx.x + 256];
    o2[threadIdx.x]       = make_uint2(pkh2(v0.x*inv*a.x, v0.y*inv*a.y), pkh2(v0.z*inv*a.z, v0.w*inv*a.w));
    o2[threadIdx.x + 256] = make_uint2(pkh2(v1.x*inv*b.x, v1.y*inv*b.y), pkh2(v1.z*inv*b.z, v1.w*inv*b.w));
}

// ================= fp16 GEMM: C[M,N] = A[M,K] @ B[K,N] =====================
// 128x256 block, 8 warps of 64x64, BK=64, 4-stage cp.async pipeline.
#define GSTG_BYTES (48*1024)
#define GEMM_SMEM  (4*GSTG_BYTES)     // 196608

template<bool ADD, bool HOUT, bool ROPE, bool SILU>
__global__ void __launch_bounds__(256)
gemm_kernel(const __half* __restrict__ A, const __half* __restrict__ B,
            const float* __restrict__ Add, void* __restrict__ Cv,
            int M, int N, int K,
            const float* __restrict__ fc, const float* __restrict__ fs)
{
    extern __shared__ char smem[];
    const uint32_t sb = smem_u32(smem);
    const int tid = threadIdx.x, lane = tid & 31, wid = tid >> 5;
    const int wm = (wid >> 2) * 64;
    const int wn = (wid & 3) * 64;
    const int bm = blockIdx.y * 128, bn = blockIdx.x * 256;

    float acc[4][8][4];
    #pragma unroll
    for (int i=0;i<4;i++)
        #pragma unroll
        for (int j=0;j<8;j++)
            #pragma unroll
            for (int r=0;r<4;r++) acc[i][j][r] = 0.f;

    const int nk = K / 64;

    auto issue = [&](int kt, int st){
        char* Ad = smem + st*GSTG_BYTES;
        const __half* Ag = A + (size_t)bm*K + kt*64;
        #pragma unroll
        for (int i = 0; i < 4; i++){
            int idx = tid + i*256;
            int m = idx >> 3, c = idx & 7;
            cp16(Ad + swA(m*128 + c*16), Ag + (size_t)m*K + c*8);
        }
        char* Bd = Ad + 16*1024;
        const __half* Bg = B + (size_t)(kt*64)*N + bn;
        #pragma unroll
        for (int i = 0; i < 8; i++){
            int idx = tid + i*256;
            int k = idx >> 5, c = idx & 31;
            cp16(Bd + sw512(k*512 + c*16), Bg + (size_t)k*N + c*8);
        }
        cp_commit();
    };

    issue(0, 0); issue(1, 1); issue(2, 2);
    int cur = 0, nxt = 3;
    for (int kt = 0; kt < nk; kt++){
        cp_wait2();
        __syncthreads();
        if (kt+3 < nk) issue(kt+3, nxt);
        const uint32_t sA = sb + cur*GSTG_BYTES;
        const uint32_t sB = sA + 16*1024;
        if (++cur == 4) cur = 0;
        if (++nxt == 4) nxt = 0;
        #pragma unroll
        for (int ks = 0; ks < 4; ks++){
            uint32_t af[4][4];
            #pragma unroll
            for (int mt = 0; mt < 4; mt++){
                int row = wm + mt*16 + (lane&7) + ((lane>>3)&1)*8;
                int ch  = 2*ks + (lane>>4);
                ldm4(af[mt], sA + swA(row*128 + ch*16));
            }
            uint32_t bf[4][4];
            #pragma unroll
            for (int ntp = 0; ntp < 4; ntp++){
                int n0 = wn + ntp*16;
                int krow = ks*16 + (lane&7) + ((lane>>3)&1)*8;
                int ch   = (n0 >> 3) + (lane>>4);
                ldm4t(bf[ntp], sB + sw512(krow*512 + ch*16));
            }
            #pragma unroll
            for (int mt = 0; mt < 4; mt++)
                #pragma unroll
                for (int ntp = 0; ntp < 4; ntp++){
                    mma_f16(acc[mt][2*ntp],   af[mt], bf[ntp][0], bf[ntp][1]);
                    mma_f16(acc[mt][2*ntp+1], af[mt], bf[ntp][2], bf[ntp][3]);
                }
        }
    }

    // ---------------- epilogue ----------------
    if (SILU){
        __half* C = (__half*)Cv;
        const int NO = N >> 1;    // HID
        #pragma unroll
        for (int mt = 0; mt < 4; mt++){
            int r0 = bm + wm + mt*16 + (lane>>2);
            #pragma unroll
            for (int ntp = 0; ntp < 4; ntp++){
                int j = ((bn + wn) >> 1) + ntp*8 + (lane&3)*2;
                const float* a1 = acc[mt][2*ntp];
                const float* a3 = acc[mt][2*ntp+1];
                *(uint32_t*)(C + (size_t)r0*NO + j) =
                    pkh2(siluf(a1[0])*a3[0], siluf(a1[1])*a3[1]);
                *(uint32_t*)(C + (size_t)(r0+8)*NO + j) =
                    pkh2(siluf(a1[2])*a3[2], siluf(a1[3])*a3[3]);
            }
        }
        return;
    }
    #pragma unroll
    for (int mt = 0; mt < 4; mt++){
        #pragma unroll
        for (int nt = 0; nt < 8; nt++){
            int r = bm + wm + mt*16 + (lane>>2);
            int c = bn + wn + nt*8 + (lane&3)*2;
            float2 v0 = make_float2(acc[mt][nt][0], acc[mt][nt][1]);
            float2 v1 = make_float2(acc[mt][nt][2], acc[mt][nt][3]);
            if (ADD){
                const float* A0 = Add + (size_t)r*N + c;
                const float* A1 = Add + (size_t)(r+8)*N + c;
                v0.x += A0[0]; v0.y += A0[1];
                v1.x += A1[0]; v1.y += A1[1];
            }
            if (ROPE && c < 2*DM){
                int i = (c & (HDIM-1)) >> 1;
                int s0 = r & (SEQ-1), s1 = (r+8) & (SEQ-1);
                float c0 = fc[s0*64 + i], sn0 = fs[s0*64 + i];
                float c1 = fc[s1*64 + i], sn1 = fs[s1*64 + i];
                float a = v0.x, b = v0.y;
                v0.x = a*c0 - b*sn0; v0.y = a*sn0 + b*c0;
                a = v1.x; b = v1.y;
                v1.x = a*c1 - b*sn1; v1.y = a*sn1 + b*c1;
            }
            if (HOUT){
                __half* C = (__half*)Cv;
                *(uint32_t*)(C + (size_t)r*N + c)     = pkh2(v0.x, v0.y);
                *(uint32_t*)(C + (size_t)(r+8)*N + c) = pkh2(v1.x, v1.y);
            } else {
                float* C = (float*)Cv;
                *(float2*)(C + (size_t)r*N + c)     = v0;
                *(float2*)(C + (size_t)(r+8)*N + c) = v1;
            }
        }
    }
}

// ---------------- flash attention, fp16 fragments, P in registers ----------
#define FQ_OFF  0
#define FK_OFF  (16*1024)
#define FV_OFF  (48*1024)
#define FLASH_SMEM (80*1024)

__global__ void __launch_bounds__(128)
flash_kernel(const __half* __restrict__ QKV, __half* __restrict__ O)
{
    extern __shared__ char smem[];
    const uint32_t sb = smem_u32(smem);
    const int tid = threadIdx.x, lane = tid & 31, wid = tid >> 5;
    const int qt = blockIdx.x, h = blockIdx.y, b = blockIdx.z;
    const int q0 = qt*64;
    const float scale = 0.08838834764831845f;

    {
        const __half* Qg = QKV + ((size_t)b*SEQ + q0)*QKVN + h*HDIM;
        #pragma unroll
        for (int i = 0; i < 8; i++){
            int idx = tid + i*128;
            int r = idx >> 4, c = idx & 15;
            cp16(smem + FQ_OFF + sw256(r*256 + c*16), Qg + (size_t)r*QKVN + c*8);
        }
    }
    auto issueKV = [&](int kt, int st){
        const __half* Kg = QKV + ((size_t)b*SEQ + kt*64)*QKVN + DM   + h*HDIM;
        const __half* Vg = QKV + ((size_t)b*SEQ + kt*64)*QKVN + 2*DM + h*HDIM;
        char* Kd = smem + FK_OFF + st*16*1024;
        char* Vd = smem + FV_OFF + st*16*1024;
        #pragma unroll
        for (int i = 0; i < 8; i++){
            int idx = tid + i*128;
            int r = idx >> 4, c = idx & 15;
            uint32_t so = sw256(r*256 + c*16);
            cp16(Kd + so, Kg + (size_t)r*QKVN + c*8);
            cp16(Vd + so, Vg + (size_t)r*QKVN + c*8);
        }
        cp_commit();
    };
    issueKV(0, 0);
    cp_wait0();
    __syncthreads();

    uint32_t qf[8][4];
    #pragma unroll
    for (int ks = 0; ks < 8; ks++){
        int row = wid*16 + (lane&7) + ((lane>>3)&1)*8;
        int ch  = 2*ks + (lane>>4);
        ldm4(qf[ks], sb + FQ_OFF + sw256(row*256 + ch*16));
    }

    float m0 = -1e30f, m1 = -1e30f, l0 = 0.f, l1 = 0.f;
    float oacc[16][4];
    #pragma unroll
    for (int i=0;i<16;i++)
        #pragma unroll
        for (int j=0;j<4;j++) oacc[i][j] = 0.f;

    const int nkt = SEQ / 64;
    for (int kt = 0; kt < nkt; kt++){
        if (kt > 0){ cp_wait0(); __syncthreads(); }
        if (kt+1 < nkt) issueKV(kt+1, (kt+1)&1);
        const uint32_t sK = sb + FK_OFF + (kt&1)*16*1024;
        const uint32_t sV = sb + FV_OFF + (kt&1)*16*1024;

        float sacc[8][4];
        #pragma unroll
        for (int i=0;i<8;i++)
            #pragma unroll
            for (int j=0;j<4;j++) sacc[i][j] = 0.f;
        #pragma unroll
        for (int ks = 0; ks < 8; ks++){
            #pragma unroll
            for (int ntp = 0; ntp < 4; ntp++){
                uint32_t kf[4];
                int row = ntp*16 + ((lane>>4)&1)*8 + (lane&7);
                int ch  = 2*ks + ((lane>>3)&1);
                ldm4(kf, sK + sw256(row*256 + ch*16));
                mma_f16(sacc[2*ntp],   qf[ks], kf[0], kf[1]);
                mma_f16(sacc[2*ntp+1], qf[ks], kf[2], kf[3]);
            }
        }

        float mx0 = -1e30f, mx1 = -1e30f;
        #pragma unroll
        for (int nt=0; nt<8; nt++){
            #pragma unroll
            for (int j=0;j<4;j++) sacc[nt][j] *= scale;
            mx0 = fmaxf(mx0, fmaxf(sacc[nt][0], sacc[nt][1]));
            mx1 = fmaxf(mx1, fmaxf(sacc[nt][2], sacc[nt][3]));
        }
        mx0 = fmaxf(mx0, __shfl_xor_sync(~0u, mx0, 1));
        mx0 = fmaxf(mx0, __shfl_xor_sync(~0u, mx0, 2));
        mx1 = fmaxf(mx1, __shfl_xor_sync(~0u, mx1, 1));
        mx1 = fmaxf(mx1, __shfl_xor_sync(~0u, mx1, 2));
        float mn0 = fmaxf(m0, mx0), mn1 = fmaxf(m1, mx1);
        float cr0 = __expf(m0 - mn0), cr1 = __expf(m1 - mn1);
        m0 = mn0; m1 = mn1;
        float rs0 = 0.f, rs1 = 0.f;
        #pragma unroll
        for (int nt=0; nt<8; nt++){
            sacc[nt][0] = __expf(sacc[nt][0] - mn0);
            sacc[nt][1] = __expf(sacc[nt][1] - mn0);
            sacc[nt][2] = __expf(sacc[nt][2] - mn1);
            sacc[nt][3] = __expf(sacc[nt][3] - mn1);
            rs0 += sacc[nt][0] + sacc[nt][1];
            rs1 += sacc[nt][2] + sacc[nt][3];
        }
        rs0 += __shfl_xor_sync(~0u, rs0, 1); rs0 += __shfl_xor_sync(~0u, rs0, 2);
        rs1 += __shfl_xor_sync(~0u, rs1, 1); rs1 += __shfl_xor_sync(~0u, rs1, 2);
        l0 = l0*cr0 + rs0; l1 = l1*cr1 + rs1;
        #pragma unroll
        for (int i=0;i<16;i++){
            oacc[i][0] *= cr0; oacc[i][1] *= cr0;
            oacc[i][2] *= cr1; oacc[i][3] *= cr1;
        }

        #pragma unroll
        for (int kv = 0; kv < 4; kv++){
            uint32_t pf[4];
            pf[0] = pkh2(sacc[2*kv][0],   sacc[2*kv][1]);
            pf[1] = pkh2(sacc[2*kv][2],   sacc[2*kv][3]);
            pf[2] = pkh2(sacc[2*kv+1][0], sacc[2*kv+1][1]);
            pf[3] = pkh2(sacc[2*kv+1][2], sacc[2*kv+1][3]);
            #pragma unroll
            for (int ntp = 0; ntp < 8; ntp++){
                uint32_t vf[4];
                int row = kv*16 + (lane&7) + ((lane>>3)&1)*8;
                int ch  = 2*ntp + (lane>>4);
                ldm4t(vf, sV + sw256(row*256 + ch*16));
                mma_f16(oacc[2*ntp],   pf, vf[0], vf[1]);
                mma_f16(oacc[2*ntp+1], pf, vf[2], vf[3]);
            }
        }
    }

    float inv0 = 1.f/l0, inv1 = 1.f/l1;
    int r = wid*16 + (lane>>2);
    __half* Og0 = O + ((size_t)b*SEQ + q0 + r)*DM + h*HDIM;
    __half* Og1 = O + ((size_t)b*SEQ + q0 + r + 8)*DM + h*HDIM;
    #pragma unroll
    for (int nt=0; nt<16; nt++){
        int c = nt*8 + (lane&3)*2;
        *(uint32_t*)(Og0 + c) = pkh2(oacc[nt][0]*inv0, oacc[nt][1]*inv0);
        *(uint32_t*)(Og1 + c) = pkh2(oacc[nt][2]*inv1, oacc[nt][3]*inv1);
    }
}

// ---------------- launch ---------------------------------------------------
extern "C" void kernel_launch(void* const* d_in, const int* in_sizes, int n_in,
                              void* d_out, int out_size){
    const float* x   = (const float*)d_in[0];
    const float* fc  = (const float*)d_in[1];
    const float* fs  = (const float*)d_in[2];
    const float* wq  = (const float*)d_in[3];
    const float* wk  = (const float*)d_in[4];
    const float* wv  = (const float*)d_in[5];
    const float* wo  = (const float*)d_in[6];
    const float* w1  = (const float*)d_in[7];
    const float* w2  = (const float*)d_in[8];
    const float* w3  = (const float*)d_in[9];
    const float* anw = (const float*)d_in[10];
    const float* fnw = (const float*)d_in[11];
    float* out = (float*)d_out;

    __half *xn,*qkv,*attn,*hn,*ffa,*wqkvH,*woH,*w13H,*w2H;
    float  *h;
    cudaGetSymbolAddress((void**)&xn,    g_xn);
    cudaGetSymbolAddress((void**)&qkv,   g_qkv);
    cudaGetSymbolAddress((void**)&attn,  g_attn);
    cudaGetSymbolAddress((void**)&h,     g_h);
    cudaGetSymbolAddress((void**)&hn,    g_hn);
    cudaGetSymbolAddress((void**)&ffa,   g_ffa);
    cudaGetSymbolAddress((void**)&wqkvH, g_wqkv);
    cudaGetSymbolAddress((void**)&woH,   g_wo);
    cudaGetSymbolAddress((void**)&w13H,  g_w13);
    cudaGetSymbolAddress((void**)&w2H,   g_w2);

    cudaFuncSetAttribute((const void*)gemm_kernel<false,true,true,false>,  cudaFuncAttributeMaxDynamicSharedMemorySize, GEMM_SMEM);
    cudaFuncSetAttribute((const void*)gemm_kernel<true,false,false,false>, cudaFuncAttributeMaxDynamicSharedMemorySize, GEMM_SMEM);
    cudaFuncSetAttribute((const void*)gemm_kernel<false,true,false,true>,  cudaFuncAttributeMaxDynamicSharedMemorySize, GEMM_SMEM);
    cudaFuncSetAttribute((const void*)flash_kernel, cudaFuncAttributeMaxDynamicSharedMemorySize, FLASH_SMEM);

    // weight fp16 conversion + fusing prepass (3 grouped launches)
    {
        int thr = 256;
        int t8  = DM*DM/8;      // 524288
        int t8h = DM*HID/8;     // 1441792
        cvt_qkv<<<dim3((t8 +thr-1)/thr, 3), thr>>>(wq, wk, wv, wqkvH);     // launch 0
        cvt_w13<<<dim3((t8h+thr-1)/thr, 2), thr>>>(w1, w3, w13H);          // launch 1
        cvt_ow2<<<dim3((t8h+thr-1)/thr, 2), thr>>>(wo, w2, woH, w2H);      // launch 2
    }

    // launch 3: attn rmsnorm -> fp16
    rmsnorm_kernel<<<NTOK, 256>>>(x, anw, xn);
    // launch 4: fused q,k,v projection with fused RoPE -> fp16
    dim3 gqkv(QKVN/256, NTOK/128);    // (24,32)
    gemm_kernel<false,true,true,false><<<gqkv, 256, GEMM_SMEM>>>(xn, wqkvH, nullptr, qkv, NTOK, QKVN, DM, fc, fs);
    // launch 5 (ncu window): attention -> fp16
    dim3 gf(SEQ/64, NH, BSZ);         // (32,16,2)
    flash_kernel<<<gf, 128, FLASH_SMEM>>>(qkv, attn);
    // output proj + residual -> fp32 h
    dim3 g2048(DM/256, NTOK/128);     // (8,32)
    gemm_kernel<true,false,false,false><<<g2048, 256, GEMM_SMEM>>>(attn, woH, x, h, NTOK, DM, DM, nullptr, nullptr);
    // ffn rmsnorm -> fp16
    rmsnorm_kernel<<<NTOK, 256>>>(h, fnw, hn);
    // fused w1/w3 with fused silu*gate -> fp16 ffa
    dim3 gff(FFN2/256, NTOK/128);     // (44,32)
    gemm_kernel<false,true,false,true><<<gff, 256, GEMM_SMEM>>>(hn, w13H, nullptr, ffa, NTOK, FFN2, DM, nullptr, nullptr);
    // w2 + residual -> fp32 out
    gemm_kernel<true,false,false,false><<<g2048, 256, GEMM_SMEM>>>(ffa, w2H, h, out, NTOK, DM, HID, nullptr, nullptr);
}

// round 7
// speedup vs baseline: 2.9533x; 1.1444x over previous
#include <cuda_runtime.h>
#include <cuda_fp16.h>
#include <math.h>
#include <stdint.h>

#define BSZ   2
#define SEQ   2048
#define DM    2048
#define NH    16
#define HDIM  128
#define HID   5632
#define NTOK  (BSZ*SEQ)     // 4096
#define QKVN  (3*DM)        // 6144
#define FFN2  (2*HID)       // 11264

// ---------------- scratch (no allocation allowed -> __device__ globals) ----
__device__ __half g_xn  [NTOK*(size_t)DM];
__device__ __half g_qkv [NTOK*(size_t)QKVN];
__device__ __half g_attn[NTOK*(size_t)DM];
__device__ float  g_h   [NTOK*(size_t)DM];
__device__ __half g_hn  [NTOK*(size_t)DM];
__device__ __half g_ffa [NTOK*(size_t)HID];
// fp16 weights, [K,N] layout (wq|wk|wv fused; w1/w3 interleaved by 8 cols)
__device__ __half g_wqkv[DM*(size_t)QKVN];
__device__ __half g_wo  [DM*(size_t)DM];
__device__ __half g_w13 [DM*(size_t)FFN2];
__device__ __half g_w2  [HID*(size_t)DM];

// ---------------- helpers --------------------------------------------------
__device__ __forceinline__ uint32_t smem_u32(const void* p){
    uint32_t a;
    asm("{ .reg .u64 t; cvta.to.shared.u64 t, %1; cvt.u32.u64 %0, t; }" : "=r"(a) : "l"(p));
    return a;
}
__device__ __forceinline__ void cp16(void* dst, const void* src){
    unsigned d = (unsigned)__cvta_generic_to_shared(dst);
    asm volatile("cp.async.cg.shared.global [%0], [%1], 16;" :: "r"(d), "l"(src));
}
__device__ __forceinline__ void cp_commit(){ asm volatile("cp.async.commit_group;"); }
__device__ __forceinline__ void cp_wait0(){ asm volatile("cp.async.wait_group 0;"); }
__device__ __forceinline__ void cp_wait1(){ asm volatile("cp.async.wait_group 1;"); }

__device__ __forceinline__ void ldm4(uint32_t r[4], uint32_t addr){
    asm volatile("ldmatrix.sync.aligned.m8n8.x4.shared.b16 {%0,%1,%2,%3}, [%4];"
        : "=r"(r[0]), "=r"(r[1]), "=r"(r[2]), "=r"(r[3]) : "r"(addr));
}
__device__ __forceinline__ void ldm4t(uint32_t r[4], uint32_t addr){
    asm volatile("ldmatrix.sync.aligned.m8n8.x4.trans.shared.b16 {%0,%1,%2,%3}, [%4];"
        : "=r"(r[0]), "=r"(r[1]), "=r"(r[2]), "=r"(r[3]) : "r"(addr));
}
__device__ __forceinline__ void mma_f16(float c[4], const uint32_t a[4], uint32_t b0, uint32_t b1){
    asm volatile("mma.sync.aligned.m16n8k16.row.col.f32.f16.f16.f32 "
        "{%0,%1,%2,%3},{%4,%5,%6,%7},{%8,%9},{%0,%1,%2,%3};"
        : "+f"(c[0]), "+f"(c[1]), "+f"(c[2]), "+f"(c[3])
        : "r"(a[0]), "r"(a[1]), "r"(a[2]), "r"(a[3]), "r"(b0), "r"(b1));
}
__device__ __forceinline__ uint32_t pkh2(float a, float b){
    __half2 h = __floats2half2_rn(a, b);
    return reinterpret_cast<uint32_t&>(h);
}
__device__ __forceinline__ float siluf(float x){ return x / (1.f + __expf(-x)); }
// swizzles (relative byte offsets; conflict-free ldmatrix phases)
__device__ __forceinline__ uint32_t swA(uint32_t o){ return o ^ (((o >> 7) & 7) << 4); }   // 128B rows
__device__ __forceinline__ uint32_t sw256(uint32_t o){ return o ^ (((o >> 8) & 7) << 4); } // 256B rows

// ------- weight convert prepass (grouped): fp32[K,Ns] -> fp16 --------------
__device__ __forceinline__ void cvt8_body(const float* __restrict__ src, __half* __restrict__ dst,
                                          int Ns, int Nd, int mul, int col0, int total8){
    int idx = blockIdx.x*blockDim.x + threadIdx.x;
    if (idx >= total8) return;
    int ns8 = Ns >> 3;
    int k = idx / ns8, j = (idx - k*ns8) << 3;
    const float4* s = (const float4*)(src + (size_t)k*Ns + j);
    float4 v0 = s[0], v1 = s[1];
    uint4 o;
    o.x = pkh2(v0.x, v0.y); o.y = pkh2(v0.z, v0.w);
    o.z = pkh2(v1.x, v1.y); o.w = pkh2(v1.z, v1.w);
    *(uint4*)(dst + (size_t)k*Nd + j*mul + col0) = o;
}

__global__ void cvt_qkv(const float* wq, const float* wk, const float* wv, __half* dst){
    const float* srcs[3] = {wq, wk, wv};
    int y = blockIdx.y;
    cvt8_body(srcs[y], dst, DM, QKVN, 1, y*DM, DM*DM/8);
}
__global__ void cvt_w13(const float* w1, const float* w3, __half* dst){
    const float* srcs[2] = {w1, w3};
    int y = blockIdx.y;
    cvt8_body(srcs[y], dst, HID, FFN2, 2, y*8, DM*HID/8);
}
__global__ void cvt_ow2(const float* wo, const float* w2, __half* dwo, __half* dw2){
    if (blockIdx.y == 0) cvt8_body(wo, dwo, DM, DM, 1, 0, DM*DM/8);
    else                 cvt8_body(w2, dw2, DM, DM, 1, 0, HID*DM/8);
}

// ---------------- rmsnorm (fp32 in -> fp16 out, vectorized) ----------------
__global__ void rmsnorm_kernel(const float* __restrict__ x, const float* __restrict__ w,
                               __half* __restrict__ out){
    int row = blockIdx.x;
    const float4* xr = (const float4*)(x + (size_t)row*DM);
    float4 v0 = xr[threadIdx.x], v1 = xr[threadIdx.x + 256];
    float ss = v0.x*v0.x + v0.y*v0.y + v0.z*v0.z + v0.w*v0.w
             + v1.x*v1.x + v1.y*v1.y + v1.z*v1.z + v1.w*v1.w;
    __shared__ float red[8];
    #pragma unroll
    for (int o = 16; o; o >>= 1) ss += __shfl_xor_sync(~0u, ss, o);
    if ((threadIdx.x & 31) == 0) red[threadIdx.x >> 5] = ss;
    __syncthreads();
    if (threadIdx.x == 0){
        float t = 0.f;
        #pragma unroll
        for (int i = 0; i < 8; i++) t += red[i];
        red[0] = t;
    }
    __syncthreads();
    float inv = rsqrtf(red[0] / (float)DM + 1e-5f);
    const float4* w4 = (const float4*)w;
    uint2* o2 = (uint2*)(out + (size_t)row*DM);
    float4 a = w4[threadIdx.x], b = w4[threadIdx.x + 256];
    o2[threadIdx.x]       = make_uint2(pkh2(v0.x*inv*a.x, v0.y*inv*a.y), pkh2(v0.z*inv*a.z, v0.w*inv*a.w));
    o2[threadIdx.x + 256] = make_uint2(pkh2(v1.x*inv*b.x, v1.y*inv*b.y), pkh2(v1.z*inv*b.z, v1.w*inv*b.w));
}

// ================= fp16 GEMM: C[M,N] = A[M,K] @ B[K,N] =====================
// 128x128 block, 8 warps of 32x64, BK=64, 3-stage cp.async, 2 CTAs/SM.
#define GSTG_BYTES (32*1024)
#define GEMM_SMEM  (3*GSTG_BYTES)     // 98304 -> 2 CTAs/SM

template<bool ADD, bool HOUT, bool ROPE, bool SILU>
__global__ void __launch_bounds__(256, 2)
gemm_kernel(const __half* __restrict__ A, const __half* __restrict__ B,
            const float* __restrict__ Add, void* __restrict__ Cv,
            int M, int N, int K,
            const float* __restrict__ fc, const float* __restrict__ fs)
{
    extern __shared__ char smem[];
    const uint32_t sb = smem_u32(smem);
    const int tid = threadIdx.x, lane = tid & 31, wid = tid >> 5;
    const int wm = (wid >> 1) * 32;       // 4 warp-rows of 32
    const int wn = (wid & 1) * 64;        // 2 warp-cols of 64
    const int bm = blockIdx.y * 128, bn = blockIdx.x * 128;

    float acc[2][8][4];
    #pragma unroll
    for (int i=0;i<2;i++)
        #pragma unroll
        for (int j=0;j<8;j++)
            #pragma unroll
            for (int r=0;r<4;r++) acc[i][j][r] = 0.f;

    const int nk = K / 64;

    auto issue = [&](int kt, int st){
        char* Ad = smem + st*GSTG_BYTES;
        const __half* Ag = A + (size_t)bm*K + kt*64;
        #pragma unroll
        for (int i = 0; i < 4; i++){
            int idx = tid + i*256;            // 0..1023
            int m = idx >> 3, c = idx & 7;
            cp16(Ad + swA(m*128 + c*16), Ag + (size_t)m*K + c*8);
        }
        char* Bd = Ad + 16*1024;
        const __half* Bg = B + (size_t)(kt*64)*N + bn;
        #pragma unroll
        for (int i = 0; i < 4; i++){
            int idx = tid + i*256;            // 0..1023
            int k = idx >> 4, c = idx & 15;
            cp16(Bd + sw256(k*256 + c*16), Bg + (size_t)k*N + c*8);
        }
        cp_commit();
    };

    issue(0, 0); issue(1, 1);
    int cur = 0, nxt = 2;
    for (int kt = 0; kt < nk; kt++){
        cp_wait1();
        __syncthreads();
        if (kt+2 < nk) issue(kt+2, nxt);
        const uint32_t sA = sb + cur*GSTG_BYTES;
        const uint32_t sB = sA + 16*1024;
        if (++cur == 3) cur = 0;
        if (++nxt == 3) nxt = 0;
        #pragma unroll
        for (int ks = 0; ks < 4; ks++){
            uint32_t af[2][4];
            #pragma unroll
            for (int mt = 0; mt < 2; mt++){
                int row = wm + mt*16 + (lane&7) + ((lane>>3)&1)*8;
                int ch  = 2*ks + (lane>>4);
                ldm4(af[mt], sA + swA(row*128 + ch*16));
            }
            uint32_t bf[4][4];
            #pragma unroll
            for (int ntp = 0; ntp < 4; ntp++){
                int krow = ks*16 + (lane&7) + ((lane>>3)&1)*8;
                int ch   = ((wn + ntp*16) >> 3) + (lane>>4);
                ldm4t(bf[ntp], sB + sw256(krow*256 + ch*16));
            }
            #pragma unroll
            for (int mt = 0; mt < 2; mt++)
                #pragma unroll
                for (int ntp = 0; ntp < 4; ntp++){
                    mma_f16(acc[mt][2*ntp],   af[mt], bf[ntp][0], bf[ntp][1]);
                    mma_f16(acc[mt][2*ntp+1], af[mt], bf[ntp][2], bf[ntp][3]);
                }
        }
    }

    // ---------------- epilogue ----------------
    if (SILU){
        __half* C = (__half*)Cv;
        const int NO = N >> 1;    // HID
        #pragma unroll
        for (int mt = 0; mt < 2; mt++){
            int r0 = bm + wm + mt*16 + (lane>>2);
            #pragma unroll
            for (int ntp = 0; ntp < 4; ntp++){
                int j = ((bn + wn) >> 1) + ntp*8 + (lane&3)*2;
                const float* a1 = acc[mt][2*ntp];
                const float* a3 = acc[mt][2*ntp+1];
                *(uint32_t*)(C + (size_t)r0*NO + j) =
                    pkh2(siluf(a1[0])*a3[0], siluf(a1[1])*a3[1]);
                *(uint32_t*)(C + (size_t)(r0+8)*NO + j) =
                    pkh2(siluf(a1[2])*a3[2], siluf(a1[3])*a3[3]);
            }
        }
        return;
    }
    #pragma unroll
    for (int mt = 0; mt < 2; mt++){
        #pragma unroll
        for (int nt = 0; nt < 8; nt++){
            int r = bm + wm + mt*16 + (lane>>2);
            int c = bn + wn + nt*8 + (lane&3)*2;
            float2 v0 = make_float2(acc[mt][nt][0], acc[mt][nt][1]);
            float2 v1 = make_float2(acc[mt][nt][2], acc[mt][nt][3]);
            if (ADD){
                const float* A0 = Add + (size_t)r*N + c;
                const float* A1 = Add + (size_t)(r+8)*N + c;
                v0.x += A0[0]; v0.y += A0[1];
                v1.x += A1[0]; v1.y += A1[1];
            }
            if (ROPE && c < 2*DM){
                int i = (c & (HDIM-1)) >> 1;
                int s0 = r & (SEQ-1), s1 = (r+8) & (SEQ-1);
                float c0 = fc[s0*64 + i], sn0 = fs[s0*64 + i];
                float c1 = fc[s1*64 + i], sn1 = fs[s1*64 + i];
                float a = v0.x, b = v0.y;
                v0.x = a*c0 - b*sn0; v0.y = a*sn0 + b*c0;
                a = v1.x; b = v1.y;
                v1.x = a*c1 - b*sn1; v1.y = a*sn1 + b*c1;
            }
            if (HOUT){
                __half* C = (__half*)Cv;
                *(uint32_t*)(C + (size_t)r*N + c)     = pkh2(v0.x, v0.y);
                *(uint32_t*)(C + (size_t)(r+8)*N + c) = pkh2(v1.x, v1.y);
            } else {
                float* C = (float*)Cv;
                *(float2*)(C + (size_t)r*N + c)     = v0;
                *(float2*)(C + (size_t)(r+8)*N + c) = v1;
            }
        }
    }
}

// ---------------- flash attention, fp16 fragments, P in registers ----------
#define FQ_OFF  0
#define FK_OFF  (16*1024)
#define FV_OFF  (48*1024)
#define FLASH_SMEM (80*1024)

__global__ void __launch_bounds__(128)
flash_kernel(const __half* __restrict__ QKV, __half* __restrict__ O)
{
    extern __shared__ char smem[];
    const uint32_t sb = smem_u32(smem);
    const int tid = threadIdx.x, lane = tid & 31, wid = tid >> 5;
    const int qt = blockIdx.x, h = blockIdx.y, b = blockIdx.z;
    const int q0 = qt*64;
    const float scale = 0.08838834764831845f;

    {
        const __half* Qg = QKV + ((size_t)b*SEQ + q0)*QKVN + h*HDIM;
        #pragma unroll
        for (int i = 0; i < 8; i++){
            int idx = tid + i*128;
            int r = idx >> 4, c = idx & 15;
            cp16(smem + FQ_OFF + sw256(r*256 + c*16), Qg + (size_t)r*QKVN + c*8);
        }
    }
    auto issueKV = [&](int kt, int st){
        const __half* Kg = QKV + ((size_t)b*SEQ + kt*64)*QKVN + DM   + h*HDIM;
        const __half* Vg = QKV + ((size_t)b*SEQ + kt*64)*QKVN + 2*DM + h*HDIM;
        char* Kd = smem + FK_OFF + st*16*1024;
        char* Vd = smem + FV_OFF + st*16*1024;
        #pragma unroll
        for (int i = 0; i < 8; i++){
            int idx = tid + i*128;
            int r = idx >> 4, c = idx & 15;
            uint32_t so = sw256(r*256 + c*16);
            cp16(Kd + so, Kg + (size_t)r*QKVN + c*8);
            cp16(Vd + so, Vg + (size_t)r*QKVN + c*8);
        }
        cp_commit();
    };
    issueKV(0, 0);
    cp_wait0();
    __syncthreads();

    uint32_t qf[8][4];
    #pragma unroll
    for (int ks = 0; ks < 8; ks++){
        int row = wid*16 + (lane&7) + ((lane>>3)&1)*8;
        int ch  = 2*ks + (lane>>4);
        ldm4(qf[ks], sb + FQ_OFF + sw256(row*256 + ch*16));
    }

    float m0 = -1e30f, m1 = -1e30f, l0 = 0.f, l1 = 0.f;
    float oacc[16][4];
    #pragma unroll
    for (int i=0;i<16;i++)
        #pragma unroll
        for (int j=0;j<4;j++) oacc[i][j] = 0.f;

    const int nkt = SEQ / 64;
    for (int kt = 0; kt < nkt; kt++){
        if (kt > 0){ cp_wait0(); __syncthreads(); }
        if (kt+1 < nkt) issueKV(kt+1, (kt+1)&1);
        const uint32_t sK = sb + FK_OFF + (kt&1)*16*1024;
        const uint32_t sV = sb + FV_OFF + (kt&1)*16*1024;

        float sacc[8][4];
        #pragma unroll
        for (int i=0;i<8;i++)
            #pragma unroll
            for (int j=0;j<4;j++) sacc[i][j] = 0.f;
        #pragma unroll
        for (int ks = 0; ks < 8; ks++){
            #pragma unroll
            for (int ntp = 0; ntp < 4; ntp++){
                uint32_t kf[4];
                int row = ntp*16 + ((lane>>4)&1)*8 + (lane&7);
                int ch  = 2*ks + ((lane>>3)&1);
                ldm4(kf, sK + sw256(row*256 + ch*16));
                mma_f16(sacc[2*ntp],   qf[ks], kf[0], kf[1]);
                mma_f16(sacc[2*ntp+1], qf[ks], kf[2], kf[3]);
            }
        }

        float mx0 = -1e30f, mx1 = -1e30f;
        #pragma unroll
        for (int nt=0; nt<8; nt++){
            #pragma unroll
            for (int j=0;j<4;j++) sacc[nt][j] *= scale;
            mx0 = fmaxf(mx0, fmaxf(sacc[nt][0], sacc[nt][1]));
            mx1 = fmaxf(mx1, fmaxf(sacc[nt][2], sacc[nt][3]));
        }
        mx0 = fmaxf(mx0, __shfl_xor_sync(~0u, mx0, 1));
        mx0 = fmaxf(mx0, __shfl_xor_sync(~0u, mx0, 2));
        mx1 = fmaxf(mx1, __shfl_xor_sync(~0u, mx1, 1));
        mx1 = fmaxf(mx1, __shfl_xor_sync(~0u, mx1, 2));
        float mn0 = fmaxf(m0, mx0), mn1 = fmaxf(m1, mx1);
        float cr0 = __expf(m0 - mn0), cr1 = __expf(m1 - mn1);
        m0 = mn0; m1 = mn1;
        float rs0 = 0.f, rs1 = 0.f;
        #pragma unroll
        for (int nt=0; nt<8; nt++){
            sacc[nt][0] = __expf(sacc[nt][0] - mn0);
            sacc[nt][1] = __expf(sacc[nt][1] - mn0);
            sacc[nt][2] = __expf(sacc[nt][2] - mn1);
            sacc[nt][3] = __expf(sacc[nt][3] - mn1);
            rs0 += sacc[nt][0] + sacc[nt][1];
            rs1 += sacc[nt][2] + sacc[nt][3];
        }
        rs0 += __shfl_xor_sync(~0u, rs0, 1); rs0 += __shfl_xor_sync(~0u, rs0, 2);
        rs1 += __shfl_xor_sync(~0u, rs1, 1); rs1 += __shfl_xor_sync(~0u, rs1, 2);
        l0 = l0*cr0 + rs0; l1 = l1*cr1 + rs1;
        #pragma unroll
        for (int i=0;i<16;i++){
            oacc[i][0] *= cr0; oacc[i][1] *= cr0;
            oacc[i][2] *= cr1; oacc[i][3] *= cr1;
        }

        #pragma unroll
        for (int kv = 0; kv < 4; kv++){
            uint32_t pf[4];
            pf[0] = pkh2(sacc[2*kv][0],   sacc[2*kv][1]);
            pf[1] = pkh2(sacc[2*kv][2],   sacc[2*kv][3]);
            pf[2] = pkh2(sacc[2*kv+1][0], sacc[2*kv+1][1]);
            pf[3] = pkh2(sacc[2*kv+1][2], sacc[2*kv+1][3]);
            #pragma unroll
            for (int ntp = 0; ntp < 8; ntp++){
                uint32_t vf[4];
                int row = kv*16 + (lane&7) + ((lane>>3)&1)*8;
                int ch  = 2*ntp + (lane>>4);
                ldm4t(vf, sV + sw256(row*256 + ch*16));
                mma_f16(oacc[2*ntp],   pf, vf[0], vf[1]);
                mma_f16(oacc[2*ntp+1], pf, vf[2], vf[3]);
            }
        }
    }

    float inv0 = 1.f/l0, inv1 = 1.f/l1;
    int r = wid*16 + (lane>>2);
    __half* Og0 = O + ((size_t)b*SEQ + q0 + r)*DM + h*HDIM;
    __half* Og1 = O + ((size_t)b*SEQ + q0 + r + 8)*DM + h*HDIM;
    #pragma unroll
    for (int nt=0; nt<16; nt++){
        int c = nt*8 + (lane&3)*2;
        *(uint32_t*)(Og0 + c) = pkh2(oacc[nt][0]*inv0, oacc[nt][1]*inv0);
        *(uint32_t*)(Og1 + c) = pkh2(oacc[nt][2]*inv1, oacc[nt][3]*inv1);
    }
}

// ---------------- launch ---------------------------------------------------
extern "C" void kernel_launch(void* const* d_in, const int* in_sizes, int n_in,
                              void* d_out, int out_size){
    const float* x   = (const float*)d_in[0];
    const float* fc  = (const float*)d_in[1];
    const float* fs  = (const float*)d_in[2];
    const float* wq  = (const float*)d_in[3];
    const float* wk  = (const float*)d_in[4];
    const float* wv  = (const float*)d_in[5];
    const float* wo  = (const float*)d_in[6];
    const float* w1  = (const float*)d_in[7];
    const float* w2  = (const float*)d_in[8];
    const float* w3  = (const float*)d_in[9];
    const float* anw = (const float*)d_in[10];
    const float* fnw = (const float*)d_in[11];
    float* out = (float*)d_out;

    __half *xn,*qkv,*attn,*hn,*ffa,*wqkvH,*woH,*w13H,*w2H;
    float  *h;
    cudaGetSymbolAddress((void**)&xn,    g_xn);
    cudaGetSymbolAddress((void**)&qkv,   g_qkv);
    cudaGetSymbolAddress((void**)&attn,  g_attn);
    cudaGetSymbolAddress((void**)&h,     g_h);
    cudaGetSymbolAddress((void**)&hn,    g_hn);
    cudaGetSymbolAddress((void**)&ffa,   g_ffa);
    cudaGetSymbolAddress((void**)&wqkvH, g_wqkv);
    cudaGetSymbolAddress((void**)&woH,   g_wo);
    cudaGetSymbolAddress((void**)&w13H,  g_w13);
    cudaGetSymbolAddress((void**)&w2H,   g_w2);

    cudaFuncSetAttribute((const void*)gemm_kernel<false,true,true,false>,  cudaFuncAttributeMaxDynamicSharedMemorySize, GEMM_SMEM);
    cudaFuncSetAttribute((const void*)gemm_kernel<true,false,false,false>, cudaFuncAttributeMaxDynamicSharedMemorySize, GEMM_SMEM);
    cudaFuncSetAttribute((const void*)gemm_kernel<false,true,false,true>,  cudaFuncAttributeMaxDynamicSharedMemorySize, GEMM_SMEM);
    cudaFuncSetAttribute((const void*)flash_kernel, cudaFuncAttributeMaxDynamicSharedMemorySize, FLASH_SMEM);

    // weight fp16 conversion + fusing prepass (3 grouped launches)
    {
        int thr = 256;
        int t8  = DM*DM/8;      // 524288
        int t8h = DM*HID/8;     // 1441792
        cvt_qkv<<<dim3((t8 +thr-1)/thr, 3), thr>>>(wq, wk, wv, wqkvH);
        cvt_w13<<<dim3((t8h+thr-1)/thr, 2), thr>>>(w1, w3, w13H);
        cvt_ow2<<<dim3((t8h+thr-1)/thr, 2), thr>>>(wo, w2, woH, w2H);
    }

    // attn rmsnorm -> fp16
    rmsnorm_kernel<<<NTOK, 256>>>(x, anw, xn);
    // fused q,k,v projection with fused RoPE -> fp16
    dim3 gqkv(QKVN/128, NTOK/128);    // (48,32)
    gemm_kernel<false,true,true,false><<<gqkv, 256, GEMM_SMEM>>>(xn, wqkvH, nullptr, qkv, NTOK, QKVN, DM, fc, fs);
    // attention -> fp16
    dim3 gf(SEQ/64, NH, BSZ);         // (32,16,2)
    flash_kernel<<<gf, 128, FLASH_SMEM>>>(qkv, attn);
    // output proj + residual -> fp32 h
    dim3 g2048(DM/128, NTOK/128);     // (16,32)
    gemm_kernel<true,false,false,false><<<g2048, 256, GEMM_SMEM>>>(attn, woH, x, h, NTOK, DM, DM, nullptr, nullptr);
    // ffn rmsnorm -> fp16
    rmsnorm_kernel<<<NTOK, 256>>>(h, fnw, hn);
    // fused w1/w3 with fused silu*gate -> fp16 ffa
    dim3 gff(FFN2/128, NTOK/128);     // (88,32)
    gemm_kernel<false,true,false,true><<<gff, 256, GEMM_SMEM>>>(hn, w13H, nullptr, ffa, NTOK, FFN2, DM, nullptr, nullptr);
    // w2 + residual -> fp32 out
    gemm_kernel<true,false,false,false><<<g2048, 256, GEMM_SMEM>>>(ffa, w2H, h, out, NTOK, DM, HID, nullptr, nullptr);
}

// round 8
// speedup vs baseline: 2.9846x; 1.0106x over previous
#include <cuda_runtime.h>
#include <cuda_fp16.h>
#include <math.h>
#include <stdint.h>

#define BSZ   2
#define SEQ   2048
#define DM    2048
#define NH    16
#define HDIM  128
#define HID   5632
#define NTOK  (BSZ*SEQ)     // 4096
#define QKVN  (3*DM)        // 6144
#define FFN2  (2*HID)       // 11264

// ---------------- scratch (no allocation allowed -> __device__ globals) ----
__device__ __half g_xn  [NTOK*(size_t)DM];
__device__ __half g_qkv [NTOK*(size_t)QKVN];
__device__ __half g_attn[NTOK*(size_t)DM];
__device__ float  g_h   [NTOK*(size_t)DM];
__device__ __half g_hn  [NTOK*(size_t)DM];
__device__ __half g_ffa [NTOK*(size_t)HID];
// fp16 weights, [K,N] layout (wq|wk|wv fused; w1/w3 interleaved by 8 cols)
__device__ __half g_wqkv[DM*(size_t)QKVN];
__device__ __half g_wo  [DM*(size_t)DM];
__device__ __half g_w13 [DM*(size_t)FFN2];
__device__ __half g_w2  [HID*(size_t)DM];

// ---------------- helpers --------------------------------------------------
__device__ __forceinline__ uint32_t smem_u32(const void* p){
    uint32_t a;
    asm("{ .reg .u64 t; cvta.to.shared.u64 t, %1; cvt.u32.u64 %0, t; }" : "=r"(a) : "l"(p));
    return a;
}
__device__ __forceinline__ void cp16(void* dst, const void* src){
    unsigned d = (unsigned)__cvta_generic_to_shared(dst);
    asm volatile("cp.async.cg.shared.global [%0], [%1], 16;" :: "r"(d), "l"(src));
}
__device__ __forceinline__ void cp_commit(){ asm volatile("cp.async.commit_group;"); }
__device__ __forceinline__ void cp_wait0(){ asm volatile("cp.async.wait_group 0;"); }
__device__ __forceinline__ void cp_wait1(){ asm volatile("cp.async.wait_group 1;"); }

__device__ __forceinline__ void ldm4(uint32_t r[4], uint32_t addr){
    asm volatile("ldmatrix.sync.aligned.m8n8.x4.shared.b16 {%0,%1,%2,%3}, [%4];"
        : "=r"(r[0]), "=r"(r[1]), "=r"(r[2]), "=r"(r[3]) : "r"(addr));
}
__device__ __forceinline__ void ldm4t(uint32_t r[4], uint32_t addr){
    asm volatile("ldmatrix.sync.aligned.m8n8.x4.trans.shared.b16 {%0,%1,%2,%3}, [%4];"
        : "=r"(r[0]), "=r"(r[1]), "=r"(r[2]), "=r"(r[3]) : "r"(addr));
}
__device__ __forceinline__ void mma_f16(float c[4], const uint32_t a[4], uint32_t b0, uint32_t b1){
    asm volatile("mma.sync.aligned.m16n8k16.row.col.f32.f16.f16.f32 "
        "{%0,%1,%2,%3},{%4,%5,%6,%7},{%8,%9},{%0,%1,%2,%3};"
        : "+f"(c[0]), "+f"(c[1]), "+f"(c[2]), "+f"(c[3])
        : "r"(a[0]), "r"(a[1]), "r"(a[2]), "r"(a[3]), "r"(b0), "r"(b1));
}
__device__ __forceinline__ uint32_t pkh2(float a, float b){
    __half2 h = __floats2half2_rn(a, b);
    return reinterpret_cast<uint32_t&>(h);
}
__device__ __forceinline__ float siluf(float x){ return x / (1.f + __expf(-x)); }
// swizzles (relative byte offsets; conflict-free ldmatrix phases)
__device__ __forceinline__ uint32_t swA(uint32_t o){ return o ^ (((o >> 7) & 7) << 4); }   // 128B rows
__device__ __forceinline__ uint32_t sw256(uint32_t o){ return o ^ (((o >> 8) & 7) << 4); } // 256B rows

// ------- weight convert prepass (grouped): fp32[K,Ns] -> fp16 --------------
__device__ __forceinline__ void cvt8_body(const float* __restrict__ src, __half* __restrict__ dst,
                                          int Ns, int Nd, int mul, int col0, int total8){
    int idx = blockIdx.x*blockDim.x + threadIdx.x;
    if (idx >= total8) return;
    int ns8 = Ns >> 3;
    int k = idx / ns8, j = (idx - k*ns8) << 3;
    const float4* s = (const float4*)(src + (size_t)k*Ns + j);
    float4 v0 = s[0], v1 = s[1];
    uint4 o;
    o.x = pkh2(v0.x, v0.y); o.y = pkh2(v0.z, v0.w);
    o.z = pkh2(v1.x, v1.y); o.w = pkh2(v1.z, v1.w);
    *(uint4*)(dst + (size_t)k*Nd + j*mul + col0) = o;
}

__global__ void cvt_qkv(const float* wq, const float* wk, const float* wv, __half* dst){
    const float* srcs[3] = {wq, wk, wv};
    int y = blockIdx.y;
    cvt8_body(srcs[y], dst, DM, QKVN, 1, y*DM, DM*DM/8);
}
__global__ void cvt_w13(const float* w1, const float* w3, __half* dst){
    const float* srcs[2] = {w1, w3};
    int y = blockIdx.y;
    cvt8_body(srcs[y], dst, HID, FFN2, 2, y*8, DM*HID/8);
}
__global__ void cvt_ow2(const float* wo, const float* w2, __half* dwo, __half* dw2){
    if (blockIdx.y == 0) cvt8_body(wo, dwo, DM, DM, 1, 0, DM*DM/8);
    else                 cvt8_body(w2, dw2, DM, DM, 1, 0, HID*DM/8);
}

// ---------------- rmsnorm (fp32 in -> fp16 out, vectorized) ----------------
__global__ void rmsnorm_kernel(const float* __restrict__ x, const float* __restrict__ w,
                               __half* __restrict__ out){
    int row = blockIdx.x;
    const float4* xr = (const float4*)(x + (size_t)row*DM);
    float4 v0 = xr[threadIdx.x], v1 = xr[threadIdx.x + 256];
    float ss = v0.x*v0.x + v0.y*v0.y + v0.z*v0.z + v0.w*v0.w
             + v1.x*v1.x + v1.y*v1.y + v1.z*v1.z + v1.w*v1.w;
    __shared__ float red[8];
    #pragma unroll
    for (int o = 16; o; o >>= 1) ss += __shfl_xor_sync(~0u, ss, o);
    if ((threadIdx.x & 31) == 0) red[threadIdx.x >> 5] = ss;
    __syncthreads();
    if (threadIdx.x == 0){
        float t = 0.f;
        #pragma unroll
        for (int i = 0; i < 8; i++) t += red[i];
        red[0] = t;
    }
    __syncthreads();
    float inv = rsqrtf(red[0] / (float)DM + 1e-5f);
    const float4* w4 = (const float4*)w;
    uint2* o2 = (uint2*)(out + (size_t)row*DM);
    float4 a = w4[threadIdx.x], b = w4[threadIdx.x + 256];
    o2[threadIdx.x]       = make_uint2(pkh2(v0.x*inv*a.x, v0.y*inv*a.y), pkh2(v0.z*inv*a.z, v0.w*inv*a.w));
    o2[threadIdx.x + 256] = make_uint2(pkh2(v1.x*inv*b.x, v1.y*inv*b.y), pkh2(v1.z*inv*b.z, v1.w*inv*b.w));
}

// ================= fp16 GEMM: C[M,N] = A[M,K] @ B[K,N] =====================
// 128x128 block, 8 warps of 32x64, BK=64, 3-stage cp.async, 2 CTAs/SM.
#define GSTG_BYTES (32*1024)
#define GEMM_SMEM  (3*GSTG_BYTES)     // 98304 -> 2 CTAs/SM

template<bool ADD, bool HOUT, bool ROPE, bool SILU>
__global__ void __launch_bounds__(256, 2)
gemm_kernel(const __half* __restrict__ A, const __half* __restrict__ B,
            const float* __restrict__ Add, void* __restrict__ Cv,
            int M, int N, int K,
            const float* __restrict__ fc, const float* __restrict__ fs)
{
    extern __shared__ char smem[];
    const uint32_t sb = smem_u32(smem);
    const int tid = threadIdx.x, lane = tid & 31, wid = tid >> 5;
    const int wm = (wid >> 1) * 32;
    const int wn = (wid & 1) * 64;
    const int bm = blockIdx.y * 128, bn = blockIdx.x * 128;

    float acc[2][8][4];
    #pragma unroll
    for (int i=0;i<2;i++)
        #pragma unroll
        for (int j=0;j<8;j++)
            #pragma unroll
            for (int r=0;r<4;r++) acc[i][j][r] = 0.f;

    const int nk = K / 64;

    auto issue = [&](int kt, int st){
        char* Ad = smem + st*GSTG_BYTES;
        const __half* Ag = A + (size_t)bm*K + kt*64;
        #pragma unroll
        for (int i = 0; i < 4; i++){
            int idx = tid + i*256;
            int m = idx >> 3, c = idx & 7;
            cp16(Ad + swA(m*128 + c*16), Ag + (size_t)m*K + c*8);
        }
        char* Bd = Ad + 16*1024;
        const __half* Bg = B + (size_t)(kt*64)*N + bn;
        #pragma unroll
        for (int i = 0; i < 4; i++){
            int idx = tid + i*256;
            int k = idx >> 4, c = idx & 15;
            cp16(Bd + sw256(k*256 + c*16), Bg + (size_t)k*N + c*8);
        }
        cp_commit();
    };

    issue(0, 0); issue(1, 1);
    int cur = 0, nxt = 2;
    for (int kt = 0; kt < nk; kt++){
        cp_wait1();
        __syncthreads();
        if (kt+2 < nk) issue(kt+2, nxt);
        const uint32_t sA = sb + cur*GSTG_BYTES;
        const uint32_t sB = sA + 16*1024;
        if (++cur == 3) cur = 0;
        if (++nxt == 3) nxt = 0;
        #pragma unroll
        for (int ks = 0; ks < 4; ks++){
            uint32_t af[2][4];
            #pragma unroll
            for (int mt = 0; mt < 2; mt++){
                int row = wm + mt*16 + (lane&7) + ((lane>>3)&1)*8;
                int ch  = 2*ks + (lane>>4);
                ldm4(af[mt], sA + swA(row*128 + ch*16));
            }
            uint32_t bf[4][4];
            #pragma unroll
            for (int ntp = 0; ntp < 4; ntp++){
                int krow = ks*16 + (lane&7) + ((lane>>3)&1)*8;
                int ch   = ((wn + ntp*16) >> 3) + (lane>>4);
                ldm4t(bf[ntp], sB + sw256(krow*256 + ch*16));
            }
            #pragma unroll
            for (int mt = 0; mt < 2; mt++)
                #pragma unroll
                for (int ntp = 0; ntp < 4; ntp++){
                    mma_f16(acc[mt][2*ntp],   af[mt], bf[ntp][0], bf[ntp][1]);
                    mma_f16(acc[mt][2*ntp+1], af[mt], bf[ntp][2], bf[ntp][3]);
                }
        }
    }

    // ---------------- epilogue ----------------
    if (SILU){
        __half* C = (__half*)Cv;
        const int NO = N >> 1;    // HID
        #pragma unroll
        for (int mt = 0; mt < 2; mt++){
            int r0 = bm + wm + mt*16 + (lane>>2);
            #pragma unroll
            for (int ntp = 0; ntp < 4; ntp++){
                int j = ((bn + wn) >> 1) + ntp*8 + (lane&3)*2;
                const float* a1 = acc[mt][2*ntp];
                const float* a3 = acc[mt][2*ntp+1];
                *(uint32_t*)(C + (size_t)r0*NO + j) =
                    pkh2(siluf(a1[0])*a3[0], siluf(a1[1])*a3[1]);
                *(uint32_t*)(C + (size_t)(r0+8)*NO + j) =
                    pkh2(siluf(a1[2])*a3[2], siluf(a1[3])*a3[3]);
            }
        }
        return;
    }
    #pragma unroll
    for (int mt = 0; mt < 2; mt++){
        #pragma unroll
        for (int nt = 0; nt < 8; nt++){
            int r = bm + wm + mt*16 + (lane>>2);
            int c = bn + wn + nt*8 + (lane&3)*2;
            float2 v0 = make_float2(acc[mt][nt][0], acc[mt][nt][1]);
            float2 v1 = make_float2(acc[mt][nt][2], acc[mt][nt][3]);
            if (ADD){
                const float* A0 = Add + (size_t)r*N + c;
                const float* A1 = Add + (size_t)(r+8)*N + c;
                v0.x += A0[0]; v0.y += A0[1];
                v1.x += A1[0]; v1.y += A1[1];
            }
            if (ROPE && c < 2*DM){
                int i = (c & (HDIM-1)) >> 1;
                int s0 = r & (SEQ-1), s1 = (r+8) & (SEQ-1);
                float c0 = fc[s0*64 + i], sn0 = fs[s0*64 + i];
                float c1 = fc[s1*64 + i], sn1 = fs[s1*64 + i];
                float a = v0.x, b = v0.y;
                v0.x = a*c0 - b*sn0; v0.y = a*sn0 + b*c0;
                a = v1.x; b = v1.y;
                v1.x = a*c1 - b*sn1; v1.y = a*sn1 + b*c1;
            }
            if (HOUT){
                __half* C = (__half*)Cv;
                *(uint32_t*)(C + (size_t)r*N + c)     = pkh2(v0.x, v0.y);
                *(uint32_t*)(C + (size_t)(r+8)*N + c) = pkh2(v1.x, v1.y);
            } else {
                float* C = (float*)Cv;
                *(float2*)(C + (size_t)r*N + c)     = v0;
                *(float2*)(C + (size_t)(r+8)*N + c) = v1;
            }
        }
    }
}

// ---------------- flash attention, BQ=128, 256 threads, P in registers -----
// smem: Q 32KB | K 2x16KB | V 2x16KB = 96KB. 8 warps, each owns 16 q-rows.
#define FQ_OFF  0
#define FK_OFF  (32*1024)
#define FV_OFF  (64*1024)
#define FLASH_SMEM (96*1024)

__global__ void __launch_bounds__(256)
flash_kernel(const __half* __restrict__ QKV, __half* __restrict__ O)
{
    extern __shared__ char smem[];
    const uint32_t sb = smem_u32(smem);
    const int tid = threadIdx.x, lane = tid & 31, wid = tid >> 5;
    const int qt = blockIdx.x, h = blockIdx.y, b = blockIdx.z;
    const int q0 = qt*128;
    const float scale = 0.08838834764831845f;

    {   // Q: 128 rows x 256B
        const __half* Qg = QKV + ((size_t)b*SEQ + q0)*QKVN + h*HDIM;
        #pragma unroll
        for (int i = 0; i < 8; i++){
            int idx = tid + i*256;            // 0..2047
            int r = idx >> 4, c = idx & 15;
            cp16(smem + FQ_OFF + sw256(r*256 + c*16), Qg + (size_t)r*QKVN + c*8);
        }
    }
    auto issueKV = [&](int kt, int st){
        const __half* Kg = QKV + ((size_t)b*SEQ + kt*64)*QKVN + DM   + h*HDIM;
        const __half* Vg = QKV + ((size_t)b*SEQ + kt*64)*QKVN + 2*DM + h*HDIM;
        char* Kd = smem + FK_OFF + st*16*1024;
        char* Vd = smem + FV_OFF + st*16*1024;
        #pragma unroll
        for (int i = 0; i < 4; i++){
            int idx = tid + i*256;            // 0..1023
            int r = idx >> 4, c = idx & 15;
            uint32_t so = sw256(r*256 + c*16);
            cp16(Kd + so, Kg + (size_t)r*QKVN + c*8);
            cp16(Vd + so, Vg + (size_t)r*QKVN + c*8);
        }
        cp_commit();
    };
    issueKV(0, 0);
    cp_wait0();
    __syncthreads();

    uint32_t qf[8][4];
    #pragma unroll
    for (int ks = 0; ks < 8; ks++){
        int row = wid*16 + (lane&7) + ((lane>>3)&1)*8;
        int ch  = 2*ks + (lane>>4);
        ldm4(qf[ks], sb + FQ_OFF + sw256(row*256 + ch*16));
    }

    float m0 = -1e30f, m1 = -1e30f, l0 = 0.f, l1 = 0.f;
    float oacc[16][4];
    #pragma unroll
    for (int i=0;i<16;i++)
        #pragma unroll
        for (int j=0;j<4;j++) oacc[i][j] = 0.f;

    const int nkt = SEQ / 64;     // 32
    for (int kt = 0; kt < nkt; kt++){
        if (kt > 0){ cp_wait0(); __syncthreads(); }
        if (kt+1 < nkt) issueKV(kt+1, (kt+1)&1);
        const uint32_t sK = sb + FK_OFF + (kt&1)*16*1024;
        const uint32_t sV = sb + FV_OFF + (kt&1)*16*1024;

        float sacc[8][4];
        #pragma unroll
        for (int i=0;i<8;i++)
            #pragma unroll
            for (int j=0;j<4;j++) sacc[i][j] = 0.f;
        #pragma unroll
        for (int ks = 0; ks < 8; ks++){
            #pragma unroll
            for (int ntp = 0; ntp < 4; ntp++){
                uint32_t kf[4];
                int row = ntp*16 + ((lane>>4)&1)*8 + (lane&7);
                int ch  = 2*ks + ((lane>>3)&1);
                ldm4(kf, sK + sw256(row*256 + ch*16));
                mma_f16(sacc[2*ntp],   qf[ks], kf[0], kf[1]);
                mma_f16(sacc[2*ntp+1], qf[ks], kf[2], kf[3]);
            }
        }

        float mx0 = -1e30f, mx1 = -1e30f;
        #pragma unroll
        for (int nt=0; nt<8; nt++){
            #pragma unroll
            for (int j=0;j<4;j++) sacc[nt][j] *= scale;
            mx0 = fmaxf(mx0, fmaxf(sacc[nt][0], sacc[nt][1]));
            mx1 = fmaxf(mx1, fmaxf(sacc[nt][2], sacc[nt][3]));
        }
        mx0 = fmaxf(mx0, __shfl_xor_sync(~0u, mx0, 1));
        mx0 = fmaxf(mx0, __shfl_xor_sync(~0u, mx0, 2));
        mx1 = fmaxf(mx1, __shfl_xor_sync(~0u, mx1, 1));
        mx1 = fmaxf(mx1, __shfl_xor_sync(~0u, mx1, 2));
        float mn0 = fmaxf(m0, mx0), mn1 = fmaxf(m1, mx1);
        float cr0 = __expf(m0 - mn0), cr1 = __expf(m1 - mn1);
        m0 = mn0; m1 = mn1;
        float rs0 = 0.f, rs1 = 0.f;
        #pragma unroll
        for (int nt=0; nt<8; nt++){
            sacc[nt][0] = __expf(sacc[nt][0] - mn0);
            sacc[nt][1] = __expf(sacc[nt][1] - mn0);
            sacc[nt][2] = __expf(sacc[nt][2] - mn1);
            sacc[nt][3] = __expf(sacc[nt][3] - mn1);
            rs0 += sacc[nt][0] + sacc[nt][1];
            rs1 += sacc[nt][2] + sacc[nt][3];
        }
        rs0 += __shfl_xor_sync(~0u, rs0, 1); rs0 += __shfl_xor_sync(~0u, rs0, 2);
        rs1 += __shfl_xor_sync(~0u, rs1, 1); rs1 += __shfl_xor_sync(~0u, rs1, 2);
        l0 = l0*cr0 + rs0; l1 = l1*cr1 + rs1;
        #pragma unroll
        for (int i=0;i<16;i++){
            oacc[i][0] *= cr0; oacc[i][1] *= cr0;
            oacc[i][2] *= cr1; oacc[i][3] *= cr1;
        }

        #pragma unroll
        for (int kv = 0; kv < 4; kv++){
            uint32_t pf[4];
            pf[0] = pkh2(sacc[2*kv][0],   sacc[2*kv][1]);
            pf[1] = pkh2(sacc[2*kv][2],   sacc[2*kv][3]);
            pf[2] = pkh2(sacc[2*kv+1][0], sacc[2*kv+1][1]);
            pf[3] = pkh2(sacc[2*kv+1][2], sacc[2*kv+1][3]);
            #pragma unroll
            for (int ntp = 0; ntp < 8; ntp++){
                uint32_t vf[4];
                int row = kv*16 + (lane&7) + ((lane>>3)&1)*8;
                int ch  = 2*ntp + (lane>>4);
                ldm4t(vf, sV + sw256(row*256 + ch*16));
                mma_f16(oacc[2*ntp],   pf, vf[0], vf[1]);
                mma_f16(oacc[2*ntp+1], pf, vf[2], vf[3]);
            }
        }
    }

    float inv0 = 1.f/l0, inv1 = 1.f/l1;
    int r = wid*16 + (lane>>2);
    __half* Og0 = O + ((size_t)b*SEQ + q0 + r)*DM + h*HDIM;
    __half* Og1 = O + ((size_t)b*SEQ + q0 + r + 8)*DM + h*HDIM;
    #pragma unroll
    for (int nt=0; nt<16; nt++){
        int c = nt*8 + (lane&3)*2;
        *(uint32_t*)(Og0 + c) = pkh2(oacc[nt][0]*inv0, oacc[nt][1]*inv0);
        *(uint32_t*)(Og1 + c) = pkh2(oacc[nt][2]*inv1, oacc[nt][3]*inv1);
    }
}

// ---------------- launch ---------------------------------------------------
extern "C" void kernel_launch(void* const* d_in, const int* in_sizes, int n_in,
                              void* d_out, int out_size){
    const float* x   = (const float*)d_in[0];
    const float* fc  = (const float*)d_in[1];
    const float* fs  = (const float*)d_in[2];
    const float* wq  = (const float*)d_in[3];
    const float* wk  = (const float*)d_in[4];
    const float* wv  = (const float*)d_in[5];
    const float* wo  = (const float*)d_in[6];
    const float* w1  = (const float*)d_in[7];
    const float* w2  = (const float*)d_in[8];
    const float* w3  = (const float*)d_in[9];
    const float* anw = (const float*)d_in[10];
    const float* fnw = (const float*)d_in[11];
    float* out = (float*)d_out;

    __half *xn,*qkv,*attn,*hn,*ffa,*wqkvH,*woH,*w13H,*w2H;
    float  *h;
    cudaGetSymbolAddress((void**)&xn,    g_xn);
    cudaGetSymbolAddress((void**)&qkv,   g_qkv);
    cudaGetSymbolAddress((void**)&attn,  g_attn);
    cudaGetSymbolAddress((void**)&h,     g_h);
    cudaGetSymbolAddress((void**)&hn,    g_hn);
    cudaGetSymbolAddress((void**)&ffa,   g_ffa);
    cudaGetSymbolAddress((void**)&wqkvH, g_wqkv);
    cudaGetSymbolAddress((void**)&woH,   g_wo);
    cudaGetSymbolAddress((void**)&w13H,  g_w13);
    cudaGetSymbolAddress((void**)&w2H,   g_w2);

    cudaFuncSetAttribute((const void*)gemm_kernel<false,true,true,false>,  cudaFuncAttributeMaxDynamicSharedMemorySize, GEMM_SMEM);
    cudaFuncSetAttribute((const void*)gemm_kernel<true,false,false,false>, cudaFuncAttributeMaxDynamicSharedMemorySize, GEMM_SMEM);
    cudaFuncSetAttribute((const void*)gemm_kernel<false,true,false,true>,  cudaFuncAttributeMaxDynamicSharedMemorySize, GEMM_SMEM);
    cudaFuncSetAttribute((const void*)flash_kernel, cudaFuncAttributeMaxDynamicSharedMemorySize, FLASH_SMEM);

    // weight fp16 conversion + fusing prepass (3 grouped launches)
    {
        int thr = 256;
        int t8  = DM*DM/8;      // 524288
        int t8h = DM*HID/8;     // 1441792
        cvt_qkv<<<dim3((t8 +thr-1)/thr, 3), thr>>>(wq, wk, wv, wqkvH);
        cvt_w13<<<dim3((t8h+thr-1)/thr, 2), thr>>>(w1, w3, w13H);
        cvt_ow2<<<dim3((t8h+thr-1)/thr, 2), thr>>>(wo, w2, woH, w2H);
    }

    // attn rmsnorm -> fp16
    rmsnorm_kernel<<<NTOK, 256>>>(x, anw, xn);
    // fused q,k,v projection with fused RoPE -> fp16
    dim3 gqkv(QKVN/128, NTOK/128);    // (48,32)
    gemm_kernel<false,true,true,false><<<gqkv, 256, GEMM_SMEM>>>(xn, wqkvH, nullptr, qkv, NTOK, QKVN, DM, fc, fs);
    // attention -> fp16 (BQ=128)
    dim3 gf(SEQ/128, NH, BSZ);        // (16,16,2)
    flash_kernel<<<gf, 256, FLASH_SMEM>>>(qkv, attn);
    // output proj + residual -> fp32 h
    dim3 g2048(DM/128, NTOK/128);     // (16,32)
    gemm_kernel<true,false,false,false><<<g2048, 256, GEMM_SMEM>>>(attn, woH, x, h, NTOK, DM, DM, nullptr, nullptr);
    // ffn rmsnorm -> fp16
    rmsnorm_kernel<<<NTOK, 256>>>(h, fnw, hn);
    // fused w1/w3 with fused silu*gate -> fp16 ffa
    dim3 gff(FFN2/128, NTOK/128);     // (88,32)
    gemm_kernel<false,true,false,true><<<gff, 256, GEMM_SMEM>>>(hn, w13H, nullptr, ffa, NTOK, FFN2, DM, nullptr, nullptr);
    // w2 + residual -> fp32 out
    gemm_kernel<true,false,false,false><<<g2048, 256, GEMM_SMEM>>>(ffa, w2H, h, out, NTOK, DM, HID, nullptr, nullptr);
}

// round 9
// speedup vs baseline: 3.2814x; 1.0994x over previous
#include <cuda_runtime.h>
#include <cuda_fp16.h>
#include <math.h>
#include <stdint.h>

#define BSZ   2
#define SEQ   2048
#define DM    2048
#define NH    16
#define HDIM  128
#define HID   5632
#define NTOK  (BSZ*SEQ)     // 4096
#define HTOK  (NTOK/2)      // 2048 rows per batch half
#define QKVN  (3*DM)        // 6144
#define FFN2  (2*HID)       // 11264

// ---------------- scratch (no allocation allowed -> __device__ globals) ----
__device__ __half g_xn  [NTOK*(size_t)DM];
__device__ __half g_qkv [NTOK*(size_t)QKVN];
__device__ __half g_attn[NTOK*(size_t)DM];
__device__ float  g_h   [NTOK*(size_t)DM];
__device__ __half g_hn  [NTOK*(size_t)DM];
__device__ __half g_ffa [NTOK*(size_t)HID];
// fp16 weights, [K,N] layout (wq|wk|wv fused; w1/w3 interleaved by 8 cols)
__device__ __half g_wqkv[DM*(size_t)QKVN];
__device__ __half g_wo  [DM*(size_t)DM];
__device__ __half g_w13 [DM*(size_t)FFN2];
__device__ __half g_w2  [HID*(size_t)DM];

// ---------------- streams/events created at static init (pre-checkpoint) ---
static cudaStream_t g_s1, g_s2;
static cudaEvent_t  g_e0, g_eQ, g_eW, g_e1, g_e2;
static struct StreamInit {
    StreamInit(){
        cudaStreamCreateWithFlags(&g_s1, cudaStreamNonBlocking);
        cudaStreamCreateWithFlags(&g_s2, cudaStreamNonBlocking);
        cudaEventCreateWithFlags(&g_e0, cudaEventDisableTiming);
        cudaEventCreateWithFlags(&g_eQ, cudaEventDisableTiming);
        cudaEventCreateWithFlags(&g_eW, cudaEventDisableTiming);
        cudaEventCreateWithFlags(&g_e1, cudaEventDisableTiming);
        cudaEventCreateWithFlags(&g_e2, cudaEventDisableTiming);
    }
} g_stream_init;

// ---------------- helpers --------------------------------------------------
__device__ __forceinline__ uint32_t smem_u32(const void* p){
    uint32_t a;
    asm("{ .reg .u64 t; cvta.to.shared.u64 t, %1; cvt.u32.u64 %0, t; }" : "=r"(a) : "l"(p));
    return a;
}
__device__ __forceinline__ void cp16(void* dst, const void* src){
    unsigned d = (unsigned)__cvta_generic_to_shared(dst);
    asm volatile("cp.async.cg.shared.global [%0], [%1], 16;" :: "r"(d), "l"(src));
}
__device__ __forceinline__ void cp_commit(){ asm volatile("cp.async.commit_group;"); }
__device__ __forceinline__ void cp_wait0(){ asm volatile("cp.async.wait_group 0;"); }
__device__ __forceinline__ void cp_wait1(){ asm volatile("cp.async.wait_group 1;"); }

__device__ __forceinline__ void ldm4(uint32_t r[4], uint32_t addr){
    asm volatile("ldmatrix.sync.aligned.m8n8.x4.shared.b16 {%0,%1,%2,%3}, [%4];"
        : "=r"(r[0]), "=r"(r[1]), "=r"(r[2]), "=r"(r[3]) : "r"(addr));
}
__device__ __forceinline__ void ldm4t(uint32_t r[4], uint32_t addr){
    asm volatile("ldmatrix.sync.aligned.m8n8.x4.trans.shared.b16 {%0,%1,%2,%3}, [%4];"
        : "=r"(r[0]), "=r"(r[1]), "=r"(r[2]), "=r"(r[3]) : "r"(addr));
}
__device__ __forceinline__ void mma_f16(float c[4], const uint32_t a[4], uint32_t b0, uint32_t b1){
    asm volatile("mma.sync.aligned.m16n8k16.row.col.f32.f16.f16.f32 "
        "{%0,%1,%2,%3},{%4,%5,%6,%7},{%8,%9},{%0,%1,%2,%3};"
        : "+f"(c[0]), "+f"(c[1]), "+f"(c[2]), "+f"(c[3])
        : "r"(a[0]), "r"(a[1]), "r"(a[2]), "r"(a[3]), "r"(b0), "r"(b1));
}
__device__ __forceinline__ uint32_t pkh2(float a, float b){
    __half2 h = __floats2half2_rn(a, b);
    return reinterpret_cast<uint32_t&>(h);
}
__device__ __forceinline__ float siluf(float x){ return x / (1.f + __expf(-x)); }
// swizzles (relative byte offsets; conflict-free ldmatrix phases)
__device__ __forceinline__ uint32_t swA(uint32_t o){ return o ^ (((o >> 7) & 7) << 4); }   // 128B rows
__device__ __forceinline__ uint32_t sw256(uint32_t o){ return o ^ (((o >> 8) & 7) << 4); } // 256B rows

// ------- weight convert prepass (grouped): fp32[K,Ns] -> fp16 --------------
__device__ __forceinline__ void cvt8_body(const float* __restrict__ src, __half* __restrict__ dst,
                                          int Ns, int Nd, int mul, int col0, int total8){
    int idx = blockIdx.x*blockDim.x + threadIdx.x;
    if (idx >= total8) return;
    int ns8 = Ns >> 3;
    int k = idx / ns8, j = (idx - k*ns8) << 3;
    const float4* s = (const float4*)(src + (size_t)k*Ns + j);
    float4 v0 = s[0], v1 = s[1];
    uint4 o;
    o.x = pkh2(v0.x, v0.y); o.y = pkh2(v0.z, v0.w);
    o.z = pkh2(v1.x, v1.y); o.w = pkh2(v1.z, v1.w);
    *(uint4*)(dst + (size_t)k*Nd + j*mul + col0) = o;
}

__global__ void cvt_qkv(const float* wq, const float* wk, const float* wv, __half* dst){
    const float* srcs[3] = {wq, wk, wv};
    int y = blockIdx.y;
    cvt8_body(srcs[y], dst, DM, QKVN, 1, y*DM, DM*DM/8);
}
__global__ void cvt_w13(const float* w1, const float* w3, __half* dst){
    const float* srcs[2] = {w1, w3};
    int y = blockIdx.y;
    cvt8_body(srcs[y], dst, HID, FFN2, 2, y*8, DM*HID/8);
}
__global__ void cvt_ow2(const float* wo, const float* w2, __half* dwo, __half* dw2){
    if (blockIdx.y == 0) cvt8_body(wo, dwo, DM, DM, 1, 0, DM*DM/8);
    else                 cvt8_body(w2, dw2, DM, DM, 1, 0, HID*DM/8);
}

// ---------------- rmsnorm (fp32 in -> fp16 out, vectorized) ----------------
__global__ void rmsnorm_kernel(const float* __restrict__ x, const float* __restrict__ w,
                               __half* __restrict__ out){
    int row = blockIdx.x;
    const float4* xr = (const float4*)(x + (size_t)row*DM);
    float4 v0 = xr[threadIdx.x], v1 = xr[threadIdx.x + 256];
    float ss = v0.x*v0.x + v0.y*v0.y + v0.z*v0.z + v0.w*v0.w
             + v1.x*v1.x + v1.y*v1.y + v1.z*v1.z + v1.w*v1.w;
    __shared__ float red[8];
    #pragma unroll
    for (int o = 16; o; o >>= 1) ss += __shfl_xor_sync(~0u, ss, o);
    if ((threadIdx.x & 31) == 0) red[threadIdx.x >> 5] = ss;
    __syncthreads();
    if (threadIdx.x == 0){
        float t = 0.f;
        #pragma unroll
        for (int i = 0; i < 8; i++) t += red[i];
        red[0] = t;
    }
    __syncthreads();
    float inv = rsqrtf(red[0] / (float)DM + 1e-5f);
    const float4* w4 = (const float4*)w;
    uint2* o2 = (uint2*)(out + (size_t)row*DM);
    float4 a = w4[threadIdx.x], b = w4[threadIdx.x + 256];
    o2[threadIdx.x]       = make_uint2(pkh2(v0.x*inv*a.x, v0.y*inv*a.y), pkh2(v0.z*inv*a.z, v0.w*inv*a.w));
    o2[threadIdx.x + 256] = make_uint2(pkh2(v1.x*inv*b.x, v1.y*inv*b.y), pkh2(v1.z*inv*b.z, v1.w*inv*b.w));
}

// ================= fp16 GEMM: C[M,N] = A[M,K] @ B[K,N] =====================
// 128x128 block, 8 warps of 32x64, BK=64, 3-stage cp.async, 2 CTAs/SM.
// A/C/Add pointers are pre-offset for batch halves (row offset ≡ 0 mod SEQ).
#define GSTG_BYTES (32*1024)
#define GEMM_SMEM  (3*GSTG_BYTES)     // 98304 -> 2 CTAs/SM
#define QSCALE 0.08838834764831845f   // 1/sqrt(128), folded into Q

template<bool ADD, bool HOUT, bool ROPE, bool SILU>
__global__ void __launch_bounds__(256, 2)
gemm_kernel(const __half* __restrict__ A, const __half* __restrict__ B,
            const float* __restrict__ Add, void* __restrict__ Cv,
            int M, int N, int K,
            const float* __restrict__ fc, const float* __restrict__ fs)
{
    extern __shared__ char smem[];
    const uint32_t sb = smem_u32(smem);
    const int tid = threadIdx.x, lane = tid & 31, wid = tid >> 5;
    const int wm = (wid >> 1) * 32;
    const int wn = (wid & 1) * 64;
    const int bm = blockIdx.y * 128, bn = blockIdx.x * 128;

    float acc[2][8][4];
    #pragma unroll
    for (int i=0;i<2;i++)
        #pragma unroll
        for (int j=0;j<8;j++)
            #pragma unroll
            for (int r=0;r<4;r++) acc[i][j][r] = 0.f;

    const int nk = K / 64;

    auto issue = [&](int kt, int st){
        char* Ad = smem + st*GSTG_BYTES;
        const __half* Ag = A + (size_t)bm*K + kt*64;
        #pragma unroll
        for (int i = 0; i < 4; i++){
            int idx = tid + i*256;
            int m = idx >> 3, c = idx & 7;
            cp16(Ad + swA(m*128 + c*16), Ag + (size_t)m*K + c*8);
        }
        char* Bd = Ad + 16*1024;
        const __half* Bg = B + (size_t)(kt*64)*N + bn;
        #pragma unroll
        for (int i = 0; i < 4; i++){
            int idx = tid + i*256;
            int k = idx >> 4, c = idx & 15;
            cp16(Bd + sw256(k*256 + c*16), Bg + (size_t)k*N + c*8);
        }
        cp_commit();
    };

    issue(0, 0); issue(1, 1);
    int cur = 0, nxt = 2;
    for (int kt = 0; kt < nk; kt++){
        cp_wait1();
        __syncthreads();
        if (kt+2 < nk) issue(kt+2, nxt);
        const uint32_t sA = sb + cur*GSTG_BYTES;
        const uint32_t sB = sA + 16*1024;
        if (++cur == 3) cur = 0;
        if (++nxt == 3) nxt = 0;
        #pragma unroll
        for (int ks = 0; ks < 4; ks++){
            uint32_t af[2][4];
            #pragma unroll
            for (int mt = 0; mt < 2; mt++){
                int row = wm + mt*16 + (lane&7) + ((lane>>3)&1)*8;
                int ch  = 2*ks + (lane>>4);
                ldm4(af[mt], sA + swA(row*128 + ch*16));
            }
            uint32_t bf[4][4];
            #pragma unroll
            for (int ntp = 0; ntp < 4; ntp++){
                int krow = ks*16 + (lane&7) + ((lane>>3)&1)*8;
                int ch   = ((wn + ntp*16) >> 3) + (lane>>4);
                ldm4t(bf[ntp], sB + sw256(krow*256 + ch*16));
            }
            #pragma unroll
            for (int mt = 0; mt < 2; mt++)
                #pragma unroll
                for (int ntp = 0; ntp < 4; ntp++){
                    mma_f16(acc[mt][2*ntp],   af[mt], bf[ntp][0], bf[ntp][1]);
                    mma_f16(acc[mt][2*ntp+1], af[mt], bf[ntp][2], bf[ntp][3]);
                }
        }
    }

    // ---------------- epilogue ----------------
    if (SILU){
        __half* C = (__half*)Cv;
        const int NO = N >> 1;    // HID
        #pragma unroll
        for (int mt = 0; mt < 2; mt++){
            int r0 = bm + wm + mt*16 + (lane>>2);
            #pragma unroll
            for (int ntp = 0; ntp < 4; ntp++){
                int j = ((bn + wn) >> 1) + ntp*8 + (lane&3)*2;
                const float* a1 = acc[mt][2*ntp];
                const float* a3 = acc[mt][2*ntp+1];
                *(uint32_t*)(C + (size_t)r0*NO + j) =
                    pkh2(siluf(a1[0])*a3[0], siluf(a1[1])*a3[1]);
                *(uint32_t*)(C + (size_t)(r0+8)*NO + j) =
                    pkh2(siluf(a1[2])*a3[2], siluf(a1[3])*a3[3]);
            }
        }
        return;
    }
    #pragma unroll
    for (int mt = 0; mt < 2; mt++){
        #pragma unroll
        for (int nt = 0; nt < 8; nt++){
            int r = bm + wm + mt*16 + (lane>>2);
            int c = bn + wn + nt*8 + (lane&3)*2;
            float2 v0 = make_float2(acc[mt][nt][0], acc[mt][nt][1]);
            float2 v1 = make_float2(acc[mt][nt][2], acc[mt][nt][3]);
            if (ADD){
                const float* A0 = Add + (size_t)r*N + c;
                const float* A1 = Add + (size_t)(r+8)*N + c;
                v0.x += A0[0]; v0.y += A0[1];
                v1.x += A1[0]; v1.y += A1[1];
            }
            if (ROPE && c < 2*DM){
                int i = (c & (HDIM-1)) >> 1;
                int s0 = r & (SEQ-1), s1 = (r+8) & (SEQ-1);
                float c0 = fc[s0*64 + i], sn0 = fs[s0*64 + i];
                float c1 = fc[s1*64 + i], sn1 = fs[s1*64 + i];
                float a = v0.x, b = v0.y;
                v0.x = a*c0 - b*sn0; v0.y = a*sn0 + b*c0;
                a = v1.x; b = v1.y;
                v1.x = a*c1 - b*sn1; v1.y = a*sn1 + b*c1;
                if (c < DM){   // q slice: fold softmax scale
                    v0.x *= QSCALE; v0.y *= QSCALE;
                    v1.x *= QSCALE; v1.y *= QSCALE;
                }
            }
            if (HOUT){
                __half* C = (__half*)Cv;
                *(uint32_t*)(C + (size_t)r*N + c)     = pkh2(v0.x, v0.y);
                *(uint32_t*)(C + (size_t)(r+8)*N + c) = pkh2(v1.x, v1.y);
            } else {
                float* C = (float*)Cv;
                *(float2*)(C + (size_t)r*N + c)     = v0;
                *(float2*)(C + (size_t)(r+8)*N + c) = v1;
            }
        }
    }
}

// ---------------- flash attention, BQ=128, 256 threads, P in registers -----
// QKV/O pointers pre-offset to the batch; grid (S/128, NH, 1).
// smem: Q 32KB | K 2x16KB | V 2x16KB = 96KB. 8 warps, each owns 16 q-rows.
#define FQ_OFF  0
#define FK_OFF  (32*1024)
#define FV_OFF  (64*1024)
#define FLASH_SMEM (96*1024)

__global__ void __launch_bounds__(256)
flash_kernel(const __half* __restrict__ QKV, __half* __restrict__ O)
{
    extern __shared__ char smem[];
    const uint32_t sb = smem_u32(smem);
    const int tid = threadIdx.x, lane = tid & 31, wid = tid >> 5;
    const int qt = blockIdx.x, h = blockIdx.y;
    const int q0 = qt*128;

    {   // Q: 128 rows x 256B (pre-scaled by 1/sqrt(HD) in QKV epilogue)
        const __half* Qg = QKV + (size_t)q0*QKVN + h*HDIM;
        #pragma unroll
        for (int i = 0; i < 8; i++){
            int idx = tid + i*256;            // 0..2047
            int r = idx >> 4, c = idx & 15;
            cp16(smem + FQ_OFF + sw256(r*256 + c*16), Qg + (size_t)r*QKVN + c*8);
        }
    }
    auto issueKV = [&](int kt, int st){
        const __half* Kg = QKV + (size_t)(kt*64)*QKVN + DM   + h*HDIM;
        const __half* Vg = QKV + (size_t)(kt*64)*QKVN + 2*DM + h*HDIM;
        char* Kd = smem + FK_OFF + st*16*1024;
        char* Vd = smem + FV_OFF + st*16*1024;
        #pragma unroll
        for (int i = 0; i < 4; i++){
            int idx = tid + i*256;            // 0..1023
            int r = idx >> 4, c = idx & 15;
            uint32_t so = sw256(r*256 + c*16);
            cp16(Kd + so, Kg + (size_t)r*QKVN + c*8);
            cp16(Vd + so, Vg + (size_t)r*QKVN + c*8);
        }
        cp_commit();
    };
    issueKV(0, 0);
    cp_wait0();
    __syncthreads();

    uint32_t qf[8][4];
    #pragma unroll
    for (int ks = 0; ks < 8; ks++){
        int row = wid*16 + (lane&7) + ((lane>>3)&1)*8;
        int ch  = 2*ks + (lane>>4);
        ldm4(qf[ks], sb + FQ_OFF + sw256(row*256 + ch*16));
    }

    float m0 = -1e30f, m1 = -1e30f, l0 = 0.f, l1 = 0.f;
    float oacc[16][4];
    #pragma unroll
    for (int i=0;i<16;i++)
        #pragma unroll
        for (int j=0;j<4;j++) oacc[i][j] = 0.f;

    const int nkt = SEQ / 64;     // 32
    for (int kt = 0; kt < nkt; kt++){
        if (kt > 0){ cp_wait0(); __syncthreads(); }
        if (kt+1 < nkt) issueKV(kt+1, (kt+1)&1);
        const uint32_t sK = sb + FK_OFF + (kt&1)*16*1024;
        const uint32_t sV = sb + FV_OFF + (kt&1)*16*1024;

        float sacc[8][4];
        #pragma unroll
        for (int i=0;i<8;i++)
            #pragma unroll
            for (int j=0;j<4;j++) sacc[i][j] = 0.f;
        #pragma unroll
        for (int ks = 0; ks < 8; ks++){
            #pragma unroll
            for (int ntp = 0; ntp < 4; ntp++){
                uint32_t kf[4];
                int row = ntp*16 + ((lane>>4)&1)*8 + (lane&7);
                int ch  = 2*ks + ((lane>>3)&1);
                ldm4(kf, sK + sw256(row*256 + ch*16));
                mma_f16(sacc[2*ntp],   qf[ks], kf[0], kf[1]);
                mma_f16(sacc[2*ntp+1], qf[ks], kf[2], kf[3]);
            }
        }

        float mx0 = -1e30f, mx1 = -1e30f;
        #pragma unroll
        for (int nt=0; nt<8; nt++){
            mx0 = fmaxf(mx0, fmaxf(sacc[nt][0], sacc[nt][1]));
            mx1 = fmaxf(mx1, fmaxf(sacc[nt][2], sacc[nt][3]));
        }
        mx0 = fmaxf(mx0, __shfl_xor_sync(~0u, mx0, 1));
        mx0 = fmaxf(mx0, __shfl_xor_sync(~0u, mx0, 2));
        mx1 = fmaxf(mx1, __shfl_xor_sync(~0u, mx1, 1));
        mx1 = fmaxf(mx1, __shfl_xor_sync(~0u, mx1, 2));
        float mn0 = fmaxf(m0, mx0), mn1 = fmaxf(m1, mx1);
        float cr0 = __expf(m0 - mn0), cr1 = __expf(m1 - mn1);
        m0 = mn0; m1 = mn1;
        float rs0 = 0.f, rs1 = 0.f;
        #pragma unroll
        for (int nt=0; nt<8; nt++){
            sacc[nt][0] = __expf(sacc[nt][0] - mn0);
            sacc[nt][1] = __expf(sacc[nt][1] - mn0);
            sacc[nt][2] = __expf(sacc[nt][2] - mn1);
            sacc[nt][3] = __expf(sacc[nt][3] - mn1);
            rs0 += sacc[nt][0] + sacc[nt][1];
            rs1 += sacc[nt][2] + sacc[nt][3];
        }
        rs0 += __shfl_xor_sync(~0u, rs0, 1); rs0 += __shfl_xor_sync(~0u, rs0, 2);
        rs1 += __shfl_xor_sync(~0u, rs1, 1); rs1 += __shfl_xor_sync(~0u, rs1, 2);
        l0 = l0*cr0 + rs0; l1 = l1*cr1 + rs1;
        #pragma unroll
        for (int i=0;i<16;i++){
            oacc[i][0] *= cr0; oacc[i][1] *= cr0;
            oacc[i][2] *= cr1; oacc[i][3] *= cr1;
        }

        #pragma unroll
        for (int kv = 0; kv < 4; kv++){
            uint32_t pf[4];
            pf[0] = pkh2(sacc[2*kv][0],   sacc[2*kv][1]);
            pf[1] = pkh2(sacc[2*kv][2],   sacc[2*kv][3]);
            pf[2] = pkh2(sacc[2*kv+1][0], sacc[2*kv+1][1]);
            pf[3] = pkh2(sacc[2*kv+1][2], sacc[2*kv+1][3]);
            #pragma unroll
            for (int ntp = 0; ntp < 8; ntp++){
                uint32_t vf[4];
                int row = kv*16 + (lane&7) + ((lane>>3)&1)*8;
                int ch  = 2*ntp + (lane>>4);
                ldm4t(vf, sV + sw256(row*256 + ch*16));
                mma_f16(oacc[2*ntp],   pf, vf[0], vf[1]);
                mma_f16(oacc[2*ntp+1], pf, vf[2], vf[3]);
            }
        }
    }

    float inv0 = 1.f/l0, inv1 = 1.f/l1;
    int r = wid*16 + (lane>>2);
    __half* Og0 = O + ((size_t)(q0 + r))*DM + h*HDIM;
    __half* Og1 = O + ((size_t)(q0 + r + 8))*DM + h*HDIM;
    #pragma unroll
    for (int nt=0; nt<16; nt++){
        int c = nt*8 + (lane&3)*2;
        *(uint32_t*)(Og0 + c) = pkh2(oacc[nt][0]*inv0, oacc[nt][1]*inv0);
        *(uint32_t*)(Og1 + c) = pkh2(oacc[nt][2]*inv1, oacc[nt][3]*inv1);
    }
}

// ---------------- launch: two-stream batch-split pipeline -------------------
extern "C" void kernel_launch(void* const* d_in, const int* in_sizes, int n_in,
                              void* d_out, int out_size){
    const float* x   = (const float*)d_in[0];
    const float* fc  = (const float*)d_in[1];
    const float* fs  = (const float*)d_in[2];
    const float* wq  = (const float*)d_in[3];
    const float* wk  = (const float*)d_in[4];
    const float* wv  = (const float*)d_in[5];
    const float* wo  = (const float*)d_in[6];
    const float* w1  = (const float*)d_in[7];
    const float* w2  = (const float*)d_in[8];
    const float* w3  = (const float*)d_in[9];
    const float* anw = (const float*)d_in[10];
    const float* fnw = (const float*)d_in[11];
    float* out = (float*)d_out;

    __half *xn,*qkv,*attn,*hn,*ffa,*wqkvH,*woH,*w13H,*w2H;
    float  *h;
    cudaGetSymbolAddress((void**)&xn,    g_xn);
    cudaGetSymbolAddress((void**)&qkv,   g_qkv);
    cudaGetSymbolAddress((void**)&attn,  g_attn);
    cudaGetSymbolAddress((void**)&h,     g_h);
    cudaGetSymbolAddress((void**)&hn,    g_hn);
    cudaGetSymbolAddress((void**)&ffa,   g_ffa);
    cudaGetSymbolAddress((void**)&wqkvH, g_wqkv);
    cudaGetSymbolAddress((void**)&woH,   g_wo);
    cudaGetSymbolAddress((void**)&w13H,  g_w13);
    cudaGetSymbolAddress((void**)&w2H,   g_w2);

    cudaFuncSetAttribute((const void*)gemm_kernel<false,true,true,false>,  cudaFuncAttributeMaxDynamicSharedMemorySize, GEMM_SMEM);
    cudaFuncSetAttribute((const void*)gemm_kernel<true,false,false,false>, cudaFuncAttributeMaxDynamicSharedMemorySize, GEMM_SMEM);
    cudaFuncSetAttribute((const void*)gemm_kernel<false,true,false,true>,  cudaFuncAttributeMaxDynamicSharedMemorySize, GEMM_SMEM);
    cudaFuncSetAttribute((const void*)flash_kernel, cudaFuncAttributeMaxDynamicSharedMemorySize, FLASH_SMEM);

    const int thr = 256;
    const int t8  = DM*DM/8;      // 524288
    const int t8h = DM*HID/8;     // 1441792
    dim3 gq(QKVN/128, HTOK/128);  // (48,16)
    dim3 gd(DM/128,  HTOK/128);   // (16,16)
    dim3 gffh(FFN2/128, HTOK/128);// (88,16)
    dim3 gfl(SEQ/128, NH, 1);     // (16,16,1)

    // fork both pipelines off the capture stream
    cudaEventRecord(g_e0, 0);
    cudaStreamWaitEvent(g_s1, g_e0, 0);
    cudaStreamWaitEvent(g_s2, g_e0, 0);

    // prepass split across streams
    cvt_qkv<<<dim3((t8 +thr-1)/thr, 3), thr, 0, g_s1>>>(wq, wk, wv, wqkvH);
    cudaEventRecord(g_eQ, g_s1);
    cvt_w13<<<dim3((t8h+thr-1)/thr, 2), thr, 0, g_s2>>>(w1, w3, w13H);
    cvt_ow2<<<dim3((t8h+thr-1)/thr, 2), thr, 0, g_s2>>>(wo, w2, woH, w2H);
    cudaEventRecord(g_eW, g_s2);

    // ---- stream 1: batch 0 (rows 0..2047) ----
    {
        const size_t r0 = 0;
        rmsnorm_kernel<<<HTOK, 256, 0, g_s1>>>(x + r0*DM, anw, xn + r0*DM);
        gemm_kernel<false,true,true,false><<<gq, 256, GEMM_SMEM, g_s1>>>(
            xn + r0*DM, wqkvH, nullptr, qkv + r0*QKVN, HTOK, QKVN, DM, fc, fs);
        flash_kernel<<<gfl, 256, FLASH_SMEM, g_s1>>>(qkv + r0*QKVN, attn + r0*DM);
        cudaStreamWaitEvent(g_s1, g_eW, 0);
        gemm_kernel<true,false,false,false><<<gd, 256, GEMM_SMEM, g_s1>>>(
            attn + r0*DM, woH, x + r0*DM, h + r0*DM, HTOK, DM, DM, nullptr, nullptr);
        rmsnorm_kernel<<<HTOK, 256, 0, g_s1>>>(h + r0*DM, fnw, hn + r0*DM);
        gemm_kernel<false,true,false,true><<<gffh, 256, GEMM_SMEM, g_s1>>>(
            hn + r0*DM, w13H, nullptr, ffa + r0*HID, HTOK, FFN2, DM, nullptr, nullptr);
        gemm_kernel<true,false,false,false><<<gd, 256, GEMM_SMEM, g_s1>>>(
            ffa + r0*HID, w2H, h + r0*DM, out + r0*DM, HTOK, DM, HID, nullptr, nullptr);
        cudaEventRecord(g_e1, g_s1);
    }

    // ---- stream 2: batch 1 (rows 2048..4095) ----
    {
        const size_t r0 = HTOK;
        rmsnorm_kernel<<<HTOK, 256, 0, g_s2>>>(x + r0*DM, anw, xn + r0*DM);
        cudaStreamWaitEvent(g_s2, g_eQ, 0);
        gemm_kernel<false,true,true,false><<<gq, 256, GEMM_SMEM, g_s2>>>(
            xn + r0*DM, wqkvH, nullptr, qkv + r0*QKVN, HTOK, QKVN, DM, fc, fs);
        flash_kernel<<<gfl, 256, FLASH_SMEM, g_s2>>>(qkv + r0*QKVN, attn + r0*DM);
        gemm_kernel<true,false,false,false><<<gd, 256, GEMM_SMEM, g_s2>>>(
            attn + r0*DM, woH, x + r0*DM, h + r0*DM, HTOK, DM, DM, nullptr, nullptr);
        rmsnorm_kernel<<<HTOK, 256, 0, g_s2>>>(h + r0*DM, fnw, hn + r0*DM);
        gemm_kernel<false,true,false,true><<<gffh, 256, GEMM_SMEM, g_s2>>>(
            hn + r0*DM, w13H, nullptr, ffa + r0*HID, HTOK, FFN2, DM, nullptr, nullptr);
        gemm_kernel<true,false,false,false><<<gd, 256, GEMM_SMEM, g_s2>>>(
            ffa + r0*HID, w2H, h + r0*DM, out + r0*DM, HTOK, DM, HID, nullptr, nullptr);
        cudaEventRecord(g_e2, g_s2);
    }

    // join back to the capture stream
    cudaStreamWaitEvent(0, g_e1, 0);
    cudaStreamWaitEvent(0, g_e2, 0);
}

// round 10
// speedup vs baseline: 3.3660x; 1.0258x over previous
#include <cuda_runtime.h>
#include <cuda_fp16.h>
#include <math.h>
#include <stdint.h>

#define BSZ   2
#define SEQ   2048
#define DM    2048
#define NH    16
#define HDIM  128
#define HID   5632
#define NTOK  (BSZ*SEQ)     // 4096
#define HTOK  (NTOK/2)      // 2048 rows per batch half
#define QKVN  (3*DM)        // 6144
#define FFN2  (2*HID)       // 11264

// ---------------- scratch (no allocation allowed -> __device__ globals) ----
__device__ __half g_xn  [NTOK*(size_t)DM];
__device__ __half g_qkv [NTOK*(size_t)QKVN];
__device__ __half g_attn[NTOK*(size_t)DM];
__device__ float  g_h   [NTOK*(size_t)DM];
__device__ __half g_hn  [NTOK*(size_t)DM];
__device__ __half g_ffa [NTOK*(size_t)HID];
// fp16 weights, [K,N] layout (wq|wk|wv fused; w1/w3 interleaved by 8 cols)
__device__ __half g_wqkv[DM*(size_t)QKVN];
__device__ __half g_wo  [DM*(size_t)DM];
__device__ __half g_w13 [DM*(size_t)FFN2];
__device__ __half g_w2  [HID*(size_t)DM];

// ---------------- streams/events created at static init (pre-checkpoint) ---
static cudaStream_t g_s1, g_s2;
static cudaEvent_t  g_e0, g_eQ, g_eW, g_e1, g_e2;
static struct StreamInit {
    StreamInit(){
        cudaStreamCreateWithFlags(&g_s1, cudaStreamNonBlocking);
        cudaStreamCreateWithFlags(&g_s2, cudaStreamNonBlocking);
        cudaEventCreateWithFlags(&g_e0, cudaEventDisableTiming);
        cudaEventCreateWithFlags(&g_eQ, cudaEventDisableTiming);
        cudaEventCreateWithFlags(&g_eW, cudaEventDisableTiming);
        cudaEventCreateWithFlags(&g_e1, cudaEventDisableTiming);
        cudaEventCreateWithFlags(&g_e2, cudaEventDisableTiming);
    }
} g_stream_init;

// ---------------- helpers --------------------------------------------------
__device__ __forceinline__ uint32_t smem_u32(const void* p){
    uint32_t a;
    asm("{ .reg .u64 t; cvta.to.shared.u64 t, %1; cvt.u32.u64 %0, t; }" : "=r"(a) : "l"(p));
    return a;
}
__device__ __forceinline__ void cp16(void* dst, const void* src){
    unsigned d = (unsigned)__cvta_generic_to_shared(dst);
    asm volatile("cp.async.cg.shared.global [%0], [%1], 16;" :: "r"(d), "l"(src));
}
__device__ __forceinline__ void cp_commit(){ asm volatile("cp.async.commit_group;"); }
__device__ __forceinline__ void cp_wait0(){ asm volatile("cp.async.wait_group 0;"); }
__device__ __forceinline__ void cp_wait1(){ asm volatile("cp.async.wait_group 1;"); }

__device__ __forceinline__ void ldm4(uint32_t r[4], uint32_t addr){
    asm volatile("ldmatrix.sync.aligned.m8n8.x4.shared.b16 {%0,%1,%2,%3}, [%4];"
        : "=r"(r[0]), "=r"(r[1]), "=r"(r[2]), "=r"(r[3]) : "r"(addr));
}
__device__ __forceinline__ void ldm4t(uint32_t r[4], uint32_t addr){
    asm volatile("ldmatrix.sync.aligned.m8n8.x4.trans.shared.b16 {%0,%1,%2,%3}, [%4];"
        : "=r"(r[0]), "=r"(r[1]), "=r"(r[2]), "=r"(r[3]) : "r"(addr));
}
__device__ __forceinline__ void mma_f16(float c[4], const uint32_t a[4], uint32_t b0, uint32_t b1){
    asm volatile("mma.sync.aligned.m16n8k16.row.col.f32.f16.f16.f32 "
        "{%0,%1,%2,%3},{%4,%5,%6,%7},{%8,%9},{%0,%1,%2,%3};"
        : "+f"(c[0]), "+f"(c[1]), "+f"(c[2]), "+f"(c[3])
        : "r"(a[0]), "r"(a[1]), "r"(a[2]), "r"(a[3]), "r"(b0), "r"(b1));
}
__device__ __forceinline__ uint32_t pkh2(float a, float b){
    __half2 h = __floats2half2_rn(a, b);
    return reinterpret_cast<uint32_t&>(h);
}
__device__ __forceinline__ float siluf(float x){ return x / (1.f + __expf(-x)); }
// swizzles (relative byte offsets; conflict-free ldmatrix phases)
__device__ __forceinline__ uint32_t swA(uint32_t o){ return o ^ (((o >> 7) & 7) << 4); }   // 128B rows
__device__ __forceinline__ uint32_t sw256(uint32_t o){ return o ^ (((o >> 8) & 7) << 4); } // 256B rows

// ------- weight convert prepass (grouped): fp32[K,Ns] -> fp16 --------------
__device__ __forceinline__ void cvt8_body(const float* __restrict__ src, __half* __restrict__ dst,
                                          int Ns, int Nd, int mul, int col0, int total8){
    int idx = blockIdx.x*blockDim.x + threadIdx.x;
    if (idx >= total8) return;
    int ns8 = Ns >> 3;
    int k = idx / ns8, j = (idx - k*ns8) << 3;
    const float4* s = (const float4*)(src + (size_t)k*Ns + j);
    float4 v0 = s[0], v1 = s[1];
    uint4 o;
    o.x = pkh2(v0.x, v0.y); o.y = pkh2(v0.z, v0.w);
    o.z = pkh2(v1.x, v1.y); o.w = pkh2(v1.z, v1.w);
    *(uint4*)(dst + (size_t)k*Nd + j*mul + col0) = o;
}

__global__ void cvt_qkv(const float* wq, const float* wk, const float* wv, __half* dst){
    const float* srcs[3] = {wq, wk, wv};
    int y = blockIdx.y;
    cvt8_body(srcs[y], dst, DM, QKVN, 1, y*DM, DM*DM/8);
}
__global__ void cvt_w13(const float* w1, const float* w3, __half* dst){
    const float* srcs[2] = {w1, w3};
    int y = blockIdx.y;
    cvt8_body(srcs[y], dst, HID, FFN2, 2, y*8, DM*HID/8);
}
__global__ void cvt_ow2(const float* wo, const float* w2, __half* dwo, __half* dw2){
    if (blockIdx.y == 0) cvt8_body(wo, dwo, DM, DM, 1, 0, DM*DM/8);
    else                 cvt8_body(w2, dw2, DM, DM, 1, 0, HID*DM/8);
}

// ---------------- rmsnorm (fp32 in -> fp16 out, vectorized) ----------------
__global__ void rmsnorm_kernel(const float* __restrict__ x, const float* __restrict__ w,
                               __half* __restrict__ out){
    int row = blockIdx.x;
    const float4* xr = (const float4*)(x + (size_t)row*DM);
    float4 v0 = xr[threadIdx.x], v1 = xr[threadIdx.x + 256];
    float ss = v0.x*v0.x + v0.y*v0.y + v0.z*v0.z + v0.w*v0.w
             + v1.x*v1.x + v1.y*v1.y + v1.z*v1.z + v1.w*v1.w;
    __shared__ float red[8];
    #pragma unroll
    for (int o = 16; o; o >>= 1) ss += __shfl_xor_sync(~0u, ss, o);
    if ((threadIdx.x & 31) == 0) red[threadIdx.x >> 5] = ss;
    __syncthreads();
    if (threadIdx.x == 0){
        float t = 0.f;
        #pragma unroll
        for (int i = 0; i < 8; i++) t += red[i];
        red[0] = t;
    }
    __syncthreads();
    float inv = rsqrtf(red[0] / (float)DM + 1e-5f);
    const float4* w4 = (const float4*)w;
    uint2* o2 = (uint2*)(out + (size_t)row*DM);
    float4 a = w4[threadIdx.x], b = w4[threadIdx.x + 256];
    o2[threadIdx.x]       = make_uint2(pkh2(v0.x*inv*a.x, v0.y*inv*a.y), pkh2(v0.z*inv*a.z, v0.w*inv*a.w));
    o2[threadIdx.x + 256] = make_uint2(pkh2(v1.x*inv*b.x, v1.y*inv*b.y), pkh2(v1.z*inv*b.z, v1.w*inv*b.w));
}

// ================= fp16 GEMM: C[M,N] = A[M,K] @ B[K,N] =====================
// 128x128 block, 4 warps of 64x64, BK=64, 3-stage cp.async, 2 CTAs/SM.
// smem traffic per CTA-ktile: A 2x + B 2x dup + writes = 96KB (105 B/cyc/SM).
#define GSTG_BYTES (32*1024)
#define GEMM_SMEM  (3*GSTG_BYTES)     // 98304 -> 2 CTAs/SM
#define QSCALE 0.08838834764831845f   // 1/sqrt(128), folded into Q

template<bool ADD, bool HOUT, bool ROPE, bool SILU>
__global__ void __launch_bounds__(128, 2)
gemm_kernel(const __half* __restrict__ A, const __half* __restrict__ B,
            const float* __restrict__ Add, void* __restrict__ Cv,
            int M, int N, int K,
            const float* __restrict__ fc, const float* __restrict__ fs)
{
    extern __shared__ char smem[];
    const uint32_t sb = smem_u32(smem);
    const int tid = threadIdx.x, lane = tid & 31, wid = tid >> 5;   // 4 warps
    const int wm = (wid >> 1) * 64;       // 2 warp-rows of 64
    const int wn = (wid & 1) * 64;        // 2 warp-cols of 64
    const int bm = blockIdx.y * 128, bn = blockIdx.x * 128;

    float acc[4][8][4];
    #pragma unroll
    for (int i=0;i<4;i++)
        #pragma unroll
        for (int j=0;j<8;j++)
            #pragma unroll
            for (int r=0;r<4;r++) acc[i][j][r] = 0.f;

    const int nk = K / 64;

    auto issue = [&](int kt, int st){
        char* Ad = smem + st*GSTG_BYTES;
        const __half* Ag = A + (size_t)bm*K + kt*64;
        #pragma unroll
        for (int i = 0; i < 8; i++){
            int idx = tid + i*128;            // 0..1023
            int m = idx >> 3, c = idx & 7;
            cp16(Ad + swA(m*128 + c*16), Ag + (size_t)m*K + c*8);
        }
        char* Bd = Ad + 16*1024;
        const __half* Bg = B + (size_t)(kt*64)*N + bn;
        #pragma unroll
        for (int i = 0; i < 8; i++){
            int idx = tid + i*128;            // 0..1023
            int k = idx >> 4, c = idx & 15;
            cp16(Bd + sw256(k*256 + c*16), Bg + (size_t)k*N + c*8);
        }
        cp_commit();
    };

    issue(0, 0); issue(1, 1);
    int cur = 0, nxt = 2;
    for (int kt = 0; kt < nk; kt++){
        cp_wait1();
        __syncthreads();
        if (kt+2 < nk) issue(kt+2, nxt);
        const uint32_t sA = sb + cur*GSTG_BYTES;
        const uint32_t sB = sA + 16*1024;
        if (++cur == 3) cur = 0;
        if (++nxt == 3) nxt = 0;
        #pragma unroll
        for (int ks = 0; ks < 4; ks++){
            uint32_t af[4][4];
            #pragma unroll
            for (int mt = 0; mt < 4; mt++){
                int row = wm + mt*16 + (lane&7) + ((lane>>3)&1)*8;
                int ch  = 2*ks + (lane>>4);
                ldm4(af[mt], sA + swA(row*128 + ch*16));
            }
            uint32_t bf[4][4];
            #pragma unroll
            for (int ntp = 0; ntp < 4; ntp++){
                int krow = ks*16 + (lane&7) + ((lane>>3)&1)*8;
                int ch   = ((wn + ntp*16) >> 3) + (lane>>4);
                ldm4t(bf[ntp], sB + sw256(krow*256 + ch*16));
            }
            #pragma unroll
            for (int mt = 0; mt < 4; mt++)
                #pragma unroll
                for (int ntp = 0; ntp < 4; ntp++){
                    mma_f16(acc[mt][2*ntp],   af[mt], bf[ntp][0], bf[ntp][1]);
                    mma_f16(acc[mt][2*ntp+1], af[mt], bf[ntp][2], bf[ntp][3]);
                }
        }
    }

    // ---------------- epilogue ----------------
    if (SILU){
        __half* C = (__half*)Cv;
        const int NO = N >> 1;    // HID
        #pragma unroll
        for (int mt = 0; mt < 4; mt++){
            int r0 = bm + wm + mt*16 + (lane>>2);
            #pragma unroll
            for (int ntp = 0; ntp < 4; ntp++){
                int j = ((bn + wn) >> 1) + ntp*8 + (lane&3)*2;
                const float* a1 = acc[mt][2*ntp];
                const float* a3 = acc[mt][2*ntp+1];
                *(uint32_t*)(C + (size_t)r0*NO + j) =
                    pkh2(siluf(a1[0])*a3[0], siluf(a1[1])*a3[1]);
                *(uint32_t*)(C + (size_t)(r0+8)*NO + j) =
                    pkh2(siluf(a1[2])*a3[2], siluf(a1[3])*a3[3]);
            }
        }
        return;
    }
    #pragma unroll
    for (int mt = 0; mt < 4; mt++){
        #pragma unroll
        for (int nt = 0; nt < 8; nt++){
            int r = bm + wm + mt*16 + (lane>>2);
            int c = bn + wn + nt*8 + (lane&3)*2;
            float2 v0 = make_float2(acc[mt][nt][0], acc[mt][nt][1]);
            float2 v1 = make_float2(acc[mt][nt][2], acc[mt][nt][3]);
            if (ADD){
                const float* A0 = Add + (size_t)r*N + c;
                const float* A1 = Add + (size_t)(r+8)*N + c;
                v0.x += A0[0]; v0.y += A0[1];
                v1.x += A1[0]; v1.y += A1[1];
            }
            if (ROPE && c < 2*DM){
                int i = (c & (HDIM-1)) >> 1;
                int s0 = r & (SEQ-1), s1 = (r+8) & (SEQ-1);
                float c0 = fc[s0*64 + i], sn0 = fs[s0*64 + i];
                float c1 = fc[s1*64 + i], sn1 = fs[s1*64 + i];
                float a = v0.x, b = v0.y;
                v0.x = a*c0 - b*sn0; v0.y = a*sn0 + b*c0;
                a = v1.x; b = v1.y;
                v1.x = a*c1 - b*sn1; v1.y = a*sn1 + b*c1;
                if (c < DM){   // q slice: fold softmax scale
                    v0.x *= QSCALE; v0.y *= QSCALE;
                    v1.x *= QSCALE; v1.y *= QSCALE;
                }
            }
            if (HOUT){
                __half* C = (__half*)Cv;
                *(uint32_t*)(C + (size_t)r*N + c)     = pkh2(v0.x, v0.y);
                *(uint32_t*)(C + (size_t)(r+8)*N + c) = pkh2(v1.x, v1.y);
            } else {
                float* C = (float*)Cv;
                *(float2*)(C + (size_t)r*N + c)     = v0;
                *(float2*)(C + (size_t)(r+8)*N + c) = v1;
            }
        }
    }
}

// ---------------- flash attention, BQ=128, 256 threads, P in registers -----
// QKV/O pointers pre-offset to the batch; grid (S/128, NH, 1).
// smem: Q 32KB | K 2x16KB | V 2x16KB = 96KB. 8 warps, each owns 16 q-rows.
#define FQ_OFF  0
#define FK_OFF  (32*1024)
#define FV_OFF  (64*1024)
#define FLASH_SMEM (96*1024)

__global__ void __launch_bounds__(256)
flash_kernel(const __half* __restrict__ QKV, __half* __restrict__ O)
{
    extern __shared__ char smem[];
    const uint32_t sb = smem_u32(smem);
    const int tid = threadIdx.x, lane = tid & 31, wid = tid >> 5;
    const int qt = blockIdx.x, h = blockIdx.y;
    const int q0 = qt*128;

    {   // Q: 128 rows x 256B (pre-scaled by 1/sqrt(HD) in QKV epilogue)
        const __half* Qg = QKV + (size_t)q0*QKVN + h*HDIM;
        #pragma unroll
        for (int i = 0; i < 8; i++){
            int idx = tid + i*256;            // 0..2047
            int r = idx >> 4, c = idx & 15;
            cp16(smem + FQ_OFF + sw256(r*256 + c*16), Qg + (size_t)r*QKVN + c*8);
        }
    }
    auto issueKV = [&](int kt, int st){
        const __half* Kg = QKV + (size_t)(kt*64)*QKVN + DM   + h*HDIM;
        const __half* Vg = QKV + (size_t)(kt*64)*QKVN + 2*DM + h*HDIM;
        char* Kd = smem + FK_OFF + st*16*1024;
        char* Vd = smem + FV_OFF + st*16*1024;
        #pragma unroll
        for (int i = 0; i < 4; i++){
            int idx = tid + i*256;            // 0..1023
            int r = idx >> 4, c = idx & 15;
            uint32_t so = sw256(r*256 + c*16);
            cp16(Kd + so, Kg + (size_t)r*QKVN + c*8);
            cp16(Vd + so, Vg + (size_t)r*QKVN + c*8);
        }
        cp_commit();
    };
    issueKV(0, 0);
    cp_wait0();
    __syncthreads();

    uint32_t qf[8][4];
    #pragma unroll
    for (int ks = 0; ks < 8; ks++){
        int row = wid*16 + (lane&7) + ((lane>>3)&1)*8;
        int ch  = 2*ks + (lane>>4);
        ldm4(qf[ks], sb + FQ_OFF + sw256(row*256 + ch*16));
    }

    float m0 = -1e30f, m1 = -1e30f, l0 = 0.f, l1 = 0.f;
    float oacc[16][4];
    #pragma unroll
    for (int i=0;i<16;i++)
        #pragma unroll
        for (int j=0;j<4;j++) oacc[i][j] = 0.f;

    const int nkt = SEQ / 64;     // 32
    for (int kt = 0; kt < nkt; kt++){
        if (kt > 0){ cp_wait0(); __syncthreads(); }
        if (kt+1 < nkt) issueKV(kt+1, (kt+1)&1);
        const uint32_t sK = sb + FK_OFF + (kt&1)*16*1024;
        const uint32_t sV = sb + FV_OFF + (kt&1)*16*1024;

        float sacc[8][4];
        #pragma unroll
        for (int i=0;i<8;i++)
            #pragma unroll
            for (int j=0;j<4;j++) sacc[i][j] = 0.f;
        #pragma unroll
        for (int ks = 0; ks < 8; ks++){
            #pragma unroll
            for (int ntp = 0; ntp < 4; ntp++){
                uint32_t kf[4];
                int row = ntp*16 + ((lane>>4)&1)*8 + (lane&7);
                int ch  = 2*ks + ((lane>>3)&1);
                ldm4(kf, sK + sw256(row*256 + ch*16));
                mma_f16(sacc[2*ntp],   qf[ks], kf[0], kf[1]);
                mma_f16(sacc[2*ntp+1], qf[ks], kf[2], kf[3]);
            }
        }

        float mx0 = -1e30f, mx1 = -1e30f;
        #pragma unroll
        for (int nt=0; nt<8; nt++){
            mx0 = fmaxf(mx0, fmaxf(sacc[nt][0], sacc[nt][1]));
            mx1 = fmaxf(mx1, fmaxf(sacc[nt][2], sacc[nt][3]));
        }
        mx0 = fmaxf(mx0, __shfl_xor_sync(~0u, mx0, 1));
        mx0 = fmaxf(mx0, __shfl_xor_sync(~0u, mx0, 2));
        mx1 = fmaxf(mx1, __shfl_xor_sync(~0u, mx1, 1));
        mx1 = fmaxf(mx1, __shfl_xor_sync(~0u, mx1, 2));
        float mn0 = fmaxf(m0, mx0), mn1 = fmaxf(m1, mx1);
        float cr0 = __expf(m0 - mn0), cr1 = __expf(m1 - mn1);
        m0 = mn0; m1 = mn1;
        float rs0 = 0.f, rs1 = 0.f;
        #pragma unroll
        for (int nt=0; nt<8; nt++){
            sacc[nt][0] = __expf(sacc[nt][0] - mn0);
            sacc[nt][1] = __expf(sacc[nt][1] - mn0);
            sacc[nt][2] = __expf(sacc[nt][2] - mn1);
            sacc[nt][3] = __expf(sacc[nt][3] - mn1);
            rs0 += sacc[nt][0] + sacc[nt][1];
            rs1 += sacc[nt][2] + sacc[nt][3];
        }
        rs0 += __shfl_xor_sync(~0u, rs0, 1); rs0 += __shfl_xor_sync(~0u, rs0, 2);
        rs1 += __shfl_xor_sync(~0u, rs1, 1); rs1 += __shfl_xor_sync(~0u, rs1, 2);
        l0 = l0*cr0 + rs0; l1 = l1*cr1 + rs1;
        #pragma unroll
        for (int i=0;i<16;i++){
            oacc[i][0] *= cr0; oacc[i][1] *= cr0;
            oacc[i][2] *= cr1; oacc[i][3] *= cr1;
        }

        #pragma unroll
        for (int kv = 0; kv < 4; kv++){
            uint32_t pf[4];
            pf[0] = pkh2(sacc[2*kv][0],   sacc[2*kv][1]);
            pf[1] = pkh2(sacc[2*kv][2],   sacc[2*kv][3]);
            pf[2] = pkh2(sacc[2*kv+1][0], sacc[2*kv+1][1]);
            pf[3] = pkh2(sacc[2*kv+1][2], sacc[2*kv+1][3]);
            #pragma unroll
            for (int ntp = 0; ntp < 8; ntp++){
                uint32_t vf[4];
                int row = kv*16 + (lane&7) + ((lane>>3)&1)*8;
                int ch  = 2*ntp + (lane>>4);
                ldm4t(vf, sV + sw256(row*256 + ch*16));
                mma_f16(oacc[2*ntp],   pf, vf[0], vf[1]);
                mma_f16(oacc[2*ntp+1], pf, vf[2], vf[3]);
            }
        }
    }

    float inv0 = 1.f/l0, inv1 = 1.f/l1;
    int r = wid*16 + (lane>>2);
    __half* Og0 = O + ((size_t)(q0 + r))*DM + h*HDIM;
    __half* Og1 = O + ((size_t)(q0 + r + 8))*DM + h*HDIM;
    #pragma unroll
    for (int nt=0; nt<16; nt++){
        int c = nt*8 + (lane&3)*2;
        *(uint32_t*)(Og0 + c) = pkh2(oacc[nt][0]*inv0, oacc[nt][1]*inv0);
        *(uint32_t*)(Og1 + c) = pkh2(oacc[nt][2]*inv1, oacc[nt][3]*inv1);
    }
}

// ---------------- launch: two-stream batch-split pipeline -------------------
extern "C" void kernel_launch(void* const* d_in, const int* in_sizes, int n_in,
                              void* d_out, int out_size){
    const float* x   = (const float*)d_in[0];
    const float* fc  = (const float*)d_in[1];
    const float* fs  = (const float*)d_in[2];
    const float* wq  = (const float*)d_in[3];
    const float* wk  = (const float*)d_in[4];
    const float* wv  = (const float*)d_in[5];
    const float* wo  = (const float*)d_in[6];
    const float* w1  = (const float*)d_in[7];
    const float* w2  = (const float*)d_in[8];
    const float* w3  = (const float*)d_in[9];
    const float* anw = (const float*)d_in[10];
    const float* fnw = (const float*)d_in[11];
    float* out = (float*)d_out;

    __half *xn,*qkv,*attn,*hn,*ffa,*wqkvH,*woH,*w13H,*w2H;
    float  *h;
    cudaGetSymbolAddress((void**)&xn,    g_xn);
    cudaGetSymbolAddress((void**)&qkv,   g_qkv);
    cudaGetSymbolAddress((void**)&attn,  g_attn);
    cudaGetSymbolAddress((void**)&h,     g_h);
    cudaGetSymbolAddress((void**)&hn,    g_hn);
    cudaGetSymbolAddress((void**)&ffa,   g_ffa);
    cudaGetSymbolAddress((void**)&wqkvH, g_wqkv);
    cudaGetSymbolAddress((void**)&woH,   g_wo);
    cudaGetSymbolAddress((void**)&w13H,  g_w13);
    cudaGetSymbolAddress((void**)&w2H,   g_w2);

    cudaFuncSetAttribute((const void*)gemm_kernel<false,true,true,false>,  cudaFuncAttributeMaxDynamicSharedMemorySize, GEMM_SMEM);
    cudaFuncSetAttribute((const void*)gemm_kernel<true,false,false,false>, cudaFuncAttributeMaxDynamicSharedMemorySize, GEMM_SMEM);
    cudaFuncSetAttribute((const void*)gemm_kernel<false,true,false,true>,  cudaFuncAttributeMaxDynamicSharedMemorySize, GEMM_SMEM);
    cudaFuncSetAttribute((const void*)flash_kernel, cudaFuncAttributeMaxDynamicSharedMemorySize, FLASH_SMEM);

    const int thr = 256;
    const int t8  = DM*DM/8;      // 524288
    const int t8h = DM*HID/8;     // 1441792
    dim3 gq(QKVN/128, HTOK/128);  // (48,16)
    dim3 gd(DM/128,  HTOK/128);   // (16,16)
    dim3 gffh(FFN2/128, HTOK/128);// (88,16)
    dim3 gfl(SEQ/128, NH, 1);     // (16,16,1)

    // fork both pipelines off the capture stream
    cudaEventRecord(g_e0, 0);
    cudaStreamWaitEvent(g_s1, g_e0, 0);
    cudaStreamWaitEvent(g_s2, g_e0, 0);

    // prepass split across streams
    cvt_qkv<<<dim3((t8 +thr-1)/thr, 3), thr, 0, g_s1>>>(wq, wk, wv, wqkvH);
    cudaEventRecord(g_eQ, g_s1);
    cvt_w13<<<dim3((t8h+thr-1)/thr, 2), thr, 0, g_s2>>>(w1, w3, w13H);
    cvt_ow2<<<dim3((t8h+thr-1)/thr, 2), thr, 0, g_s2>>>(wo, w2, woH, w2H);
    cudaEventRecord(g_eW, g_s2);

    // ---- stream 1: batch 0 (rows 0..2047) ----
    {
        const size_t r0 = 0;
        rmsnorm_kernel<<<HTOK, 256, 0, g_s1>>>(x + r0*DM, anw, xn + r0*DM);
        gemm_kernel<false,true,true,false><<<gq, 128, GEMM_SMEM, g_s1>>>(
            xn + r0*DM, wqkvH, nullptr, qkv + r0*QKVN, HTOK, QKVN, DM, fc, fs);
        flash_kernel<<<gfl, 256, FLASH_SMEM, g_s1>>>(qkv + r0*QKVN, attn + r0*DM);
        cudaStreamWaitEvent(g_s1, g_eW, 0);
        gemm_kernel<true,false,false,false><<<gd, 128, GEMM_SMEM, g_s1>>>(
            attn + r0*DM, woH, x + r0*DM, h + r0*DM, HTOK, DM, DM, nullptr, nullptr);
        rmsnorm_kernel<<<HTOK, 256, 0, g_s1>>>(h + r0*DM, fnw, hn + r0*DM);
        gemm_kernel<false,true,false,true><<<gffh, 128, GEMM_SMEM, g_s1>>>(
            hn + r0*DM, w13H, nullptr, ffa + r0*HID, HTOK, FFN2, DM, nullptr, nullptr);
        gemm_kernel<true,false,false,false><<<gd, 128, GEMM_SMEM, g_s1>>>(
            ffa + r0*HID, w2H, h + r0*DM, out + r0*DM, HTOK, DM, HID, nullptr, nullptr);
        cudaEventRecord(g_e1, g_s1);
    }

    // ---- stream 2: batch 1 (rows 2048..4095) ----
    {
        const size_t r0 = HTOK;
        rmsnorm_kernel<<<HTOK, 256, 0, g_s2>>>(x + r0*DM, anw, xn + r0*DM);
        cudaStreamWaitEvent(g_s2, g_eQ, 0);
        gemm_kernel<false,true,true,false><<<gq, 128, GEMM_SMEM, g_s2>>>(
            xn + r0*DM, wqkvH, nullptr, qkv + r0*QKVN, HTOK, QKVN, DM, fc, fs);
        flash_kernel<<<gfl, 256, FLASH_SMEM, g_s2>>>(qkv + r0*QKVN, attn + r0*DM);
        gemm_kernel<true,false,false,false><<<gd, 128, GEMM_SMEM, g_s2>>>(
            attn + r0*DM, woH, x + r0*DM, h + r0*DM, HTOK, DM, DM, nullptr, nullptr);
        rmsnorm_kernel<<<HTOK, 256, 0, g_s2>>>(h + r0*DM, fnw, hn + r0*DM);
        gemm_kernel<false,true,false,true><<<gffh, 128, GEMM_SMEM, g_s2>>>(
            hn + r0*DM, w13H, nullptr, ffa + r0*HID, HTOK, FFN2, DM, nullptr, nullptr);
        gemm_kernel<true,false,false,false><<<gd, 128, GEMM_SMEM, g_s2>>>(
            ffa + r0*HID, w2H, h + r0*DM, out + r0*DM, HTOK, DM, HID, nullptr, nullptr);
        cudaEventRecord(g_e2, g_s2);
    }

    // join back to the capture stream
    cudaStreamWaitEvent(0, g_e1, 0);
    cudaStreamWaitEvent(0, g_e2, 0);
}

// round 11
// speedup vs baseline: 3.4222x; 1.0167x over previous
#include <cuda_runtime.h>
#include <cuda_fp16.h>
#include <math.h>
#include <stdint.h>

#define BSZ   2
#define SEQ   2048
#define DM    2048
#define NH    16
#define HDIM  128
#define HID   5632
#define NTOK  (BSZ*SEQ)     // 4096
#define HTOK  (NTOK/2)      // 2048 rows per batch half
#define QKVN  (3*DM)        // 6144
#define FFN2  (2*HID)       // 11264

// ---------------- scratch (no allocation allowed -> __device__ globals) ----
__device__ __half g_xn  [NTOK*(size_t)DM];
__device__ __half g_qkv [NTOK*(size_t)QKVN];
__device__ __half g_attn[NTOK*(size_t)DM];
__device__ float  g_h   [NTOK*(size_t)DM];
__device__ __half g_hn  [NTOK*(size_t)DM];
__device__ __half g_ffa [NTOK*(size_t)HID];
// fp16 weights, [K,N] layout (wq|wk|wv fused; w1/w3 interleaved by 8 cols)
__device__ __half g_wqkv[DM*(size_t)QKVN];
__device__ __half g_wo  [DM*(size_t)DM];
__device__ __half g_w13 [DM*(size_t)FFN2];
__device__ __half g_w2  [HID*(size_t)DM];

// ---------------- streams/events created at static init (pre-checkpoint) ---
static cudaStream_t g_s1, g_s2, g_s3;
static cudaEvent_t  g_e0, g_eQ, g_eW, g_e1, g_e2;
static struct StreamInit {
    StreamInit(){
        cudaStreamCreateWithFlags(&g_s1, cudaStreamNonBlocking);
        cudaStreamCreateWithFlags(&g_s2, cudaStreamNonBlocking);
        cudaStreamCreateWithFlags(&g_s3, cudaStreamNonBlocking);
        cudaEventCreateWithFlags(&g_e0, cudaEventDisableTiming);
        cudaEventCreateWithFlags(&g_eQ, cudaEventDisableTiming);
        cudaEventCreateWithFlags(&g_eW, cudaEventDisableTiming);
        cudaEventCreateWithFlags(&g_e1, cudaEventDisableTiming);
        cudaEventCreateWithFlags(&g_e2, cudaEventDisableTiming);
    }
} g_stream_init;

// ---------------- helpers --------------------------------------------------
__device__ __forceinline__ uint32_t smem_u32(const void* p){
    uint32_t a;
    asm("{ .reg .u64 t; cvta.to.shared.u64 t, %1; cvt.u32.u64 %0, t; }" : "=r"(a) : "l"(p));
    return a;
}
__device__ __forceinline__ void cp16(void* dst, const void* src){
    unsigned d = (unsigned)__cvta_generic_to_shared(dst);
    asm volatile("cp.async.cg.shared.global [%0], [%1], 16;" :: "r"(d), "l"(src));
}
__device__ __forceinline__ void cp_commit(){ asm volatile("cp.async.commit_group;"); }
__device__ __forceinline__ void cp_wait0(){ asm volatile("cp.async.wait_group 0;"); }
__device__ __forceinline__ void cp_wait1(){ asm volatile("cp.async.wait_group 1;"); }

__device__ __forceinline__ void ldm4(uint32_t r[4], uint32_t addr){
    asm volatile("ldmatrix.sync.aligned.m8n8.x4.shared.b16 {%0,%1,%2,%3}, [%4];"
        : "=r"(r[0]), "=r"(r[1]), "=r"(r[2]), "=r"(r[3]) : "r"(addr));
}
__device__ __forceinline__ void ldm4t(uint32_t r[4], uint32_t addr){
    asm volatile("ldmatrix.sync.aligned.m8n8.x4.trans.shared.b16 {%0,%1,%2,%3}, [%4];"
        : "=r"(r[0]), "=r"(r[1]), "=r"(r[2]), "=r"(r[3]) : "r"(addr));
}
__device__ __forceinline__ void mma_f16(float c[4], const uint32_t a[4], uint32_t b0, uint32_t b1){
    asm volatile("mma.sync.aligned.m16n8k16.row.col.f32.f16.f16.f32 "
        "{%0,%1,%2,%3},{%4,%5,%6,%7},{%8,%9},{%0,%1,%2,%3};"
        : "+f"(c[0]), "+f"(c[1]), "+f"(c[2]), "+f"(c[3])
        : "r"(a[0]), "r"(a[1]), "r"(a[2]), "r"(a[3]), "r"(b0), "r"(b1));
}
__device__ __forceinline__ uint32_t pkh2(float a, float b){
    __half2 h = __floats2half2_rn(a, b);
    return reinterpret_cast<uint32_t&>(h);
}
__device__ __forceinline__ float siluf(float x){ return x / (1.f + __expf(-x)); }
// swizzles (relative byte offsets; conflict-free ldmatrix phases)
__device__ __forceinline__ uint32_t swA(uint32_t o){ return o ^ (((o >> 7) & 7) << 4); }   // 128B rows
__device__ __forceinline__ uint32_t sw256(uint32_t o){ return o ^ (((o >> 8) & 7) << 4); } // 256B rows

// ------- weight convert prepass: fp32[K,Ns] -> fp16 ------------------------
__device__ __forceinline__ void cvt8_body(const float* __restrict__ src, __half* __restrict__ dst,
                                          int Ns, int Nd, int col0, int total8){
    int idx = blockIdx.x*blockDim.x + threadIdx.x;
    if (idx >= total8) return;
    int ns8 = Ns >> 3;
    int k = idx / ns8, j = (idx - k*ns8) << 3;
    const float4* s = (const float4*)(src + (size_t)k*Ns + j);
    float4 v0 = s[0], v1 = s[1];
    uint4 o;
    o.x = pkh2(v0.x, v0.y); o.y = pkh2(v0.z, v0.w);
    o.z = pkh2(v1.x, v1.y); o.w = pkh2(v1.z, v1.w);
    *(uint4*)(dst + (size_t)k*Nd + j + col0) = o;
}

__global__ void cvt_qkv(const float* wq, const float* wk, const float* wv, __half* dst){
    const float* srcs[3] = {wq, wk, wv};
    int y = blockIdx.y;
    cvt8_body(srcs[y], dst, DM, QKVN, y*DM, DM*DM/8);
}
// w1/w3 interleaved by 8 cols; each thread converts the SAME 8-col chunk of
// w1 and w3 and writes one contiguous 32B (fully coalesced).
__global__ void cvt_w13(const float* __restrict__ w1, const float* __restrict__ w3,
                        __half* __restrict__ dst){
    int idx = blockIdx.x*blockDim.x + threadIdx.x;
    const int total8 = DM*HID/8;
    if (idx >= total8) return;
    int ns8 = HID >> 3;
    int k = idx / ns8, j8 = idx - k*ns8;
    const float4* a = (const float4*)(w1 + (size_t)k*HID + j8*8);
    const float4* b = (const float4*)(w3 + (size_t)k*HID + j8*8);
    float4 a0 = a[0], a1 = a[1];
    float4 b0 = b[0], b1 = b[1];
    uint4 o1 = make_uint4(pkh2(a0.x,a0.y), pkh2(a0.z,a0.w), pkh2(a1.x,a1.y), pkh2(a1.z,a1.w));
    uint4 o3 = make_uint4(pkh2(b0.x,b0.y), pkh2(b0.z,b0.w), pkh2(b1.x,b1.y), pkh2(b1.z,b1.w));
    __half* d = dst + (size_t)k*FFN2 + j8*16;
    *(uint4*)(d)     = o1;
    *(uint4*)(d + 8) = o3;
}
__global__ void cvt_ow2(const float* wo, const float* w2, __half* dwo, __half* dw2){
    if (blockIdx.y == 0) cvt8_body(wo, dwo, DM, DM, 0, DM*DM/8);
    else                 cvt8_body(w2, dw2, DM, DM, 0, HID*DM/8);
}

// ---------------- rmsnorm (fp32 in -> fp16 out, vectorized) ----------------
__global__ void rmsnorm_kernel(const float* __restrict__ x, const float* __restrict__ w,
                               __half* __restrict__ out){
    int row = blockIdx.x;
    const float4* xr = (const float4*)(x + (size_t)row*DM);
    float4 v0 = xr[threadIdx.x], v1 = xr[threadIdx.x + 256];
    float ss = v0.x*v0.x + v0.y*v0.y + v0.z*v0.z + v0.w*v0.w
             + v1.x*v1.x + v1.y*v1.y + v1.z*v1.z + v1.w*v1.w;
    __shared__ float red[8];
    #pragma unroll
    for (int o = 16; o; o >>= 1) ss += __shfl_xor_sync(~0u, ss, o);
    if ((threadIdx.x & 31) == 0) red[threadIdx.x >> 5] = ss;
    __syncthreads();
    if (threadIdx.x == 0){
        float t = 0.f;
        #pragma unroll
        for (int i = 0; i < 8; i++) t += red[i];
        red[0] = t;
    }
    __syncthreads();
    float inv = rsqrtf(red[0] / (float)DM + 1e-5f);
    const float4* w4 = (const float4*)w;
    uint2* o2 = (uint2*)(out + (size_t)row*DM);
    float4 a = w4[threadIdx.x], b = w4[threadIdx.x + 256];
    o2[threadIdx.x]       = make_uint2(pkh2(v0.x*inv*a.x, v0.y*inv*a.y), pkh2(v0.z*inv*a.z, v0.w*inv*a.w));
    o2[threadIdx.x + 256] = make_uint2(pkh2(v1.x*inv*b.x, v1.y*inv*b.y), pkh2(v1.z*inv*b.z, v1.w*inv*b.w));
}

// ================= fp16 GEMM: C[M,N] = A[M,K] @ B[K,N] =====================
// 128x128 block, 4 warps of 64x64, BK=64, 3-stage cp.async, 2 CTAs/SM.
#define GSTG_BYTES (32*1024)
#define GEMM_SMEM  (3*GSTG_BYTES)     // 98304 -> 2 CTAs/SM
#define QSCALE 0.08838834764831845f   // 1/sqrt(128), folded into Q

template<bool ADD, bool HOUT, bool ROPE, bool SILU>
__global__ void __launch_bounds__(128, 2)
gemm_kernel(const __half* __restrict__ A, const __half* __restrict__ B,
            const float* __restrict__ Add, void* __restrict__ Cv,
            int M, int N, int K,
            const float* __restrict__ fc, const float* __restrict__ fs)
{
    extern __shared__ char smem[];
    const uint32_t sb = smem_u32(smem);
    const int tid = threadIdx.x, lane = tid & 31, wid = tid >> 5;   // 4 warps
    const int wm = (wid >> 1) * 64;
    const int wn = (wid & 1) * 64;
    const int bm = blockIdx.y * 128, bn = blockIdx.x * 128;

    float acc[4][8][4];
    #pragma unroll
    for (int i=0;i<4;i++)
        #pragma unroll
        for (int j=0;j<8;j++)
            #pragma unroll
            for (int r=0;r<4;r++) acc[i][j][r] = 0.f;

    const int nk = K / 64;

    auto issue = [&](int kt, int st){
        char* Ad = smem + st*GSTG_BYTES;
        const __half* Ag = A + (size_t)bm*K + kt*64;
        #pragma unroll
        for (int i = 0; i < 8; i++){
            int idx = tid + i*128;            // 0..1023
            int m = idx >> 3, c = idx & 7;
            cp16(Ad + swA(m*128 + c*16), Ag + (size_t)m*K + c*8);
        }
        char* Bd = Ad + 16*1024;
        const __half* Bg = B + (size_t)(kt*64)*N + bn;
        #pragma unroll
        for (int i = 0; i < 8; i++){
            int idx = tid + i*128;            // 0..1023
            int k = idx >> 4, c = idx & 15;
            cp16(Bd + sw256(k*256 + c*16), Bg + (size_t)k*N + c*8);
        }
        cp_commit();
    };

    issue(0, 0); issue(1, 1);
    int cur = 0, nxt = 2;
    for (int kt = 0; kt < nk; kt++){
        cp_wait1();
        __syncthreads();
        if (kt+2 < nk) issue(kt+2, nxt);
        const uint32_t sA = sb + cur*GSTG_BYTES;
        const uint32_t sB = sA + 16*1024;
        if (++cur == 3) cur = 0;
        if (++nxt == 3) nxt = 0;
        #pragma unroll
        for (int ks = 0; ks < 4; ks++){
            uint32_t af[4][4];
            #pragma unroll
            for (int mt = 0; mt < 4; mt++){
                int row = wm + mt*16 + (lane&7) + ((lane>>3)&1)*8;
                int ch  = 2*ks + (lane>>4);
                ldm4(af[mt], sA + swA(row*128 + ch*16));
            }
            uint32_t bf[4][4];
            #pragma unroll
            for (int ntp = 0; ntp < 4; ntp++){
                int krow = ks*16 + (lane&7) + ((lane>>3)&1)*8;
                int ch   = ((wn + ntp*16) >> 3) + (lane>>4);
                ldm4t(bf[ntp], sB + sw256(krow*256 + ch*16));
            }
            #pragma unroll
            for (int mt = 0; mt < 4; mt++)
                #pragma unroll
                for (int ntp = 0; ntp < 4; ntp++){
                    mma_f16(acc[mt][2*ntp],   af[mt], bf[ntp][0], bf[ntp][1]);
                    mma_f16(acc[mt][2*ntp+1], af[mt], bf[ntp][2], bf[ntp][3]);
                }
        }
    }

    // ---------------- epilogue ----------------
    if (SILU){
        __half* C = (__half*)Cv;
        const int NO = N >> 1;    // HID
        #pragma unroll
        for (int mt = 0; mt < 4; mt++){
            int r0 = bm + wm + mt*16 + (lane>>2);
            #pragma unroll
            for (int ntp = 0; ntp < 4; ntp++){
                int j = ((bn + wn) >> 1) + ntp*8 + (lane&3)*2;
                const float* a1 = acc[mt][2*ntp];
                const float* a3 = acc[mt][2*ntp+1];
                *(uint32_t*)(C + (size_t)r0*NO + j) =
                    pkh2(siluf(a1[0])*a3[0], siluf(a1[1])*a3[1]);
                *(uint32_t*)(C + (size_t)(r0+8)*NO + j) =
                    pkh2(siluf(a1[2])*a3[2], siluf(a1[3])*a3[3]);
            }
        }
        return;
    }
    #pragma unroll
    for (int mt = 0; mt < 4; mt++){
        #pragma unroll
        for (int nt = 0; nt < 8; nt++){
            int r = bm + wm + mt*16 + (lane>>2);
            int c = bn + wn + nt*8 + (lane&3)*2;
            float2 v0 = make_float2(acc[mt][nt][0], acc[mt][nt][1]);
            float2 v1 = make_float2(acc[mt][nt][2], acc[mt][nt][3]);
            if (ADD){
                const float* A0 = Add + (size_t)r*N + c;
                const float* A1 = Add + (size_t)(r+8)*N + c;
                v0.x += A0[0]; v0.y += A0[1];
                v1.x += A1[0]; v1.y += A1[1];
            }
            if (ROPE && c < 2*DM){
                int i = (c & (HDIM-1)) >> 1;
                int s0 = r & (SEQ-1), s1 = (r+8) & (SEQ-1);
                float c0 = fc[s0*64 + i], sn0 = fs[s0*64 + i];
                float c1 = fc[s1*64 + i], sn1 = fs[s1*64 + i];
                float a = v0.x, b = v0.y;
                v0.x = a*c0 - b*sn0; v0.y = a*sn0 + b*c0;
                a = v1.x; b = v1.y;
                v1.x = a*c1 - b*sn1; v1.y = a*sn1 + b*c1;
                if (c < DM){   // q slice: fold softmax scale
                    v0.x *= QSCALE; v0.y *= QSCALE;
                    v1.x *= QSCALE; v1.y *= QSCALE;
                }
            }
            if (HOUT){
                __half* C = (__half*)Cv;
                *(uint32_t*)(C + (size_t)r*N + c)     = pkh2(v0.x, v0.y);
                *(uint32_t*)(C + (size_t)(r+8)*N + c) = pkh2(v1.x, v1.y);
            } else {
                float* C = (float*)Cv;
                *(float2*)(C + (size_t)r*N + c)     = v0;
                *(float2*)(C + (size_t)(r+8)*N + c) = v1;
            }
        }
    }
}

// ---------------- flash attention, BQ=128, 256 threads, P in registers -----
#define FQ_OFF  0
#define FK_OFF  (32*1024)
#define FV_OFF  (64*1024)
#define FLASH_SMEM (96*1024)

__global__ void __launch_bounds__(256)
flash_kernel(const __half* __restrict__ QKV, __half* __restrict__ O)
{
    extern __shared__ char smem[];
    const uint32_t sb = smem_u32(smem);
    const int tid = threadIdx.x, lane = tid & 31, wid = tid >> 5;
    const int qt = blockIdx.x, h = blockIdx.y;
    const int q0 = qt*128;

    {   // Q: 128 rows x 256B (pre-scaled by 1/sqrt(HD) in QKV epilogue)
        const __half* Qg = QKV + (size_t)q0*QKVN + h*HDIM;
        #pragma unroll
        for (int i = 0; i < 8; i++){
            int idx = tid + i*256;
            int r = idx >> 4, c = idx & 15;
            cp16(smem + FQ_OFF + sw256(r*256 + c*16), Qg + (size_t)r*QKVN + c*8);
        }
    }
    auto issueKV = [&](int kt, int st){
        const __half* Kg = QKV + (size_t)(kt*64)*QKVN + DM   + h*HDIM;
        const __half* Vg = QKV + (size_t)(kt*64)*QKVN + 2*DM + h*HDIM;
        char* Kd = smem + FK_OFF + st*16*1024;
        char* Vd = smem + FV_OFF + st*16*1024;
        #pragma unroll
        for (int i = 0; i < 4; i++){
            int idx = tid + i*256;
            int r = idx >> 4, c = idx & 15;
            uint32_t so = sw256(r*256 + c*16);
            cp16(Kd + so, Kg + (size_t)r*QKVN + c*8);
            cp16(Vd + so, Vg + (size_t)r*QKVN + c*8);
        }
        cp_commit();
    };
    issueKV(0, 0);
    cp_wait0();
    __syncthreads();

    uint32_t qf[8][4];
    #pragma unroll
    for (int ks = 0; ks < 8; ks++){
        int row = wid*16 + (lane&7) + ((lane>>3)&1)*8;
        int ch  = 2*ks + (lane>>4);
        ldm4(qf[ks], sb + FQ_OFF + sw256(row*256 + ch*16));
    }

    float m0 = -1e30f, m1 = -1e30f, l0 = 0.f, l1 = 0.f;
    float oacc[16][4];
    #pragma unroll
    for (int i=0;i<16;i++)
        #pragma unroll
        for (int j=0;j<4;j++) oacc[i][j] = 0.f;

    const int nkt = SEQ / 64;     // 32
    for (int kt = 0; kt < nkt; kt++){
        if (kt > 0){ cp_wait0(); __syncthreads(); }
        if (kt+1 < nkt) issueKV(kt+1, (kt+1)&1);
        const uint32_t sK = sb + FK_OFF + (kt&1)*16*1024;
        const uint32_t sV = sb + FV_OFF + (kt&1)*16*1024;

        float sacc[8][4];
        #pragma unroll
        for (int i=0;i<8;i++)
            #pragma unroll
            for (int j=0;j<4;j++) sacc[i][j] = 0.f;
        #pragma unroll
        for (int ks = 0; ks < 8; ks++){
            #pragma unroll
            for (int ntp = 0; ntp < 4; ntp++){
                uint32_t kf[4];
                int row = ntp*16 + ((lane>>4)&1)*8 + (lane&7);
                int ch  = 2*ks + ((lane>>3)&1);
                ldm4(kf, sK + sw256(row*256 + ch*16));
                mma_f16(sacc[2*ntp],   qf[ks], kf[0], kf[1]);
                mma_f16(sacc[2*ntp+1], qf[ks], kf[2], kf[3]);
            }
        }

        float mx0 = -1e30f, mx1 = -1e30f;
        #pragma unroll
        for (int nt=0; nt<8; nt++){
            mx0 = fmaxf(mx0, fmaxf(sacc[nt][0], sacc[nt][1]));
            mx1 = fmaxf(mx1, fmaxf(sacc[nt][2], sacc[nt][3]));
        }
        mx0 = fmaxf(mx0, __shfl_xor_sync(~0u, mx0, 1));
        mx0 = fmaxf(mx0, __shfl_xor_sync(~0u, mx0, 2));
        mx1 = fmaxf(mx1, __shfl_xor_sync(~0u, mx1, 1));
        mx1 = fmaxf(mx1, __shfl_xor_sync(~0u, mx1, 2));
        float mn0 = fmaxf(m0, mx0), mn1 = fmaxf(m1, mx1);
        float cr0 = __expf(m0 - mn0), cr1 = __expf(m1 - mn1);
        m0 = mn0; m1 = mn1;
        float rs0 = 0.f, rs1 = 0.f;
        #pragma unroll
        for (int nt=0; nt<8; nt++){
            sacc[nt][0] = __expf(sacc[nt][0] - mn0);
            sacc[nt][1] = __expf(sacc[nt][1] - mn0);
            sacc[nt][2] = __expf(sacc[nt][2] - mn1);
            sacc[nt][3] = __expf(sacc[nt][3] - mn1);
            rs0 += sacc[nt][0] + sacc[nt][1];
            rs1 += sacc[nt][2] + sacc[nt][3];
        }
        rs0 += __shfl_xor_sync(~0u, rs0, 1); rs0 += __shfl_xor_sync(~0u, rs0, 2);
        rs1 += __shfl_xor_sync(~0u, rs1, 1); rs1 += __shfl_xor_sync(~0u, rs1, 2);
        l0 = l0*cr0 + rs0; l1 = l1*cr1 + rs1;
        #pragma unroll
        for (int i=0;i<16;i++){
            oacc[i][0] *= cr0; oacc[i][1] *= cr0;
            oacc[i][2] *= cr1; oacc[i][3] *= cr1;
        }

        #pragma unroll
        for (int kv = 0; kv < 4; kv++){
            uint32_t pf[4];
            pf[0] = pkh2(sacc[2*kv][0],   sacc[2*kv][1]);
            pf[1] = pkh2(sacc[2*kv][2],   sacc[2*kv][3]);
            pf[2] = pkh2(sacc[2*kv+1][0], sacc[2*kv+1][1]);
            pf[3] = pkh2(sacc[2*kv+1][2], sacc[2*kv+1][3]);
            #pragma unroll
            for (int ntp = 0; ntp < 8; ntp++){
                uint32_t vf[4];
                int row = kv*16 + (lane&7) + ((lane>>3)&1)*8;
                int ch  = 2*ntp + (lane>>4);
                ldm4t(vf, sV + sw256(row*256 + ch*16));
                mma_f16(oacc[2*ntp],   pf, vf[0], vf[1]);
                mma_f16(oacc[2*ntp+1], pf, vf[2], vf[3]);
            }
        }
    }

    float inv0 = 1.f/l0, inv1 = 1.f/l1;
    int r = wid*16 + (lane>>2);
    __half* Og0 = O + ((size_t)(q0 + r))*DM + h*HDIM;
    __half* Og1 = O + ((size_t)(q0 + r + 8))*DM + h*HDIM;
    #pragma unroll
    for (int nt=0; nt<16; nt++){
        int c = nt*8 + (lane&3)*2;
        *(uint32_t*)(Og0 + c) = pkh2(oacc[nt][0]*inv0, oacc[nt][1]*inv0);
        *(uint32_t*)(Og1 + c) = pkh2(oacc[nt][2]*inv1, oacc[nt][3]*inv1);
    }
}

// ---------------- launch: 3-stream pipeline (cvt overlapped) ----------------
extern "C" void kernel_launch(void* const* d_in, const int* in_sizes, int n_in,
                              void* d_out, int out_size){
    const float* x   = (const float*)d_in[0];
    const float* fc  = (const float*)d_in[1];
    const float* fs  = (const float*)d_in[2];
    const float* wq  = (const float*)d_in[3];
    const float* wk  = (const float*)d_in[4];
    const float* wv  = (const float*)d_in[5];
    const float* wo  = (const float*)d_in[6];
    const float* w1  = (const float*)d_in[7];
    const float* w2  = (const float*)d_in[8];
    const float* w3  = (const float*)d_in[9];
    const float* anw = (const float*)d_in[10];
    const float* fnw = (const float*)d_in[11];
    float* out = (float*)d_out;

    __half *xn,*qkv,*attn,*hn,*ffa,*wqkvH,*woH,*w13H,*w2H;
    float  *h;
    cudaGetSymbolAddress((void**)&xn,    g_xn);
    cudaGetSymbolAddress((void**)&qkv,   g_qkv);
    cudaGetSymbolAddress((void**)&attn,  g_attn);
    cudaGetSymbolAddress((void**)&h,     g_h);
    cudaGetSymbolAddress((void**)&hn,    g_hn);
    cudaGetSymbolAddress((void**)&ffa,   g_ffa);
    cudaGetSymbolAddress((void**)&wqkvH, g_wqkv);
    cudaGetSymbolAddress((void**)&woH,   g_wo);
    cudaGetSymbolAddress((void**)&w13H,  g_w13);
    cudaGetSymbolAddress((void**)&w2H,   g_w2);

    cudaFuncSetAttribute((const void*)gemm_kernel<false,true,true,false>,  cudaFuncAttributeMaxDynamicSharedMemorySize, GEMM_SMEM);
    cudaFuncSetAttribute((const void*)gemm_kernel<true,false,false,false>, cudaFuncAttributeMaxDynamicSharedMemorySize, GEMM_SMEM);
    cudaFuncSetAttribute((const void*)gemm_kernel<false,true,false,true>,  cudaFuncAttributeMaxDynamicSharedMemorySize, GEMM_SMEM);
    cudaFuncSetAttribute((const void*)flash_kernel, cudaFuncAttributeMaxDynamicSharedMemorySize, FLASH_SMEM);

    const int thr = 256;
    const int t8  = DM*DM/8;      // 524288
    const int t8p = DM*HID/8;     // 1441792 (w13 pair chunks)
    dim3 gq(QKVN/128, HTOK/128);  // (48,16)
    dim3 gd(DM/128,  HTOK/128);   // (16,16)
    dim3 gffh(FFN2/128, HTOK/128);// (88,16)
    dim3 gfl(SEQ/128, NH, 1);     // (16,16,1)

    // fork all three pipelines off the capture stream
    cudaEventRecord(g_e0, 0);
    cudaStreamWaitEvent(g_s1, g_e0, 0);
    cudaStreamWaitEvent(g_s2, g_e0, 0);
    cudaStreamWaitEvent(g_s3, g_e0, 0);

    // s3: all weight converts. qkv first (critical path head), then w13/ow2
    // which overlap with the tensor-bound qkv GEMM + flash phases.
    cvt_qkv<<<dim3((t8 +thr-1)/thr, 3), thr, 0, g_s3>>>(wq, wk, wv, wqkvH);
    cudaEventRecord(g_eQ, g_s3);
    cvt_w13<<<(t8p+thr-1)/thr, thr, 0, g_s3>>>(w1, w3, w13H);
    cvt_ow2<<<dim3((t8p+thr-1)/thr, 2), thr, 0, g_s3>>>(wo, w2, woH, w2H);
    cudaEventRecord(g_eW, g_s3);

    // ---- stream 1: batch 0 (rows 0..2047) ----
    {
        const size_t r0 = 0;
        rmsnorm_kernel<<<HTOK, 256, 0, g_s1>>>(x + r0*DM, anw, xn + r0*DM);
        cudaStreamWaitEvent(g_s1, g_eQ, 0);
        gemm_kernel<false,true,true,false><<<gq, 128, GEMM_SMEM, g_s1>>>(
            xn + r0*DM, wqkvH, nullptr, qkv + r0*QKVN, HTOK, QKVN, DM, fc, fs);
        flash_kernel<<<gfl, 256, FLASH_SMEM, g_s1>>>(qkv + r0*QKVN, attn + r0*DM);
        cudaStreamWaitEvent(g_s1, g_eW, 0);
        gemm_kernel<true,false,false,false><<<gd, 128, GEMM_SMEM, g_s1>>>(
            attn + r0*DM, woH, x + r0*DM, h + r0*DM, HTOK, DM, DM, nullptr, nullptr);
        rmsnorm_kernel<<<HTOK, 256, 0, g_s1>>>(h + r0*DM, fnw, hn + r0*DM);
        gemm_kernel<false,true,false,true><<<gffh, 128, GEMM_SMEM, g_s1>>>(
            hn + r0*DM, w13H, nullptr, ffa + r0*HID, HTOK, FFN2, DM, nullptr, nullptr);
        gemm_kernel<true,false,false,false><<<gd, 128, GEMM_SMEM, g_s1>>>(
            ffa + r0*HID, w2H, h + r0*DM, out + r0*DM, HTOK, DM, HID, nullptr, nullptr);
        cudaEventRecord(g_e1, g_s1);
    }

    // ---- stream 2: batch 1 (rows 2048..4095) ----
    {
        const size_t r0 = HTOK;
        rmsnorm_kernel<<<HTOK, 256, 0, g_s2>>>(x + r0*DM, anw, xn + r0*DM);
        cudaStreamWaitEvent(g_s2, g_eQ, 0);
        gemm_kernel<false,true,true,false><<<gq, 128, GEMM_SMEM, g_s2>>>(
            xn + r0*DM, wqkvH, nullptr, qkv + r0*QKVN, HTOK, QKVN, DM, fc, fs);
        flash_kernel<<<gfl, 256, FLASH_SMEM, g_s2>>>(qkv + r0*QKVN, attn + r0*DM);
        cudaStreamWaitEvent(g_s2, g_eW, 0);
        gemm_kernel<true,false,false,false><<<gd, 128, GEMM_SMEM, g_s2>>>(
            attn + r0*DM, woH, x + r0*DM, h + r0*DM, HTOK, DM, DM, nullptr, nullptr);
        rmsnorm_kernel<<<HTOK, 256, 0, g_s2>>>(h + r0*DM, fnw, hn + r0*DM);
        gemm_kernel<false,true,false,true><<<gffh, 128, GEMM_SMEM, g_s2>>>(
            hn + r0*DM, w13H, nullptr, ffa + r0*HID, HTOK, FFN2, DM, nullptr, nullptr);
        gemm_kernel<true,false,false,false><<<gd, 128, GEMM_SMEM, g_s2>>>(
            ffa + r0*HID, w2H, h + r0*DM, out + r0*DM, HTOK, DM, HID, nullptr, nullptr);
        cudaEventRecord(g_e2, g_s2);
    }

    // join back to the capture stream
    cudaStreamWaitEvent(0, g_e1, 0);
    cudaStreamWaitEvent(0, g_e2, 0);
}